// round 3
// baseline (speedup 1.0000x reference)
#include <cuda_runtime.h>

#define MAXN 50000
#define MAXE 800000
#define MAXT (MAXN + MAXE)

// ---------------- scratch (device globals; no allocation allowed) ----------------
__device__ __align__(16) float g_xl1[(size_t)MAXN * 256];
__device__ __align__(16) float g_xr1[(size_t)MAXN * 256];
__device__ __align__(16) float g_h1 [(size_t)MAXN * 256];
__device__ __align__(16) float g_xl2[(size_t)MAXN * 64];
__device__ __align__(16) float g_xr2[(size_t)MAXN * 64];
__device__ __align__(16) float g_out2[(size_t)MAXN * 64];
__device__ __align__(16) float g_sc1[(size_t)MAXT * 4];
__device__ __align__(16) float g_ex1[(size_t)MAXT * 4];
__device__ __align__(16) unsigned g_smax1[(size_t)MAXN * 4];
__device__ __align__(16) float g_den1[(size_t)MAXN * 4];
__device__ __align__(16) float g_sc2[MAXT];
__device__ __align__(16) float g_ex2[MAXT];
__device__ __align__(16) unsigned g_smax2[MAXN];
__device__ __align__(16) float g_den2[MAXN];
__device__ __align__(16) float g_acc[64];
__device__ __align__(16) float g_cnt[64];

// ---------------- helpers ----------------
// order-preserving float<->uint encoding for atomicMax on floats
__device__ __forceinline__ unsigned fenc(float f) {
    unsigned u = __float_as_uint(f);
    return (u & 0x80000000u) ? ~u : (u | 0x80000000u);
}
__device__ __forceinline__ float fdec(unsigned u) {
    return (u & 0x80000000u) ? __uint_as_float(u & 0x7fffffffu) : __uint_as_float(~u);
}

// vector reduction-add to global (sm_90+): one 16B L2 RMW instead of 4 scalar atomics
__device__ __forceinline__ void red_add_v4(float* addr, float4 v) {
    asm volatile("red.global.add.v4.f32 [%0], {%1,%2,%3,%4};"
                 :: "l"(addr), "f"(v.x), "f"(v.y), "f"(v.z), "f"(v.w) : "memory");
}

__device__ __forceinline__ float lrelu(float v) { return v > 0.f ? v : 0.2f * v; }

// ---------------- init ----------------
__global__ void init_kernel(int N) {
    int i = blockIdx.x * blockDim.x + threadIdx.x;
    if (i < N * 256) g_h1[i] = 0.f;
    if (i < N * 64)  g_out2[i] = 0.f;
    if (i < N * 4) { g_den1[i] = 0.f; g_smax1[i] = 0u; }
    if (i < N)     { g_den2[i] = 0.f; g_smax2[i] = 0u; }
    if (i < 64)    { g_acc[i] = 0.f; g_cnt[i] = 0.f; }
}

// ---------------- tiled fp32 GEMM ----------------
// layer==1: A = x_param (N x 128), B = Wl1/Wr1 (128 x 256), C = g_xl1/g_xr1
// layer==2: A = relu(g_h1 + b1) (N x 256), B = Wl2/Wr2 (256 x 64), C = g_xl2/g_xr2
__global__ void gemm_dual(const float* __restrict__ x_param,
                          const float* __restrict__ B0, const float* __restrict__ B1,
                          int M, int K, int Nout,
                          const float* __restrict__ abias, int layer)
{
    const float* A = (layer == 1) ? x_param : g_h1;
    const float* B = blockIdx.z ? B1 : B0;
    float* C = (layer == 1) ? (blockIdx.z ? g_xr1 : g_xl1)
                            : (blockIdx.z ? g_xr2 : g_xl2);
    __shared__ float As[16][64];
    __shared__ float Bs[16][64];
    int tid = threadIdx.x;
    int tx = tid & 15, ty = tid >> 4;
    int m0 = blockIdx.y * 64, n0 = blockIdx.x * 64;
    float acc[4][4] = {};
    int ar = tid >> 2, ak0 = (tid & 3) * 4;   // A tile load: 64 rows x 16 k
    int br = tid >> 4, bc0 = (tid & 15) * 4;  // B tile load: 16 k x 64 cols

    for (int k0 = 0; k0 < K; k0 += 16) {
        float4 av;
        if (m0 + ar < M) av = *(const float4*)(A + (size_t)(m0 + ar) * K + k0 + ak0);
        else av = make_float4(0.f, 0.f, 0.f, 0.f);
        if (layer == 2) {
            const float* bb = abias + k0 + ak0;
            av.x = fmaxf(av.x + bb[0], 0.f); av.y = fmaxf(av.y + bb[1], 0.f);
            av.z = fmaxf(av.z + bb[2], 0.f); av.w = fmaxf(av.w + bb[3], 0.f);
        }
        As[ak0 + 0][ar] = av.x; As[ak0 + 1][ar] = av.y;
        As[ak0 + 2][ar] = av.z; As[ak0 + 3][ar] = av.w;
        *(float4*)&Bs[br][bc0] = *(const float4*)(B + (size_t)(k0 + br) * Nout + n0 + bc0);
        __syncthreads();
        #pragma unroll
        for (int kk = 0; kk < 16; kk++) {
            float a4[4], b4[4];
            #pragma unroll
            for (int i = 0; i < 4; i++) a4[i] = As[kk][ty * 4 + i];
            #pragma unroll
            for (int j = 0; j < 4; j++) b4[j] = Bs[kk][tx * 4 + j];
            #pragma unroll
            for (int i = 0; i < 4; i++)
                #pragma unroll
                for (int j = 0; j < 4; j++) acc[i][j] += a4[i] * b4[j];
        }
        __syncthreads();
    }
    #pragma unroll
    for (int i = 0; i < 4; i++) {
        int m = m0 + ty * 4 + i;
        if (m < M)
            *(float4*)(C + (size_t)m * Nout + n0 + tx * 4) =
                make_float4(acc[i][0], acc[i][1], acc[i][2], acc[i][3]);
    }
}

// ---------------- layer 1 attention (H=4, C=64): one warp per edge ----------------
__global__ void edge_score1(const int* __restrict__ src, const int* __restrict__ dst,
                            int E, int Etot, const float* __restrict__ att)
{
    int w = (blockIdx.x * blockDim.x + threadIdx.x) >> 5;
    if (w >= Etot) return;
    int lane = threadIdx.x & 31;
    int s, d;
    if (w < E) { s = src[w]; d = dst[w]; } else { s = w - E; d = s; }
    int off = lane * 8;  // lane covers 8 channels of head (lane>>3)
    const float4* pa = (const float4*)(g_xl1 + (size_t)s * 256 + off);
    const float4* pb = (const float4*)(g_xr1 + (size_t)d * 256 + off);
    const float4* pw = (const float4*)(att + off);
    float acc = 0.f;
    #pragma unroll
    for (int j = 0; j < 2; j++) {
        float4 a = pa[j], b = pb[j], t = pw[j];
        acc += lrelu(a.x + b.x) * t.x;
        acc += lrelu(a.y + b.y) * t.y;
        acc += lrelu(a.z + b.z) * t.z;
        acc += lrelu(a.w + b.w) * t.w;
    }
    acc += __shfl_xor_sync(0xffffffffu, acc, 1);
    acc += __shfl_xor_sync(0xffffffffu, acc, 2);
    acc += __shfl_xor_sync(0xffffffffu, acc, 4);
    if ((lane & 7) == 0) {
        int h = lane >> 3;
        g_sc1[(size_t)w * 4 + h] = acc;
        atomicMax(&g_smax1[(size_t)d * 4 + h], fenc(acc));
    }
}

__global__ void edge_exp1(const int* __restrict__ dst, int E, int Etot)
{
    int i = blockIdx.x * blockDim.x + threadIdx.x;
    if (i >= Etot * 4) return;
    int e = i >> 2, h = i & 3;
    int d = (e < E) ? dst[e] : (e - E);
    float mx = fdec(g_smax1[(size_t)d * 4 + h]);
    float ex = __expf(g_sc1[i] - mx);
    g_ex1[i] = ex;
    atomicAdd(&g_den1[(size_t)d * 4 + h], ex);
}

__global__ void edge_agg1(const int* __restrict__ src, const int* __restrict__ dst,
                          int E, int Etot)
{
    int w = (blockIdx.x * blockDim.x + threadIdx.x) >> 5;
    if (w >= Etot) return;
    int lane = threadIdx.x & 31;
    int s, d;
    if (w < E) { s = src[w]; d = dst[w]; } else { s = w - E; d = s; }
    int h = lane >> 3;
    float alpha = g_ex1[(size_t)w * 4 + h] / (g_den1[(size_t)d * 4 + h] + 1e-16f);
    int off = lane * 8;
    const float4* pa = (const float4*)(g_xl1 + (size_t)s * 256 + off);
    float* po = g_h1 + (size_t)d * 256 + off;
    #pragma unroll
    for (int j = 0; j < 2; j++) {
        float4 a = pa[j];
        a.x *= alpha; a.y *= alpha; a.z *= alpha; a.w *= alpha;
        red_add_v4(po + j * 4, a);
    }
}

// ---------------- layer 2 attention (H=1, C=64): 16 lanes per edge, 2 edges/warp ----------------
__global__ void edge_score2(const int* __restrict__ src, const int* __restrict__ dst,
                            int E, int Etot, const float* __restrict__ att)
{
    int w = (blockIdx.x * blockDim.x + threadIdx.x) >> 5;
    int lane = threadIdx.x & 31;
    int e_raw = w * 2 + (lane >> 4);
    bool valid = e_raw < Etot;
    int e = valid ? e_raw : Etot - 1;
    int t = lane & 15;
    int s, d;
    if (e < E) { s = src[e]; d = dst[e]; } else { s = e - E; d = s; }
    float4 a = *(const float4*)(g_xl2 + (size_t)s * 64 + t * 4);
    float4 b = *(const float4*)(g_xr2 + (size_t)d * 64 + t * 4);
    float4 tt = *(const float4*)(att + t * 4);
    float acc = 0.f;
    acc += lrelu(a.x + b.x) * tt.x;
    acc += lrelu(a.y + b.y) * tt.y;
    acc += lrelu(a.z + b.z) * tt.z;
    acc += lrelu(a.w + b.w) * tt.w;
    acc += __shfl_xor_sync(0xffffffffu, acc, 1);
    acc += __shfl_xor_sync(0xffffffffu, acc, 2);
    acc += __shfl_xor_sync(0xffffffffu, acc, 4);
    acc += __shfl_xor_sync(0xffffffffu, acc, 8);
    if (valid && t == 0) {
        g_sc2[e] = acc;
        atomicMax(&g_smax2[d], fenc(acc));
    }
}

__global__ void edge_exp2(const int* __restrict__ dst, int E, int Etot)
{
    int e = blockIdx.x * blockDim.x + threadIdx.x;
    if (e >= Etot) return;
    int d = (e < E) ? dst[e] : (e - E);
    float mx = fdec(g_smax2[d]);
    float ex = __expf(g_sc2[e] - mx);
    g_ex2[e] = ex;
    atomicAdd(&g_den2[d], ex);
}

__global__ void edge_agg2(const int* __restrict__ src, const int* __restrict__ dst,
                          int E, int Etot)
{
    int w = (blockIdx.x * blockDim.x + threadIdx.x) >> 5;
    int lane = threadIdx.x & 31;
    int e = w * 2 + (lane >> 4);
    if (e >= Etot) return;
    int t = lane & 15;
    int s, d;
    if (e < E) { s = src[e]; d = dst[e]; } else { s = e - E; d = s; }
    float alpha = g_ex2[e] / (g_den2[d] + 1e-16f);
    float4 a = *(const float4*)(g_xl2 + (size_t)s * 64 + t * 4);
    a.x *= alpha; a.y *= alpha; a.z *= alpha; a.w *= alpha;
    red_add_v4(g_out2 + (size_t)d * 64 + t * 4, a);
}

// ---------------- pooling: per-node dot with Wo, segment mean via atomics ----------------
__global__ void pool_kernel(const int* __restrict__ batch, int N,
                            const float* __restrict__ b2, const float* __restrict__ Wo)
{
    int n = blockIdx.x * blockDim.x + threadIdx.x;
    if (n >= N) return;
    const float4* row = (const float4*)(g_out2 + (size_t)n * 64);
    float y = 0.f;
    #pragma unroll
    for (int j = 0; j < 16; j++) {
        float4 v = row[j];
        float4 bb = ((const float4*)b2)[j];
        float4 w = ((const float4*)Wo)[j];
        y += (v.x + bb.x) * w.x + (v.y + bb.y) * w.y
           + (v.z + bb.z) * w.z + (v.w + bb.w) * w.w;
    }
    int g = batch[n];
    atomicAdd(&g_acc[g], y);
    atomicAdd(&g_cnt[g], 1.f);
}

__global__ void final_kernel(float* __restrict__ out, int G, const float* __restrict__ bo)
{
    int g = threadIdx.x;
    if (g < G) out[g] = g_acc[g] / fmaxf(g_cnt[g], 1.f) + bo[0];
}

// ---------------- launch ----------------
extern "C" void kernel_launch(void* const* d_in, const int* in_sizes, int n_in,
                              void* d_out, int out_size)
{
    const float* x    = (const float*)d_in[0];
    const int* ei     = (const int*)d_in[1];   // int32: JAX default (x64 disabled) downcasts int64
    const int* bat    = (const int*)d_in[2];
    const float* Wl1 = (const float*)d_in[3];
    const float* Wr1 = (const float*)d_in[4];
    const float* att1 = (const float*)d_in[5];
    const float* b1  = (const float*)d_in[6];
    const float* Wl2 = (const float*)d_in[7];
    const float* Wr2 = (const float*)d_in[8];
    const float* att2 = (const float*)d_in[9];
    const float* b2  = (const float*)d_in[10];
    const float* Wo  = (const float*)d_in[11];
    const float* bo  = (const float*)d_in[12];

    int N = in_sizes[0] / 128;
    int E = in_sizes[1] / 2;
    int Etot = E + N;
    int G = out_size;
    const int* src = ei;
    const int* dst = ei + E;

    init_kernel<<<(N * 256 + 255) / 256, 256>>>(N);

    // layer 1 transforms: xl1 = x@Wl1, xr1 = x@Wr1   (M=N, K=128, Nout=256)
    gemm_dual<<<dim3(256 / 64, (N + 63) / 64, 2), 256>>>(
        x, Wl1, Wr1, N, 128, 256, nullptr, 1);

    edge_score1<<<(Etot * 32 + 255) / 256, 256>>>(src, dst, E, Etot, att1);
    edge_exp1<<<(Etot * 4 + 255) / 256, 256>>>(dst, E, Etot);
    edge_agg1<<<(Etot * 32 + 255) / 256, 256>>>(src, dst, E, Etot);

    // layer 2 transforms with fused relu(h + b1): (M=N, K=256, Nout=64)
    gemm_dual<<<dim3(1, (N + 63) / 64, 2), 256>>>(
        x, Wl2, Wr2, N, 256, 64, b1, 2);

    int warps2 = (Etot + 1) / 2;
    edge_score2<<<(warps2 * 32 + 255) / 256, 256>>>(src, dst, E, Etot, att2);
    edge_exp2<<<(Etot + 255) / 256, 256>>>(dst, E, Etot);
    edge_agg2<<<(warps2 * 32 + 255) / 256, 256>>>(src, dst, E, Etot);

    pool_kernel<<<(N + 255) / 256, 256>>>(bat, N, b2, Wo);
    final_kernel<<<1, 64>>>((float*)d_out, G, bo);
}

// round 4
// speedup vs baseline: 2.4247x; 2.4247x over previous
#include <cuda_runtime.h>

#define MAXN 50000
#define MAXE 800000

// ---------------- scratch (device globals; no allocation allowed) ----------------
__device__ __align__(16) float g_xl1[(size_t)MAXN * 256];
__device__ __align__(16) float g_xr1[(size_t)MAXN * 256];
__device__ __align__(16) float g_h1 [(size_t)MAXN * 256];
__device__ __align__(16) float g_xl2[(size_t)MAXN * 64];
__device__ __align__(16) float g_xr2[(size_t)MAXN * 64];
__device__ __align__(16) float g_out2[(size_t)MAXN * 64];
__device__ int g_deg[MAXN];
__device__ int g_rowptr[MAXN + 1];
__device__ int g_woff[MAXN];
__device__ int g_csr_src[MAXE];
__device__ float g_acc[64];
__device__ float g_cnt[64];

__device__ __forceinline__ float lrelu(float v) { return v > 0.f ? v : 0.2f * v; }

// ---------------- init ----------------
__global__ void init0(int N) {
    int i = blockIdx.x * blockDim.x + threadIdx.x;
    if (i < N) g_deg[i] = 0;
    if (i < 64) { g_acc[i] = 0.f; g_cnt[i] = 0.f; }
}

// ---------------- CSR build (by dst; self-loops handled explicitly later) -------
__global__ void hist_kernel(const int* __restrict__ dst, int E) {
    int e = blockIdx.x * blockDim.x + threadIdx.x;
    if (e < E) atomicAdd(&g_deg[dst[e]], 1);
}

// one-block exclusive scan over N counters
__global__ void scan_kernel(int N) {
    __shared__ int sums[1024];
    int tid = threadIdx.x;
    int chunk = (N + 1023) / 1024;
    int lo = tid * chunk, hi = min(N, lo + chunk);
    int local = 0;
    for (int i = lo; i < hi; i++) local += g_deg[i];
    sums[tid] = local;
    __syncthreads();
    for (int s = 1; s < 1024; s <<= 1) {
        int v = 0;
        if (tid >= s) v = sums[tid - s];
        __syncthreads();
        if (tid >= s) sums[tid] += v;
        __syncthreads();
    }
    int run = (tid > 0) ? sums[tid - 1] : 0;
    for (int i = lo; i < hi; i++) {
        g_rowptr[i] = run;
        g_woff[i] = run;
        run += g_deg[i];
    }
    if (tid == 1023) g_rowptr[N] = run;
}

__global__ void scatter_kernel(const int* __restrict__ src, const int* __restrict__ dst, int E) {
    int e = blockIdx.x * blockDim.x + threadIdx.x;
    if (e >= E) return;
    int pos = atomicAdd(&g_woff[dst[e]], 1);
    g_csr_src[pos] = src[e];
}

// ---------------- SGEMM: 128xBN tile, 8x(BN/16) register microtile, 256 threads --
// layer==1: A = x (N x 128), B = Wl1/Wr1 (128x256), C = g_xl1/g_xr1 (Nout=256)
// layer==2: A = relu(g_h1 + b1) (N x 256), B = Wl2/Wr2 (256x64), C = g_xl2/g_xr2 (Nout=64)
template<int BN, int LAYER>
__global__ void __launch_bounds__(256) gemm_tile(const float* __restrict__ x_param,
                                                 const float* __restrict__ B0,
                                                 const float* __restrict__ B1,
                                                 int M, int K,
                                                 const float* __restrict__ abias)
{
    const int BM = 128, BK = 16;
    const int Nout = (LAYER == 1) ? 256 : 64;
    const int MN = BN / 16;  // micro cols per thread (8 or 4)
    const float* A = (LAYER == 1) ? x_param : g_h1;
    const float* B = blockIdx.z ? B1 : B0;
    float* C = (LAYER == 1) ? (blockIdx.z ? g_xr1 : g_xl1)
                            : (blockIdx.z ? g_xr2 : g_xl2);
    __shared__ float As[BK][BM];
    __shared__ float Bs[BK][BN];
    int tid = threadIdx.x;
    int tx = tid & 15, ty = tid >> 4;
    int m0 = blockIdx.y * BM, n0 = blockIdx.x * BN;
    float acc[8][MN];
    #pragma unroll
    for (int i = 0; i < 8; i++)
        #pragma unroll
        for (int j = 0; j < MN; j++) acc[i][j] = 0.f;

    int ar = tid >> 1, ak = (tid & 1) * 8;     // A: row ar, 8 consecutive k
    int br = tid >> 4;                          // B: row br (= tid/16, 0..15)
    int bc = (tid & 15) * (BN / 16);            // B: BN/16 consecutive cols

    for (int k0 = 0; k0 < K; k0 += BK) {
        // load A tile (128x16), store transposed As[k][m]
        float av[8];
        if (m0 + ar < M) {
            float4 v0 = *(const float4*)(A + (size_t)(m0 + ar) * K + k0 + ak);
            float4 v1 = *(const float4*)(A + (size_t)(m0 + ar) * K + k0 + ak + 4);
            av[0] = v0.x; av[1] = v0.y; av[2] = v0.z; av[3] = v0.w;
            av[4] = v1.x; av[5] = v1.y; av[6] = v1.z; av[7] = v1.w;
        } else {
            #pragma unroll
            for (int j = 0; j < 8; j++) av[j] = 0.f;
        }
        if (LAYER == 2) {
            #pragma unroll
            for (int j = 0; j < 8; j++) av[j] = fmaxf(av[j] + abias[k0 + ak + j], 0.f);
        }
        #pragma unroll
        for (int j = 0; j < 8; j++) As[ak + j][ar] = av[j];
        // load B tile (16xBN)
        #pragma unroll
        for (int j = 0; j < BN / 64; j++)
            *(float4*)&Bs[br][bc + j * 4] =
                *(const float4*)(B + (size_t)(k0 + br) * Nout + n0 + bc + j * 4);
        __syncthreads();
        #pragma unroll
        for (int kk = 0; kk < BK; kk++) {
            float a8[8], b8[MN];
            #pragma unroll
            for (int i = 0; i < 8; i += 4) *(float4*)&a8[i] = *(const float4*)&As[kk][ty * 8 + i];
            #pragma unroll
            for (int j = 0; j < MN; j += 4) *(float4*)&b8[j] = *(const float4*)&Bs[kk][tx * MN + j];
            #pragma unroll
            for (int i = 0; i < 8; i++)
                #pragma unroll
                for (int j = 0; j < MN; j++) acc[i][j] += a8[i] * b8[j];
        }
        __syncthreads();
    }
    #pragma unroll
    for (int i = 0; i < 8; i++) {
        int m = m0 + ty * 8 + i;
        if (m < M) {
            #pragma unroll
            for (int j = 0; j < MN; j += 4)
                *(float4*)(C + (size_t)m * Nout + n0 + tx * MN + j) =
                    make_float4(acc[i][j], acc[i][j+1], acc[i][j+2], acc[i][j+3]);
        }
    }
}

// ---------------- layer 1 fused attention (H=4, C=64): one warp per dst node -----
// out[d] = (Sum_e ex_e * xl[s_e]) / (Sum_e ex_e),  ex_e = exp(score_e)
// score safe without max-subtraction: |score| <~ 2.
__global__ void gat1_kernel(const float* __restrict__ att, int N)
{
    int d = (blockIdx.x * blockDim.x + threadIdx.x) >> 5;
    if (d >= N) return;
    int lane = threadIdx.x & 31;
    int off = lane * 8;   // head = lane>>3, 8 channels per lane

    float4 xr0 = *(const float4*)(g_xr1 + (size_t)d * 256 + off);
    float4 xr1v = *(const float4*)(g_xr1 + (size_t)d * 256 + off + 4);
    float4 aw0 = *(const float4*)(att + off);
    float4 aw1 = *(const float4*)(att + off + 4);

    float num[8];
    #pragma unroll
    for (int j = 0; j < 8; j++) num[j] = 0.f;
    float den = 0.f;

    int lo = g_rowptr[d], hi = g_rowptr[d + 1];
    // prefetch pipeline: current edge regs, issue next load before compute
    int s_next = (lo < hi) ? g_csr_src[lo] : d;   // last iteration = self loop
    float4 nx0 = *(const float4*)(g_xl1 + (size_t)s_next * 256 + off);
    float4 nx1 = *(const float4*)(g_xl1 + (size_t)s_next * 256 + off + 4);

    for (int e = lo; e <= hi; e++) {   // hi inclusive = self loop slot
        float4 x0 = nx0, x1 = nx1;
        if (e < hi) {
            int s2 = (e + 1 < hi) ? g_csr_src[e + 1] : d;
            nx0 = *(const float4*)(g_xl1 + (size_t)s2 * 256 + off);
            nx1 = *(const float4*)(g_xl1 + (size_t)s2 * 256 + off + 4);
        }
        float p = lrelu(x0.x + xr0.x) * aw0.x + lrelu(x0.y + xr0.y) * aw0.y
                + lrelu(x0.z + xr0.z) * aw0.z + lrelu(x0.w + xr0.w) * aw0.w
                + lrelu(x1.x + xr1v.x) * aw1.x + lrelu(x1.y + xr1v.y) * aw1.y
                + lrelu(x1.z + xr1v.z) * aw1.z + lrelu(x1.w + xr1v.w) * aw1.w;
        p += __shfl_xor_sync(0xffffffffu, p, 1);
        p += __shfl_xor_sync(0xffffffffu, p, 2);
        p += __shfl_xor_sync(0xffffffffu, p, 4);
        float ex = __expf(p);
        den += ex;
        num[0] += ex * x0.x; num[1] += ex * x0.y; num[2] += ex * x0.z; num[3] += ex * x0.w;
        num[4] += ex * x1.x; num[5] += ex * x1.y; num[6] += ex * x1.z; num[7] += ex * x1.w;
    }
    float inv = 1.f / (den + 1e-16f);
    *(float4*)(g_h1 + (size_t)d * 256 + off) =
        make_float4(num[0] * inv, num[1] * inv, num[2] * inv, num[3] * inv);
    *(float4*)(g_h1 + (size_t)d * 256 + off + 4) =
        make_float4(num[4] * inv, num[5] * inv, num[6] * inv, num[7] * inv);
}

// ---------------- layer 2 fused attention (H=1, C=64): one warp per dst node -----
__global__ void gat2_kernel(const float* __restrict__ att, int N)
{
    int d = (blockIdx.x * blockDim.x + threadIdx.x) >> 5;
    if (d >= N) return;
    int lane = threadIdx.x & 31;
    int off = lane * 2;

    float2 xr = *(const float2*)(g_xr2 + (size_t)d * 64 + off);
    float2 aw = *(const float2*)(att + off);

    float num0 = 0.f, num1 = 0.f, den = 0.f;
    int lo = g_rowptr[d], hi = g_rowptr[d + 1];
    int s_next = (lo < hi) ? g_csr_src[lo] : d;
    float2 nx = *(const float2*)(g_xl2 + (size_t)s_next * 64 + off);

    for (int e = lo; e <= hi; e++) {
        float2 xv = nx;
        if (e < hi) {
            int s2 = (e + 1 < hi) ? g_csr_src[e + 1] : d;
            nx = *(const float2*)(g_xl2 + (size_t)s2 * 64 + off);
        }
        float p = lrelu(xv.x + xr.x) * aw.x + lrelu(xv.y + xr.y) * aw.y;
        p += __shfl_xor_sync(0xffffffffu, p, 1);
        p += __shfl_xor_sync(0xffffffffu, p, 2);
        p += __shfl_xor_sync(0xffffffffu, p, 4);
        p += __shfl_xor_sync(0xffffffffu, p, 8);
        p += __shfl_xor_sync(0xffffffffu, p, 16);
        float ex = __expf(p);
        den += ex;
        num0 += ex * xv.x;
        num1 += ex * xv.y;
    }
    float inv = 1.f / (den + 1e-16f);
    *(float2*)(g_out2 + (size_t)d * 64 + off) = make_float2(num0 * inv, num1 * inv);
}

// ---------------- pooling: per-node dot with Wo, segment mean via atomics --------
__global__ void pool_kernel(const int* __restrict__ batch, int N,
                            const float* __restrict__ b2, const float* __restrict__ Wo)
{
    int n = blockIdx.x * blockDim.x + threadIdx.x;
    if (n >= N) return;
    const float4* row = (const float4*)(g_out2 + (size_t)n * 64);
    float y = 0.f;
    #pragma unroll
    for (int j = 0; j < 16; j++) {
        float4 v = row[j];
        float4 bb = ((const float4*)b2)[j];
        float4 w = ((const float4*)Wo)[j];
        y += (v.x + bb.x) * w.x + (v.y + bb.y) * w.y
           + (v.z + bb.z) * w.z + (v.w + bb.w) * w.w;
    }
    int g = batch[n];
    atomicAdd(&g_acc[g], y);
    atomicAdd(&g_cnt[g], 1.f);
}

__global__ void final_kernel(float* __restrict__ out, int G, const float* __restrict__ bo)
{
    int g = threadIdx.x;
    if (g < G) out[g] = g_acc[g] / fmaxf(g_cnt[g], 1.f) + bo[0];
}

// ---------------- launch ----------------
extern "C" void kernel_launch(void* const* d_in, const int* in_sizes, int n_in,
                              void* d_out, int out_size)
{
    const float* x    = (const float*)d_in[0];
    const int* ei     = (const int*)d_in[1];   // int32 (JAX x64 disabled)
    const int* bat    = (const int*)d_in[2];
    const float* Wl1 = (const float*)d_in[3];
    const float* Wr1 = (const float*)d_in[4];
    const float* att1 = (const float*)d_in[5];
    const float* b1  = (const float*)d_in[6];
    const float* Wl2 = (const float*)d_in[7];
    const float* Wr2 = (const float*)d_in[8];
    const float* att2 = (const float*)d_in[9];
    const float* b2  = (const float*)d_in[10];
    const float* Wo  = (const float*)d_in[11];
    const float* bo  = (const float*)d_in[12];

    int N = in_sizes[0] / 128;
    int E = in_sizes[1] / 2;
    int G = out_size;
    const int* src = ei;
    const int* dst = ei + E;

    init0<<<(N + 255) / 256, 256>>>(N);
    hist_kernel<<<(E + 255) / 256, 256>>>(dst, E);
    scan_kernel<<<1, 1024>>>(N);
    scatter_kernel<<<(E + 255) / 256, 256>>>(src, dst, E);

    // layer 1 transforms: xl1 = x@Wl1, xr1 = x@Wr1
    gemm_tile<128, 1><<<dim3(2, (N + 127) / 128, 2), 256>>>(x, Wl1, Wr1, N, 128, nullptr);
    gat1_kernel<<<(N * 32 + 255) / 256, 256>>>(att1, N);

    // layer 2 transforms with fused relu(h1 + b1)
    gemm_tile<64, 2><<<dim3(1, (N + 127) / 128, 2), 256>>>(x, Wl2, Wr2, N, 256, b1);
    gat2_kernel<<<(N * 32 + 255) / 256, 256>>>(att2, N);

    pool_kernel<<<(N + 255) / 256, 256>>>(bat, N, b2, Wo);
    final_kernel<<<1, 64>>>((float*)d_out, G, bo);
}

// round 6
// speedup vs baseline: 2.6767x; 1.1040x over previous
#include <cuda_runtime.h>
#include <cuda_bf16.h>
#include <cstdint>

#define MAXN 50000
#define MAXE 800000
typedef __nv_bfloat16 bf16;

// ---------------- scratch (device globals; no allocation allowed) ----------------
__device__ __align__(16) float g_xl1[(size_t)MAXN * 256];
__device__ __align__(16) float g_xr1[(size_t)MAXN * 256];
__device__ __align__(16) float g_xl2[(size_t)MAXN * 64];
__device__ __align__(16) float g_xr2[(size_t)MAXN * 64];
__device__ __align__(16) float g_out2[(size_t)MAXN * 64];
__device__ __align__(16) bf16 g_xhi[(size_t)MAXN * 128];
__device__ __align__(16) bf16 g_xlo[(size_t)MAXN * 128];
__device__ __align__(16) bf16 g_hhi[(size_t)MAXN * 256];
__device__ __align__(16) bf16 g_hlo[(size_t)MAXN * 256];
// weight transposes [n][k], bf16 split: w1l@0 (256x128), w1r@32768, w2l@65536 (64x256), w2r@81920
__device__ __align__(16) bf16 g_wthi[98304];
__device__ __align__(16) bf16 g_wtlo[98304];
__device__ int g_deg[MAXN];
__device__ int g_rowptr[MAXN + 1];
__device__ int g_woff[MAXN];
__device__ int g_csr_src[MAXE];
__device__ float g_acc[64];
__device__ float g_cnt[64];

__device__ __forceinline__ float lrelu(float v) { return v > 0.f ? v : 0.2f * v; }

__device__ __forceinline__ uint32_t smem_u32(const void* p) {
    uint32_t a;
    asm("{ .reg .u64 t; cvta.to.shared.u64 t, %1; cvt.u32.u64 %0, t; }" : "=r"(a) : "l"(p));
    return a;
}
#define LDSM4(r0, r1, r2, r3, addr) \
    asm volatile("ldmatrix.sync.aligned.m8n8.x4.shared.b16 {%0,%1,%2,%3}, [%4];" \
                 : "=r"(r0), "=r"(r1), "=r"(r2), "=r"(r3) : "r"(addr))

__device__ __forceinline__ void mma_bf16(float* d, const uint32_t* a, const uint32_t* b) {
    asm volatile("mma.sync.aligned.m16n8k16.row.col.f32.bf16.bf16.f32 "
                 "{%0,%1,%2,%3}, {%4,%5,%6,%7}, {%8,%9}, {%0,%1,%2,%3};"
                 : "+f"(d[0]), "+f"(d[1]), "+f"(d[2]), "+f"(d[3])
                 : "r"(a[0]), "r"(a[1]), "r"(a[2]), "r"(a[3]), "r"(b[0]), "r"(b[1]));
}

// ---------------- init ----------------
__global__ void init0(int N) {
    int i = blockIdx.x * blockDim.x + threadIdx.x;
    if (i < N) g_deg[i] = 0;
    if (i < 64) { g_acc[i] = 0.f; g_cnt[i] = 0.f; }
}

// ---------------- CSR build ----------------
__global__ void hist_kernel(const int* __restrict__ dst, int E) {
    int e = blockIdx.x * blockDim.x + threadIdx.x;
    if (e < E) atomicAdd(&g_deg[dst[e]], 1);
}
__global__ void scan_kernel(int N) {
    __shared__ int sums[1024];
    int tid = threadIdx.x;
    int chunk = (N + 1023) / 1024;
    int lo = tid * chunk, hi = min(N, lo + chunk);
    int local = 0;
    for (int i = lo; i < hi; i++) local += g_deg[i];
    sums[tid] = local;
    __syncthreads();
    for (int s = 1; s < 1024; s <<= 1) {
        int v = 0;
        if (tid >= s) v = sums[tid - s];
        __syncthreads();
        if (tid >= s) sums[tid] += v;
        __syncthreads();
    }
    int run = (tid > 0) ? sums[tid - 1] : 0;
    for (int i = lo; i < hi; i++) { g_rowptr[i] = run; g_woff[i] = run; run += g_deg[i]; }
    if (tid == 1023) g_rowptr[N] = run;
}
__global__ void scatter_kernel(const int* __restrict__ src, const int* __restrict__ dst, int E) {
    int e = blockIdx.x * blockDim.x + threadIdx.x;
    if (e >= E) return;
    int pos = atomicAdd(&g_woff[dst[e]], 1);
    g_csr_src[pos] = src[e];
}

// ---------------- bf16 split preps ----------------
__global__ void split_x(const float* __restrict__ x, int n) {
    int i = blockIdx.x * blockDim.x + threadIdx.x;
    if (i >= n) return;
    float v = x[i];
    bf16 h = __float2bfloat16(v);
    g_xhi[i] = h;
    g_xlo[i] = __float2bfloat16(v - __bfloat162float(h));
}
// W [K x Nout] row-major -> Wt [Nout x K] at offset off, split
__global__ void split_wt(const float* __restrict__ W, int K, int Nout, int off) {
    int i = blockIdx.x * blockDim.x + threadIdx.x;
    if (i >= K * Nout) return;
    int k = i / Nout, n = i % Nout;
    float v = W[i];
    bf16 h = __float2bfloat16(v);
    g_wthi[off + n * K + k] = h;
    g_wtlo[off + n * K + k] = __float2bfloat16(v - __bfloat162float(h));
}

// ---------------- mma.sync split-bf16 GEMM ----------------
// LAYER 1: C = x (Mx128) @ W (128x256) per z (Wl/Wr); BN=128, grid.x=2
// LAYER 2: C = h (Mx256) @ W (256x64)  per z (Wl/Wr); BN=64,  grid.x=1
template<int LAYER>
__global__ void __launch_bounds__(256) mma_gemm(int M)
{
    constexpr int K    = (LAYER == 1) ? 128 : 256;
    constexpr int BN   = (LAYER == 1) ? 128 : 64;
    constexpr int WN   = (LAYER == 1) ? 64 : 32;     // warp n-extent
    constexpr int NT   = WN / 8;                     // n8-tiles per warp
    constexpr int Nout = (LAYER == 1) ? 256 : 64;
    constexpr int BM   = 128;
    constexpr int SA   = K + 8;                      // padded strides (elements)
    constexpr int SB   = K + 8;
    constexpr int A_H = 0;
    constexpr int A_L = A_H + BM * SA * 2;
    constexpr int B_H = A_L + BM * SA * 2;
    constexpr int B_L = B_H + BN * SB * 2;

    extern __shared__ char smem[];
    uint32_t sb = smem_u32(smem);
    int tid = threadIdx.x;
    int wid = tid >> 5, lane = tid & 31;
    int m0 = blockIdx.y * BM;
    int n0 = blockIdx.x * BN;
    int z = blockIdx.z;

    const bf16* Ah = (LAYER == 1) ? g_xhi : g_hhi;
    const bf16* Al = (LAYER == 1) ? g_xlo : g_hlo;
    int woff = (LAYER == 1) ? (z ? 32768 : 0) : (z ? 81920 : 65536);
    float* C = (LAYER == 1) ? (z ? g_xr1 : g_xl1) : (z ? g_xr2 : g_xl2);

    // ---- load A (hi+lo) into padded smem ----
    constexpr int ACH = BM * K / 8;
    for (int c = tid; c < ACH; c += 256) {
        int row = c / (K / 8), kc = (c % (K / 8)) * 8;
        uint4 vh, vl;
        if (m0 + row < M) {
            vh = *(const uint4*)(Ah + (size_t)(m0 + row) * K + kc);
            vl = *(const uint4*)(Al + (size_t)(m0 + row) * K + kc);
        } else { vh = make_uint4(0, 0, 0, 0); vl = vh; }
        *(uint4*)(smem + A_H + (row * SA + kc) * 2) = vh;
        *(uint4*)(smem + A_L + (row * SA + kc) * 2) = vl;
    }
    // ---- load B (hi+lo): rows n0..n0+BN-1 of Wt[n][k] ----
    constexpr int BCH = BN * K / 8;
    for (int c = tid; c < BCH; c += 256) {
        int n = c / (K / 8), kc = (c % (K / 8)) * 8;
        uint4 vh = *(const uint4*)(g_wthi + woff + (size_t)(n0 + n) * K + kc);
        uint4 vl = *(const uint4*)(g_wtlo + woff + (size_t)(n0 + n) * K + kc);
        *(uint4*)(smem + B_H + (n * SB + kc) * 2) = vh;
        *(uint4*)(smem + B_L + (n * SB + kc) * 2) = vl;
    }
    __syncthreads();

    // ---- warp tiling: 4 m-warps x (8/4) n-warps ----
    int mwarp = (wid & 3) * 32;
    int nwarp = (wid >> 2) * WN;

    // ldmatrix lane address offsets
    int sel = lane >> 3, r8 = lane & 7;
    uint32_t aoff[2], boff[NT / 2];
    #pragma unroll
    for (int mt = 0; mt < 2; mt++)
        aoff[mt] = (uint32_t)(((mwarp + mt * 16 + (sel & 1) * 8 + r8) * SA + (sel >> 1) * 8) * 2);
    #pragma unroll
    for (int bt = 0; bt < NT / 2; bt++)
        boff[bt] = (uint32_t)(((nwarp + bt * 16 + (sel >> 1) * 8 + r8) * SB + (sel & 1) * 8) * 2);

    float d[2][NT][4];
    #pragma unroll
    for (int mt = 0; mt < 2; mt++)
        #pragma unroll
        for (int nt = 0; nt < NT; nt++)
            #pragma unroll
            for (int j = 0; j < 4; j++) d[mt][nt][j] = 0.f;

    #pragma unroll
    for (int ks = 0; ks < K / 16; ks++) {
        uint32_t kb = ks * 32;   // bytes
        uint32_t ah[2][4], al[2][4], bh[2 * NT], bl[2 * NT];
        #pragma unroll
        for (int mt = 0; mt < 2; mt++) {
            LDSM4(ah[mt][0], ah[mt][1], ah[mt][2], ah[mt][3], sb + A_H + aoff[mt] + kb);
            LDSM4(al[mt][0], al[mt][1], al[mt][2], al[mt][3], sb + A_L + aoff[mt] + kb);
        }
        #pragma unroll
        for (int bt = 0; bt < NT / 2; bt++) {
            LDSM4(bh[bt*4], bh[bt*4+1], bh[bt*4+2], bh[bt*4+3], sb + B_H + boff[bt] + kb);
            LDSM4(bl[bt*4], bl[bt*4+1], bl[bt*4+2], bl[bt*4+3], sb + B_L + boff[bt] + kb);
        }
        #pragma unroll
        for (int mt = 0; mt < 2; mt++)
            #pragma unroll
            for (int nt = 0; nt < NT; nt++) {
                mma_bf16(d[mt][nt], ah[mt], &bh[nt * 2]);   // hi*hi
                mma_bf16(d[mt][nt], ah[mt], &bl[nt * 2]);   // hi*lo
                mma_bf16(d[mt][nt], al[mt], &bh[nt * 2]);   // lo*hi
            }
    }

    // ---- epilogue: write fp32 ----
    int g4 = lane >> 2, tig = lane & 3;
    #pragma unroll
    for (int mt = 0; mt < 2; mt++) {
        int mrow = m0 + mwarp + mt * 16 + g4;
        #pragma unroll
        for (int nt = 0; nt < NT; nt++) {
            int col = n0 + nwarp + nt * 8 + tig * 2;
            if (mrow < M)
                *(float2*)(C + (size_t)mrow * Nout + col) = make_float2(d[mt][nt][0], d[mt][nt][1]);
            if (mrow + 8 < M)
                *(float2*)(C + (size_t)(mrow + 8) * Nout + col) = make_float2(d[mt][nt][2], d[mt][nt][3]);
        }
    }
}

// ---------------- layer 1 fused attention (H=4, C=64): one warp per dst node -----
// epilogue fuses: h = relu(out + b1), split to bf16 hi/lo for layer-2 MMA
__global__ void gat1_kernel(const float* __restrict__ att, const float* __restrict__ b1, int N)
{
    int d = (blockIdx.x * blockDim.x + threadIdx.x) >> 5;
    if (d >= N) return;
    int lane = threadIdx.x & 31;
    int off = lane * 8;

    float4 xr0 = *(const float4*)(g_xr1 + (size_t)d * 256 + off);
    float4 xr1v = *(const float4*)(g_xr1 + (size_t)d * 256 + off + 4);
    float4 aw0 = *(const float4*)(att + off);
    float4 aw1 = *(const float4*)(att + off + 4);

    float num[8];
    #pragma unroll
    for (int j = 0; j < 8; j++) num[j] = 0.f;
    float den = 0.f;

    int lo = g_rowptr[d], hi = g_rowptr[d + 1];
    int s_next = (lo < hi) ? g_csr_src[lo] : d;
    float4 nx0 = *(const float4*)(g_xl1 + (size_t)s_next * 256 + off);
    float4 nx1 = *(const float4*)(g_xl1 + (size_t)s_next * 256 + off + 4);

    for (int e = lo; e <= hi; e++) {   // last slot = self loop
        float4 x0 = nx0, x1 = nx1;
        if (e < hi) {
            int s2 = (e + 1 < hi) ? g_csr_src[e + 1] : d;
            nx0 = *(const float4*)(g_xl1 + (size_t)s2 * 256 + off);
            nx1 = *(const float4*)(g_xl1 + (size_t)s2 * 256 + off + 4);
        }
        float p = lrelu(x0.x + xr0.x) * aw0.x + lrelu(x0.y + xr0.y) * aw0.y
                + lrelu(x0.z + xr0.z) * aw0.z + lrelu(x0.w + xr0.w) * aw0.w
                + lrelu(x1.x + xr1v.x) * aw1.x + lrelu(x1.y + xr1v.y) * aw1.y
                + lrelu(x1.z + xr1v.z) * aw1.z + lrelu(x1.w + xr1v.w) * aw1.w;
        p += __shfl_xor_sync(0xffffffffu, p, 1);
        p += __shfl_xor_sync(0xffffffffu, p, 2);
        p += __shfl_xor_sync(0xffffffffu, p, 4);
        float ex = __expf(p);
        den += ex;
        num[0] += ex * x0.x; num[1] += ex * x0.y; num[2] += ex * x0.z; num[3] += ex * x0.w;
        num[4] += ex * x1.x; num[5] += ex * x1.y; num[6] += ex * x1.z; num[7] += ex * x1.w;
    }
    float inv = 1.f / (den + 1e-16f);
    float4 bb0 = *(const float4*)(b1 + off);
    float4 bb1 = *(const float4*)(b1 + off + 4);
    float bias[8] = {bb0.x, bb0.y, bb0.z, bb0.w, bb1.x, bb1.y, bb1.z, bb1.w};
    bf16 hi8[8], lo8[8];
    #pragma unroll
    for (int j = 0; j < 8; j++) {
        float v = fmaxf(num[j] * inv + bias[j], 0.f);
        bf16 h = __float2bfloat16(v);
        hi8[j] = h;
        lo8[j] = __float2bfloat16(v - __bfloat162float(h));
    }
    *(uint4*)(g_hhi + (size_t)d * 256 + off) = *(uint4*)hi8;
    *(uint4*)(g_hlo + (size_t)d * 256 + off) = *(uint4*)lo8;
}

// ---------------- layer 2 fused attention (H=1, C=64): one warp per dst node -----
__global__ void gat2_kernel(const float* __restrict__ att, int N)
{
    int d = (blockIdx.x * blockDim.x + threadIdx.x) >> 5;
    if (d >= N) return;
    int lane = threadIdx.x & 31;
    int off = lane * 2;

    float2 xr = *(const float2*)(g_xr2 + (size_t)d * 64 + off);
    float2 aw = *(const float2*)(att + off);

    float num0 = 0.f, num1 = 0.f, den = 0.f;
    int lo = g_rowptr[d], hi = g_rowptr[d + 1];
    int s_next = (lo < hi) ? g_csr_src[lo] : d;
    float2 nx = *(const float2*)(g_xl2 + (size_t)s_next * 64 + off);

    for (int e = lo; e <= hi; e++) {
        float2 xv = nx;
        if (e < hi) {
            int s2 = (e + 1 < hi) ? g_csr_src[e + 1] : d;
            nx = *(const float2*)(g_xl2 + (size_t)s2 * 64 + off);
        }
        float p = lrelu(xv.x + xr.x) * aw.x + lrelu(xv.y + xr.y) * aw.y;
        p += __shfl_xor_sync(0xffffffffu, p, 1);
        p += __shfl_xor_sync(0xffffffffu, p, 2);
        p += __shfl_xor_sync(0xffffffffu, p, 4);
        p += __shfl_xor_sync(0xffffffffu, p, 8);
        p += __shfl_xor_sync(0xffffffffu, p, 16);
        float ex = __expf(p);
        den += ex;
        num0 += ex * xv.x;
        num1 += ex * xv.y;
    }
    float inv = 1.f / (den + 1e-16f);
    *(float2*)(g_out2 + (size_t)d * 64 + off) = make_float2(num0 * inv, num1 * inv);
}

// ---------------- pooling ----------------
__global__ void pool_kernel(const int* __restrict__ batch, int N,
                            const float* __restrict__ b2, const float* __restrict__ Wo)
{
    int n = blockIdx.x * blockDim.x + threadIdx.x;
    if (n >= N) return;
    const float4* row = (const float4*)(g_out2 + (size_t)n * 64);
    float y = 0.f;
    #pragma unroll
    for (int j = 0; j < 16; j++) {
        float4 v = row[j];
        float4 bb = ((const float4*)b2)[j];
        float4 w = ((const float4*)Wo)[j];
        y += (v.x + bb.x) * w.x + (v.y + bb.y) * w.y
           + (v.z + bb.z) * w.z + (v.w + bb.w) * w.w;
    }
    int g = batch[n];
    atomicAdd(&g_acc[g], y);
    atomicAdd(&g_cnt[g], 1.f);
}

__global__ void final_kernel(float* __restrict__ out, int G, const float* __restrict__ bo)
{
    int g = threadIdx.x;
    if (g < G) out[g] = g_acc[g] / fmaxf(g_cnt[g], 1.f) + bo[0];
}

// ---------------- launch ----------------
extern "C" void kernel_launch(void* const* d_in, const int* in_sizes, int n_in,
                              void* d_out, int out_size)
{
    const float* x    = (const float*)d_in[0];
    const int* ei     = (const int*)d_in[1];
    const int* bat    = (const int*)d_in[2];
    const float* Wl1 = (const float*)d_in[3];
    const float* Wr1 = (const float*)d_in[4];
    const float* att1 = (const float*)d_in[5];
    const float* b1  = (const float*)d_in[6];
    const float* Wl2 = (const float*)d_in[7];
    const float* Wr2 = (const float*)d_in[8];
    const float* att2 = (const float*)d_in[9];
    const float* b2  = (const float*)d_in[10];
    const float* Wo  = (const float*)d_in[11];
    const float* bo  = (const float*)d_in[12];

    int N = in_sizes[0] / 128;
    int E = in_sizes[1] / 2;
    int G = out_size;
    const int* src = ei;
    const int* dst = ei + E;
    int tiles = (N + 127) / 128;

    // smem sizes: layer1: 2*(128*136 + 128*136)*2 = 139264 ; layer2: 2*(128*264 + 64*264)*2 = 202752
    const int SM1 = 2 * (128 * 136 + 128 * 136) * 2;
    const int SM2 = 2 * (128 * 264 + 64 * 264) * 2;
    cudaFuncSetAttribute(mma_gemm<1>, cudaFuncAttributeMaxDynamicSharedMemorySize, SM1);
    cudaFuncSetAttribute(mma_gemm<2>, cudaFuncAttributeMaxDynamicSharedMemorySize, SM2);

    init0<<<(N + 255) / 256, 256>>>(N);
    hist_kernel<<<(E + 255) / 256, 256>>>(dst, E);
    scan_kernel<<<1, 1024>>>(N);
    scatter_kernel<<<(E + 255) / 256, 256>>>(src, dst, E);

    split_x<<<(N * 128 + 255) / 256, 256>>>(x, N * 128);
    split_wt<<<(128 * 256 + 255) / 256, 256>>>(Wl1, 128, 256, 0);
    split_wt<<<(128 * 256 + 255) / 256, 256>>>(Wr1, 128, 256, 32768);
    split_wt<<<(256 * 64 + 255) / 256, 256>>>(Wl2, 256, 64, 65536);
    split_wt<<<(256 * 64 + 255) / 256, 256>>>(Wr2, 256, 64, 81920);

    mma_gemm<1><<<dim3(2, tiles, 2), 256, SM1>>>(N);
    gat1_kernel<<<(N * 32 + 255) / 256, 256>>>(att1, b1, N);

    mma_gemm<2><<<dim3(1, tiles, 2), 256, SM2>>>(N);
    gat2_kernel<<<(N * 32 + 255) / 256, 256>>>(att2, N);

    pool_kernel<<<(N + 255) / 256, 256>>>(bat, N, b2, Wo);
    final_kernel<<<1, 64>>>((float*)d_out, G, bo);
}

// round 7
// speedup vs baseline: 2.6865x; 1.0037x over previous
#include <cuda_runtime.h>
#include <cuda_bf16.h>
#include <cstdint>

#define MAXN 50000
#define MAXE 800000
typedef __nv_bfloat16 bf16;

// ---------------- scratch (device globals; no allocation allowed) ----------------
__device__ __align__(16) float g_xl1[(size_t)MAXN * 256];
__device__ __align__(16) float g_xr1[(size_t)MAXN * 256];
__device__ __align__(16) float g_xl2[(size_t)MAXN * 64];
__device__ __align__(16) float g_xr2[(size_t)MAXN * 64];
__device__ __align__(16) float g_out2[(size_t)MAXN * 64];
__device__ __align__(16) bf16 g_xhi[(size_t)MAXN * 128];
__device__ __align__(16) bf16 g_xlo[(size_t)MAXN * 128];
__device__ __align__(16) bf16 g_hhi[(size_t)MAXN * 256];
__device__ __align__(16) bf16 g_hlo[(size_t)MAXN * 256];
// weight transposes [n][k], bf16 split: w1l@0 (256x128), w1r@32768, w2l@65536 (64x256), w2r@81920
__device__ __align__(16) bf16 g_wthi[98304];
__device__ __align__(16) bf16 g_wtlo[98304];
__device__ int g_deg[MAXN];
__device__ int g_rowptr[MAXN + 1];
__device__ int g_woff[MAXN];
__device__ int g_csr_src[MAXE];
__device__ float g_acc[64];
__device__ float g_cnt[64];

__device__ __forceinline__ float lrelu(float v) { return v > 0.f ? v : 0.2f * v; }

__device__ __forceinline__ uint32_t smem_u32(const void* p) {
    uint32_t a;
    asm("{ .reg .u64 t; cvta.to.shared.u64 t, %1; cvt.u32.u64 %0, t; }" : "=r"(a) : "l"(p));
    return a;
}
#define LDSM4(r0, r1, r2, r3, addr) \
    asm volatile("ldmatrix.sync.aligned.m8n8.x4.shared.b16 {%0,%1,%2,%3}, [%4];" \
                 : "=r"(r0), "=r"(r1), "=r"(r2), "=r"(r3) : "r"(addr))

__device__ __forceinline__ void mma_bf16(float* d, const uint32_t* a, const uint32_t* b) {
    asm volatile("mma.sync.aligned.m16n8k16.row.col.f32.bf16.bf16.f32 "
                 "{%0,%1,%2,%3}, {%4,%5,%6,%7}, {%8,%9}, {%0,%1,%2,%3};"
                 : "+f"(d[0]), "+f"(d[1]), "+f"(d[2]), "+f"(d[3])
                 : "r"(a[0]), "r"(a[1]), "r"(a[2]), "r"(a[3]), "r"(b[0]), "r"(b[1]));
}

// ---------------- init ----------------
__global__ void init0(int N) {
    int i = blockIdx.x * blockDim.x + threadIdx.x;
    if (i < N) g_deg[i] = 0;
    if (i < 64) { g_acc[i] = 0.f; g_cnt[i] = 0.f; }
}

// ---------------- CSR build ----------------
__global__ void hist_kernel(const int* __restrict__ dst, int E) {
    int e = blockIdx.x * blockDim.x + threadIdx.x;
    if (e < E) atomicAdd(&g_deg[dst[e]], 1);
}
__global__ void scan_kernel(int N) {
    __shared__ int sums[1024];
    int tid = threadIdx.x;
    int chunk = (N + 1023) / 1024;
    int lo = tid * chunk, hi = min(N, lo + chunk);
    int local = 0;
    for (int i = lo; i < hi; i++) local += g_deg[i];
    sums[tid] = local;
    __syncthreads();
    for (int s = 1; s < 1024; s <<= 1) {
        int v = 0;
        if (tid >= s) v = sums[tid - s];
        __syncthreads();
        if (tid >= s) sums[tid] += v;
        __syncthreads();
    }
    int run = (tid > 0) ? sums[tid - 1] : 0;
    for (int i = lo; i < hi; i++) { g_rowptr[i] = run; g_woff[i] = run; run += g_deg[i]; }
    if (tid == 1023) g_rowptr[N] = run;
}
__global__ void scatter_kernel(const int* __restrict__ src, const int* __restrict__ dst, int E) {
    int e = blockIdx.x * blockDim.x + threadIdx.x;
    if (e >= E) return;
    int pos = atomicAdd(&g_woff[dst[e]], 1);
    g_csr_src[pos] = src[e];
}

// ---------------- bf16 split preps ----------------
__global__ void split_x(const float* __restrict__ x, int n) {
    int i = blockIdx.x * blockDim.x + threadIdx.x;
    if (i >= n) return;
    float v = x[i];
    bf16 h = __float2bfloat16(v);
    g_xhi[i] = h;
    g_xlo[i] = __float2bfloat16(v - __bfloat162float(h));
}
// W [K x Nout] row-major -> Wt [Nout x K] at offset off, split
__global__ void split_wt(const float* __restrict__ W, int K, int Nout, int off) {
    int i = blockIdx.x * blockDim.x + threadIdx.x;
    if (i >= K * Nout) return;
    int k = i / Nout, n = i % Nout;
    float v = W[i];
    bf16 h = __float2bfloat16(v);
    g_wthi[off + n * K + k] = h;
    g_wtlo[off + n * K + k] = __float2bfloat16(v - __bfloat162float(h));
}

// ---------------- mma.sync split-bf16 GEMM ----------------
// LAYER 1: C = x (Mx128) @ W (128x256) per z (Wl/Wr); BN=128, grid.x=2
// LAYER 2: C = h (Mx256) @ W (256x64)  per z (Wl/Wr); BN=64,  grid.x=1
template<int LAYER>
__global__ void __launch_bounds__(256) mma_gemm(int M)
{
    constexpr int K    = (LAYER == 1) ? 128 : 256;
    constexpr int BN   = (LAYER == 1) ? 128 : 64;
    constexpr int WN   = (LAYER == 1) ? 64 : 32;     // warp n-extent
    constexpr int NT   = WN / 8;                     // n8-tiles per warp
    constexpr int Nout = (LAYER == 1) ? 256 : 64;
    constexpr int BM   = 128;
    constexpr int SA   = K + 8;                      // padded strides (elements)
    constexpr int SB   = K + 8;
    constexpr int A_H = 0;
    constexpr int A_L = A_H + BM * SA * 2;
    constexpr int B_H = A_L + BM * SA * 2;
    constexpr int B_L = B_H + BN * SB * 2;

    extern __shared__ char smem[];
    uint32_t sb = smem_u32(smem);
    int tid = threadIdx.x;
    int wid = tid >> 5, lane = tid & 31;
    int m0 = blockIdx.y * BM;
    int n0 = blockIdx.x * BN;
    int z = blockIdx.z;

    const bf16* Ah = (LAYER == 1) ? g_xhi : g_hhi;
    const bf16* Al = (LAYER == 1) ? g_xlo : g_hlo;
    int woff = (LAYER == 1) ? (z ? 32768 : 0) : (z ? 81920 : 65536);
    float* C = (LAYER == 1) ? (z ? g_xr1 : g_xl1) : (z ? g_xr2 : g_xl2);

    // ---- load A (hi+lo) into padded smem ----
    constexpr int ACH = BM * K / 8;
    for (int c = tid; c < ACH; c += 256) {
        int row = c / (K / 8), kc = (c % (K / 8)) * 8;
        uint4 vh, vl;
        if (m0 + row < M) {
            vh = *(const uint4*)(Ah + (size_t)(m0 + row) * K + kc);
            vl = *(const uint4*)(Al + (size_t)(m0 + row) * K + kc);
        } else { vh = make_uint4(0, 0, 0, 0); vl = vh; }
        *(uint4*)(smem + A_H + (row * SA + kc) * 2) = vh;
        *(uint4*)(smem + A_L + (row * SA + kc) * 2) = vl;
    }
    // ---- load B (hi+lo): rows n0..n0+BN-1 of Wt[n][k] ----
    constexpr int BCH = BN * K / 8;
    for (int c = tid; c < BCH; c += 256) {
        int n = c / (K / 8), kc = (c % (K / 8)) * 8;
        uint4 vh = *(const uint4*)(g_wthi + woff + (size_t)(n0 + n) * K + kc);
        uint4 vl = *(const uint4*)(g_wtlo + woff + (size_t)(n0 + n) * K + kc);
        *(uint4*)(smem + B_H + (n * SB + kc) * 2) = vh;
        *(uint4*)(smem + B_L + (n * SB + kc) * 2) = vl;
    }
    __syncthreads();

    // ---- warp tiling: 4 m-warps x (8/4) n-warps ----
    int mwarp = (wid & 3) * 32;
    int nwarp = (wid >> 2) * WN;

    // ldmatrix lane address offsets
    int sel = lane >> 3, r8 = lane & 7;
    uint32_t aoff[2], boff[NT / 2];
    #pragma unroll
    for (int mt = 0; mt < 2; mt++)
        aoff[mt] = (uint32_t)(((mwarp + mt * 16 + (sel & 1) * 8 + r8) * SA + (sel >> 1) * 8) * 2);
    #pragma unroll
    for (int bt = 0; bt < NT / 2; bt++)
        boff[bt] = (uint32_t)(((nwarp + bt * 16 + (sel >> 1) * 8 + r8) * SB + (sel & 1) * 8) * 2);

    float d[2][NT][4];
    #pragma unroll
    for (int mt = 0; mt < 2; mt++)
        #pragma unroll
        for (int nt = 0; nt < NT; nt++)
            #pragma unroll
            for (int j = 0; j < 4; j++) d[mt][nt][j] = 0.f;

    #pragma unroll
    for (int ks = 0; ks < K / 16; ks++) {
        uint32_t kb = ks * 32;   // bytes
        uint32_t ah[2][4], al[2][4], bh[2 * NT], bl[2 * NT];
        #pragma unroll
        for (int mt = 0; mt < 2; mt++) {
            LDSM4(ah[mt][0], ah[mt][1], ah[mt][2], ah[mt][3], sb + A_H + aoff[mt] + kb);
            LDSM4(al[mt][0], al[mt][1], al[mt][2], al[mt][3], sb + A_L + aoff[mt] + kb);
        }
        #pragma unroll
        for (int bt = 0; bt < NT / 2; bt++) {
            LDSM4(bh[bt*4], bh[bt*4+1], bh[bt*4+2], bh[bt*4+3], sb + B_H + boff[bt] + kb);
            LDSM4(bl[bt*4], bl[bt*4+1], bl[bt*4+2], bl[bt*4+3], sb + B_L + boff[bt] + kb);
        }
        #pragma unroll
        for (int mt = 0; mt < 2; mt++)
            #pragma unroll
            for (int nt = 0; nt < NT; nt++) {
                mma_bf16(d[mt][nt], ah[mt], &bh[nt * 2]);   // hi*hi
                mma_bf16(d[mt][nt], ah[mt], &bl[nt * 2]);   // hi*lo
                mma_bf16(d[mt][nt], al[mt], &bh[nt * 2]);   // lo*hi
            }
    }

    // ---- epilogue: write fp32 ----
    int g4 = lane >> 2, tig = lane & 3;
    #pragma unroll
    for (int mt = 0; mt < 2; mt++) {
        int mrow = m0 + mwarp + mt * 16 + g4;
        #pragma unroll
        for (int nt = 0; nt < NT; nt++) {
            int col = n0 + nwarp + nt * 8 + tig * 2;
            if (mrow < M)
                *(float2*)(C + (size_t)mrow * Nout + col) = make_float2(d[mt][nt][0], d[mt][nt][1]);
            if (mrow + 8 < M)
                *(float2*)(C + (size_t)(mrow + 8) * Nout + col) = make_float2(d[mt][nt][2], d[mt][nt][3]);
        }
    }
}

// ---------------- layer 1 fused attention (H=4, C=64): one warp per dst node -----
// epilogue fuses: h = relu(out + b1), split to bf16 hi/lo for layer-2 MMA
__global__ void gat1_kernel(const float* __restrict__ att, const float* __restrict__ b1, int N)
{
    int d = (blockIdx.x * blockDim.x + threadIdx.x) >> 5;
    if (d >= N) return;
    int lane = threadIdx.x & 31;
    int off = lane * 8;

    float4 xr0 = *(const float4*)(g_xr1 + (size_t)d * 256 + off);
    float4 xr1v = *(const float4*)(g_xr1 + (size_t)d * 256 + off + 4);
    float4 aw0 = *(const float4*)(att + off);
    float4 aw1 = *(const float4*)(att + off + 4);

    float num[8];
    #pragma unroll
    for (int j = 0; j < 8; j++) num[j] = 0.f;
    float den = 0.f;

    int lo = g_rowptr[d], hi = g_rowptr[d + 1];
    int s_next = (lo < hi) ? g_csr_src[lo] : d;
    float4 nx0 = *(const float4*)(g_xl1 + (size_t)s_next * 256 + off);
    float4 nx1 = *(const float4*)(g_xl1 + (size_t)s_next * 256 + off + 4);

    for (int e = lo; e <= hi; e++) {   // last slot = self loop
        float4 x0 = nx0, x1 = nx1;
        if (e < hi) {
            int s2 = (e + 1 < hi) ? g_csr_src[e + 1] : d;
            nx0 = *(const float4*)(g_xl1 + (size_t)s2 * 256 + off);
            nx1 = *(const float4*)(g_xl1 + (size_t)s2 * 256 + off + 4);
        }
        float p = lrelu(x0.x + xr0.x) * aw0.x + lrelu(x0.y + xr0.y) * aw0.y
                + lrelu(x0.z + xr0.z) * aw0.z + lrelu(x0.w + xr0.w) * aw0.w
                + lrelu(x1.x + xr1v.x) * aw1.x + lrelu(x1.y + xr1v.y) * aw1.y
                + lrelu(x1.z + xr1v.z) * aw1.z + lrelu(x1.w + xr1v.w) * aw1.w;
        p += __shfl_xor_sync(0xffffffffu, p, 1);
        p += __shfl_xor_sync(0xffffffffu, p, 2);
        p += __shfl_xor_sync(0xffffffffu, p, 4);
        float ex = __expf(p);
        den += ex;
        num[0] += ex * x0.x; num[1] += ex * x0.y; num[2] += ex * x0.z; num[3] += ex * x0.w;
        num[4] += ex * x1.x; num[5] += ex * x1.y; num[6] += ex * x1.z; num[7] += ex * x1.w;
    }
    float inv = 1.f / (den + 1e-16f);
    float4 bb0 = *(const float4*)(b1 + off);
    float4 bb1 = *(const float4*)(b1 + off + 4);
    float bias[8] = {bb0.x, bb0.y, bb0.z, bb0.w, bb1.x, bb1.y, bb1.z, bb1.w};
    bf16 hi8[8], lo8[8];
    #pragma unroll
    for (int j = 0; j < 8; j++) {
        float v = fmaxf(num[j] * inv + bias[j], 0.f);
        bf16 h = __float2bfloat16(v);
        hi8[j] = h;
        lo8[j] = __float2bfloat16(v - __bfloat162float(h));
    }
    *(uint4*)(g_hhi + (size_t)d * 256 + off) = *(uint4*)hi8;
    *(uint4*)(g_hlo + (size_t)d * 256 + off) = *(uint4*)lo8;
}

// ---------------- layer 2 fused attention (H=1, C=64): one warp per dst node -----
__global__ void gat2_kernel(const float* __restrict__ att, int N)
{
    int d = (blockIdx.x * blockDim.x + threadIdx.x) >> 5;
    if (d >= N) return;
    int lane = threadIdx.x & 31;
    int off = lane * 2;

    float2 xr = *(const float2*)(g_xr2 + (size_t)d * 64 + off);
    float2 aw = *(const float2*)(att + off);

    float num0 = 0.f, num1 = 0.f, den = 0.f;
    int lo = g_rowptr[d], hi = g_rowptr[d + 1];
    int s_next = (lo < hi) ? g_csr_src[lo] : d;
    float2 nx = *(const float2*)(g_xl2 + (size_t)s_next * 64 + off);

    for (int e = lo; e <= hi; e++) {
        float2 xv = nx;
        if (e < hi) {
            int s2 = (e + 1 < hi) ? g_csr_src[e + 1] : d;
            nx = *(const float2*)(g_xl2 + (size_t)s2 * 64 + off);
        }
        float p = lrelu(xv.x + xr.x) * aw.x + lrelu(xv.y + xr.y) * aw.y;
        p += __shfl_xor_sync(0xffffffffu, p, 1);
        p += __shfl_xor_sync(0xffffffffu, p, 2);
        p += __shfl_xor_sync(0xffffffffu, p, 4);
        p += __shfl_xor_sync(0xffffffffu, p, 8);
        p += __shfl_xor_sync(0xffffffffu, p, 16);
        float ex = __expf(p);
        den += ex;
        num0 += ex * xv.x;
        num1 += ex * xv.y;
    }
    float inv = 1.f / (den + 1e-16f);
    *(float2*)(g_out2 + (size_t)d * 64 + off) = make_float2(num0 * inv, num1 * inv);
}

// ---------------- pooling ----------------
__global__ void pool_kernel(const int* __restrict__ batch, int N,
                            const float* __restrict__ b2, const float* __restrict__ Wo)
{
    int n = blockIdx.x * blockDim.x + threadIdx.x;
    if (n >= N) return;
    const float4* row = (const float4*)(g_out2 + (size_t)n * 64);
    float y = 0.f;
    #pragma unroll
    for (int j = 0; j < 16; j++) {
        float4 v = row[j];
        float4 bb = ((const float4*)b2)[j];
        float4 w = ((const float4*)Wo)[j];
        y += (v.x + bb.x) * w.x + (v.y + bb.y) * w.y
           + (v.z + bb.z) * w.z + (v.w + bb.w) * w.w;
    }
    int g = batch[n];
    atomicAdd(&g_acc[g], y);
    atomicAdd(&g_cnt[g], 1.f);
}

__global__ void final_kernel(float* __restrict__ out, int G, const float* __restrict__ bo)
{
    int g = threadIdx.x;
    if (g < G) out[g] = g_acc[g] / fmaxf(g_cnt[g], 1.f) + bo[0];
}

// ---------------- launch ----------------
extern "C" void kernel_launch(void* const* d_in, const int* in_sizes, int n_in,
                              void* d_out, int out_size)
{
    const float* x    = (const float*)d_in[0];
    const int* ei     = (const int*)d_in[1];
    const int* bat    = (const int*)d_in[2];
    const float* Wl1 = (const float*)d_in[3];
    const float* Wr1 = (const float*)d_in[4];
    const float* att1 = (const float*)d_in[5];
    const float* b1  = (const float*)d_in[6];
    const float* Wl2 = (const float*)d_in[7];
    const float* Wr2 = (const float*)d_in[8];
    const float* att2 = (const float*)d_in[9];
    const float* b2  = (const float*)d_in[10];
    const float* Wo  = (const float*)d_in[11];
    const float* bo  = (const float*)d_in[12];

    int N = in_sizes[0] / 128;
    int E = in_sizes[1] / 2;
    int G = out_size;
    const int* src = ei;
    const int* dst = ei + E;
    int tiles = (N + 127) / 128;

    // smem sizes: layer1: 2*(128*136 + 128*136)*2 = 139264 ; layer2: 2*(128*264 + 64*264)*2 = 202752
    const int SM1 = 2 * (128 * 136 + 128 * 136) * 2;
    const int SM2 = 2 * (128 * 264 + 64 * 264) * 2;
    cudaFuncSetAttribute(mma_gemm<1>, cudaFuncAttributeMaxDynamicSharedMemorySize, SM1);
    cudaFuncSetAttribute(mma_gemm<2>, cudaFuncAttributeMaxDynamicSharedMemorySize, SM2);

    init0<<<(N + 255) / 256, 256>>>(N);
    hist_kernel<<<(E + 255) / 256, 256>>>(dst, E);
    scan_kernel<<<1, 1024>>>(N);
    scatter_kernel<<<(E + 255) / 256, 256>>>(src, dst, E);

    split_x<<<(N * 128 + 255) / 256, 256>>>(x, N * 128);
    split_wt<<<(128 * 256 + 255) / 256, 256>>>(Wl1, 128, 256, 0);
    split_wt<<<(128 * 256 + 255) / 256, 256>>>(Wr1, 128, 256, 32768);
    split_wt<<<(256 * 64 + 255) / 256, 256>>>(Wl2, 256, 64, 65536);
    split_wt<<<(256 * 64 + 255) / 256, 256>>>(Wr2, 256, 64, 81920);

    mma_gemm<1><<<dim3(2, tiles, 2), 256, SM1>>>(N);
    gat1_kernel<<<(N * 32 + 255) / 256, 256>>>(att1, b1, N);

    mma_gemm<2><<<dim3(1, tiles, 2), 256, SM2>>>(N);
    gat2_kernel<<<(N * 32 + 255) / 256, 256>>>(att2, N);

    pool_kernel<<<(N + 255) / 256, 256>>>(bat, N, b2, Wo);
    final_kernel<<<1, 64>>>((float*)d_out, G, bo);
}

// round 8
// speedup vs baseline: 3.3775x; 1.2572x over previous
#include <cuda_runtime.h>
#include <cuda_bf16.h>
#include <cstdint>

#define MAXN 50000
#define MAXE 800000
typedef __nv_bfloat16 bf16;

// ---------------- scratch (device globals; no allocation allowed) ----------------
__device__ __align__(16) float g_xr1[(size_t)MAXN * 256];
__device__ __align__(16) float g_xr2[(size_t)MAXN * 64];
__device__ __align__(16) bf16 g_xl1b[(size_t)MAXN * 256];
__device__ __align__(16) bf16 g_xl2b[(size_t)MAXN * 64];
__device__ __align__(16) bf16 g_xhi[(size_t)MAXN * 128];
__device__ __align__(16) bf16 g_xlo[(size_t)MAXN * 128];
__device__ __align__(16) bf16 g_hhi[(size_t)MAXN * 256];
__device__ __align__(16) bf16 g_hlo[(size_t)MAXN * 256];
// weight transposes [n][k], bf16 split: w1l@0 (256x128), w1r@32768, w2l@65536 (64x256), w2r@81920
__device__ __align__(16) bf16 g_wthi[98304];
__device__ __align__(16) bf16 g_wtlo[98304];
__device__ int g_deg[MAXN];
__device__ int g_rowptr[MAXN + 1];
__device__ int g_woff[MAXN];
__device__ int g_csr_src[MAXE];
__device__ int g_bsum[256];
__device__ float g_acc[64];
__device__ float g_cnt[64];

__device__ __forceinline__ float lrelu(float v) { return v > 0.f ? v : 0.2f * v; }

__device__ __forceinline__ uint32_t smem_u32(const void* p) {
    uint32_t a;
    asm("{ .reg .u64 t; cvta.to.shared.u64 t, %1; cvt.u32.u64 %0, t; }" : "=r"(a) : "l"(p));
    return a;
}
#define LDSM4(r0, r1, r2, r3, addr) \
    asm volatile("ldmatrix.sync.aligned.m8n8.x4.shared.b16 {%0,%1,%2,%3}, [%4];" \
                 : "=r"(r0), "=r"(r1), "=r"(r2), "=r"(r3) : "r"(addr))

__device__ __forceinline__ void mma_bf16(float* d, const uint32_t* a, const uint32_t* b) {
    asm volatile("mma.sync.aligned.m16n8k16.row.col.f32.bf16.bf16.f32 "
                 "{%0,%1,%2,%3}, {%4,%5,%6,%7}, {%8,%9}, {%0,%1,%2,%3};"
                 : "+f"(d[0]), "+f"(d[1]), "+f"(d[2]), "+f"(d[3])
                 : "r"(a[0]), "r"(a[1]), "r"(a[2]), "r"(a[3]), "r"(b[0]), "r"(b[1]));
}

// ---------------- init ----------------
__global__ void init0(int N) {
    int i = blockIdx.x * blockDim.x + threadIdx.x;
    if (i < N) g_deg[i] = 0;
    if (i < 64) { g_acc[i] = 0.f; g_cnt[i] = 0.f; }
}

// ---------------- prep: split x to bf16 hi/lo + degree histogram + graph counts --
__global__ void prep_kernel(const float* __restrict__ x, const int* __restrict__ dst,
                            const int* __restrict__ batch, int N, int E) {
    int i = blockIdx.x * blockDim.x + threadIdx.x;
    if (i < N * 128) {
        float v = x[i];
        bf16 h = __float2bfloat16(v);
        g_xhi[i] = h;
        g_xlo[i] = __float2bfloat16(v - __bfloat162float(h));
    }
    if (i < E) atomicAdd(&g_deg[dst[i]], 1);
    if (i < N) atomicAdd(&g_cnt[batch[i]], 1.f);
}

// all four weight transposes+splits in one launch
__global__ void split_wt_all(const float* __restrict__ Wl1, const float* __restrict__ Wr1,
                             const float* __restrict__ Wl2, const float* __restrict__ Wr2) {
    int i = blockIdx.x * blockDim.x + threadIdx.x;
    if (i >= 98304) return;
    const float* W;
    int K, Nout, off, j;
    if (i < 32768)      { W = Wl1; K = 128; Nout = 256; off = 0;     j = i; }
    else if (i < 65536) { W = Wr1; K = 128; Nout = 256; off = 32768; j = i - 32768; }
    else if (i < 81920) { W = Wl2; K = 256; Nout = 64;  off = 65536; j = i - 65536; }
    else                { W = Wr2; K = 256; Nout = 64;  off = 81920; j = i - 81920; }
    int k = j / Nout, n = j % Nout;
    float v = W[j];
    bf16 h = __float2bfloat16(v);
    g_wthi[off + n * K + k] = h;
    g_wtlo[off + n * K + k] = __float2bfloat16(v - __bfloat162float(h));
}

// ---------------- CSR build: coalesced 3-stage scan ----------------
__global__ void blocksum_kernel(int N) {
    __shared__ int sh[256];
    int tid = threadIdx.x;
    int i = blockIdx.x * 256 + tid;
    sh[tid] = (i < N) ? g_deg[i] : 0;
    __syncthreads();
    for (int s = 128; s > 0; s >>= 1) {
        if (tid < s) sh[tid] += sh[tid + s];
        __syncthreads();
    }
    if (tid == 0) g_bsum[blockIdx.x] = sh[0];
}
__global__ void scanb_kernel(int nb) {
    __shared__ int sh[256];
    int tid = threadIdx.x;
    int v = (tid < nb) ? g_bsum[tid] : 0;
    sh[tid] = v;
    __syncthreads();
    for (int s = 1; s < 256; s <<= 1) {
        int t = (tid >= s) ? sh[tid - s] : 0;
        __syncthreads();
        sh[tid] += t;
        __syncthreads();
    }
    if (tid < nb) g_bsum[tid] = sh[tid] - v;   // exclusive
}
__global__ void rowptr_kernel(int N, int E) {
    __shared__ int sh[256];
    int tid = threadIdx.x;
    int i = blockIdx.x * 256 + tid;
    int v = (i < N) ? g_deg[i] : 0;
    sh[tid] = v;
    __syncthreads();
    for (int s = 1; s < 256; s <<= 1) {
        int t = (tid >= s) ? sh[tid - s] : 0;
        __syncthreads();
        sh[tid] += t;
        __syncthreads();
    }
    if (i < N) {
        int ex = g_bsum[blockIdx.x] + sh[tid] - v;
        g_rowptr[i] = ex;
        g_woff[i] = ex;
        if (i == N - 1) g_rowptr[N] = E;
    }
}
__global__ void scatter_kernel(const int* __restrict__ src, const int* __restrict__ dst, int E) {
    int e = blockIdx.x * blockDim.x + threadIdx.x;
    if (e >= E) return;
    int pos = atomicAdd(&g_woff[dst[e]], 1);
    g_csr_src[pos] = src[e];
}

// ---------------- mma.sync split-bf16 GEMM ----------------
// LAYER 1: C = x (Mx128) @ W (128x256) per z; z=0 -> bf16 g_xl1b, z=1 -> fp32 g_xr1
// LAYER 2: C = h (Mx256) @ W (256x64)  per z; z=0 -> bf16 g_xl2b, z=1 -> fp32 g_xr2
template<int LAYER>
__global__ void __launch_bounds__(256) mma_gemm(int M)
{
    constexpr int K    = (LAYER == 1) ? 128 : 256;
    constexpr int KCH  = (LAYER == 1) ? 1 : 2;       // 128-wide k chunks
    constexpr int BN   = (LAYER == 1) ? 128 : 64;
    constexpr int WN   = (LAYER == 1) ? 64 : 32;
    constexpr int NT   = WN / 8;
    constexpr int Nout = (LAYER == 1) ? 256 : 64;
    constexpr int BM   = 128;
    constexpr int SA   = 136;                        // 128 + 8 pad
    constexpr int A_H = 0;
    constexpr int A_L = A_H + BM * SA * 2;
    constexpr int B_H = A_L + BM * SA * 2;
    constexpr int B_L = B_H + BN * SA * 2;

    extern __shared__ char smem[];
    uint32_t sb = smem_u32(smem);
    int tid = threadIdx.x;
    int wid = tid >> 5, lane = tid & 31;
    int m0 = blockIdx.y * BM;
    int n0 = blockIdx.x * BN;
    int z = blockIdx.z;

    const bf16* Ah = (LAYER == 1) ? g_xhi : g_hhi;
    const bf16* Al = (LAYER == 1) ? g_xlo : g_hlo;
    int woff = (LAYER == 1) ? (z ? 32768 : 0) : (z ? 81920 : 65536);

    int mwarp = (wid & 3) * 32;
    int nwarp = (wid >> 2) * WN;
    int sel = lane >> 3, r8 = lane & 7;
    uint32_t aoff[2], boff[NT / 2];
    #pragma unroll
    for (int mt = 0; mt < 2; mt++)
        aoff[mt] = (uint32_t)(((mwarp + mt * 16 + (sel & 1) * 8 + r8) * SA + (sel >> 1) * 8) * 2);
    #pragma unroll
    for (int bt = 0; bt < NT / 2; bt++)
        boff[bt] = (uint32_t)(((nwarp + bt * 16 + (sel >> 1) * 8 + r8) * SA + (sel & 1) * 8) * 2);

    float d[2][NT][4];
    #pragma unroll
    for (int mt = 0; mt < 2; mt++)
        #pragma unroll
        for (int nt = 0; nt < NT; nt++)
            #pragma unroll
            for (int j = 0; j < 4; j++) d[mt][nt][j] = 0.f;

    for (int kc = 0; kc < KCH; kc++) {
        if (kc > 0) __syncthreads();
        // ---- load A chunk (BM x 128, hi+lo) ----
        for (int c = tid; c < BM * 16; c += 256) {
            int row = c >> 4, kcl = (c & 15) * 8;
            uint4 vh, vl;
            if (m0 + row < M) {
                vh = *(const uint4*)(Ah + (size_t)(m0 + row) * K + kc * 128 + kcl);
                vl = *(const uint4*)(Al + (size_t)(m0 + row) * K + kc * 128 + kcl);
            } else { vh = make_uint4(0, 0, 0, 0); vl = vh; }
            *(uint4*)(smem + A_H + (row * SA + kcl) * 2) = vh;
            *(uint4*)(smem + A_L + (row * SA + kcl) * 2) = vl;
        }
        // ---- load B chunk (BN x 128, hi+lo) ----
        for (int c = tid; c < BN * 16; c += 256) {
            int n = c >> 4, kcl = (c & 15) * 8;
            uint4 vh = *(const uint4*)(g_wthi + woff + (size_t)(n0 + n) * K + kc * 128 + kcl);
            uint4 vl = *(const uint4*)(g_wtlo + woff + (size_t)(n0 + n) * K + kc * 128 + kcl);
            *(uint4*)(smem + B_H + (n * SA + kcl) * 2) = vh;
            *(uint4*)(smem + B_L + (n * SA + kcl) * 2) = vl;
        }
        __syncthreads();

        #pragma unroll
        for (int ks = 0; ks < 8; ks++) {
            uint32_t kb = ks * 32;
            uint32_t ah[2][4], al[2][4], bh[2 * NT], bl[2 * NT];
            #pragma unroll
            for (int mt = 0; mt < 2; mt++) {
                LDSM4(ah[mt][0], ah[mt][1], ah[mt][2], ah[mt][3], sb + A_H + aoff[mt] + kb);
                LDSM4(al[mt][0], al[mt][1], al[mt][2], al[mt][3], sb + A_L + aoff[mt] + kb);
            }
            #pragma unroll
            for (int bt = 0; bt < NT / 2; bt++) {
                LDSM4(bh[bt*4], bh[bt*4+1], bh[bt*4+2], bh[bt*4+3], sb + B_H + boff[bt] + kb);
                LDSM4(bl[bt*4], bl[bt*4+1], bl[bt*4+2], bl[bt*4+3], sb + B_L + boff[bt] + kb);
            }
            #pragma unroll
            for (int mt = 0; mt < 2; mt++)
                #pragma unroll
                for (int nt = 0; nt < NT; nt++) {
                    mma_bf16(d[mt][nt], ah[mt], &bh[nt * 2]);
                    mma_bf16(d[mt][nt], ah[mt], &bl[nt * 2]);
                    mma_bf16(d[mt][nt], al[mt], &bh[nt * 2]);
                }
        }
    }

    // ---- epilogue ----
    int g4 = lane >> 2, tig = lane & 3;
    if (z == 0) {   // bf16 output (consumed by edge gathers)
        bf16* Cb = (LAYER == 1) ? g_xl1b : g_xl2b;
        #pragma unroll
        for (int mt = 0; mt < 2; mt++) {
            int mrow = m0 + mwarp + mt * 16 + g4;
            #pragma unroll
            for (int nt = 0; nt < NT; nt++) {
                int col = n0 + nwarp + nt * 8 + tig * 2;
                if (mrow < M) {
                    __nv_bfloat162 p = __float22bfloat162_rn(make_float2(d[mt][nt][0], d[mt][nt][1]));
                    *(uint32_t*)(Cb + (size_t)mrow * Nout + col) = *(uint32_t*)&p;
                }
                if (mrow + 8 < M) {
                    __nv_bfloat162 p = __float22bfloat162_rn(make_float2(d[mt][nt][2], d[mt][nt][3]));
                    *(uint32_t*)(Cb + (size_t)(mrow + 8) * Nout + col) = *(uint32_t*)&p;
                }
            }
        }
    } else {        // fp32 output (per-dst operand, read once)
        float* C = (LAYER == 1) ? g_xr1 : g_xr2;
        #pragma unroll
        for (int mt = 0; mt < 2; mt++) {
            int mrow = m0 + mwarp + mt * 16 + g4;
            #pragma unroll
            for (int nt = 0; nt < NT; nt++) {
                int col = n0 + nwarp + nt * 8 + tig * 2;
                if (mrow < M)
                    *(float2*)(C + (size_t)mrow * Nout + col) = make_float2(d[mt][nt][0], d[mt][nt][1]);
                if (mrow + 8 < M)
                    *(float2*)(C + (size_t)(mrow + 8) * Nout + col) = make_float2(d[mt][nt][2], d[mt][nt][3]);
            }
        }
    }
}

// ---------------- layer 1 fused attention (H=4, C=64): one warp per dst node -----
// xl gathered as bf16; epilogue: h = relu(out + b1) split to bf16 hi/lo
__global__ void gat1_kernel(const float* __restrict__ att, const float* __restrict__ b1, int N)
{
    int d = (blockIdx.x * blockDim.x + threadIdx.x) >> 5;
    if (d >= N) return;
    int lane = threadIdx.x & 31;
    int off = lane * 8;

    float4 xr0 = *(const float4*)(g_xr1 + (size_t)d * 256 + off);
    float4 xr1v = *(const float4*)(g_xr1 + (size_t)d * 256 + off + 4);
    float4 aw0 = *(const float4*)(att + off);
    float4 aw1 = *(const float4*)(att + off + 4);

    float num[8];
    #pragma unroll
    for (int j = 0; j < 8; j++) num[j] = 0.f;
    float den = 0.f;

    int lo = g_rowptr[d], hi = g_rowptr[d + 1];
    int s_next = (lo < hi) ? g_csr_src[lo] : d;
    uint4 nx = *(const uint4*)(g_xl1b + (size_t)s_next * 256 + off);

    for (int e = lo; e <= hi; e++) {   // last slot = self loop
        uint4 cur = nx;
        if (e < hi) {
            int s2 = (e + 1 < hi) ? g_csr_src[e + 1] : d;
            nx = *(const uint4*)(g_xl1b + (size_t)s2 * 256 + off);
        }
        float2 f0 = __bfloat1622float2(*(__nv_bfloat162*)&cur.x);
        float2 f1 = __bfloat1622float2(*(__nv_bfloat162*)&cur.y);
        float2 f2 = __bfloat1622float2(*(__nv_bfloat162*)&cur.z);
        float2 f3 = __bfloat1622float2(*(__nv_bfloat162*)&cur.w);
        float p = lrelu(f0.x + xr0.x) * aw0.x + lrelu(f0.y + xr0.y) * aw0.y
                + lrelu(f1.x + xr0.z) * aw0.z + lrelu(f1.y + xr0.w) * aw0.w
                + lrelu(f2.x + xr1v.x) * aw1.x + lrelu(f2.y + xr1v.y) * aw1.y
                + lrelu(f3.x + xr1v.z) * aw1.z + lrelu(f3.y + xr1v.w) * aw1.w;
        p += __shfl_xor_sync(0xffffffffu, p, 1);
        p += __shfl_xor_sync(0xffffffffu, p, 2);
        p += __shfl_xor_sync(0xffffffffu, p, 4);
        float ex = __expf(p);
        den += ex;
        num[0] += ex * f0.x; num[1] += ex * f0.y; num[2] += ex * f1.x; num[3] += ex * f1.y;
        num[4] += ex * f2.x; num[5] += ex * f2.y; num[6] += ex * f3.x; num[7] += ex * f3.y;
    }
    float inv = 1.f / (den + 1e-16f);
    float4 bb0 = *(const float4*)(b1 + off);
    float4 bb1 = *(const float4*)(b1 + off + 4);
    float bias[8] = {bb0.x, bb0.y, bb0.z, bb0.w, bb1.x, bb1.y, bb1.z, bb1.w};
    bf16 hi8[8], lo8[8];
    #pragma unroll
    for (int j = 0; j < 8; j++) {
        float v = fmaxf(num[j] * inv + bias[j], 0.f);
        bf16 h = __float2bfloat16(v);
        hi8[j] = h;
        lo8[j] = __float2bfloat16(v - __bfloat162float(h));
    }
    *(uint4*)(g_hhi + (size_t)d * 256 + off) = *(uint4*)hi8;
    *(uint4*)(g_hlo + (size_t)d * 256 + off) = *(uint4*)lo8;
}

// ---------------- layer 2 fused attention + pooling: one warp per dst node -------
__global__ void gat2_kernel(const float* __restrict__ att, const int* __restrict__ batch,
                            const float* __restrict__ b2, const float* __restrict__ Wo, int N)
{
    int d = (blockIdx.x * blockDim.x + threadIdx.x) >> 5;
    if (d >= N) return;
    int lane = threadIdx.x & 31;
    int off = lane * 2;

    float2 xr = *(const float2*)(g_xr2 + (size_t)d * 64 + off);
    float2 aw = *(const float2*)(att + off);

    float num0 = 0.f, num1 = 0.f, den = 0.f;
    int lo = g_rowptr[d], hi = g_rowptr[d + 1];
    int s_next = (lo < hi) ? g_csr_src[lo] : d;
    uint32_t nx = *(const uint32_t*)(g_xl2b + (size_t)s_next * 64 + off);

    for (int e = lo; e <= hi; e++) {
        uint32_t cur = nx;
        if (e < hi) {
            int s2 = (e + 1 < hi) ? g_csr_src[e + 1] : d;
            nx = *(const uint32_t*)(g_xl2b + (size_t)s2 * 64 + off);
        }
        float2 xv = __bfloat1622float2(*(__nv_bfloat162*)&cur);
        float p = lrelu(xv.x + xr.x) * aw.x + lrelu(xv.y + xr.y) * aw.y;
        p += __shfl_xor_sync(0xffffffffu, p, 1);
        p += __shfl_xor_sync(0xffffffffu, p, 2);
        p += __shfl_xor_sync(0xffffffffu, p, 4);
        p += __shfl_xor_sync(0xffffffffu, p, 8);
        p += __shfl_xor_sync(0xffffffffu, p, 16);
        float ex = __expf(p);
        den += ex;
        num0 += ex * xv.x;
        num1 += ex * xv.y;
    }
    float inv = 1.f / (den + 1e-16f);
    // fused pooling: y = Sum_ch (out[ch] + b2[ch]) * Wo[ch]
    float2 bb = *(const float2*)(b2 + off);
    float2 wo = *(const float2*)(Wo + off);
    float y = (num0 * inv + bb.x) * wo.x + (num1 * inv + bb.y) * wo.y;
    y += __shfl_xor_sync(0xffffffffu, y, 1);
    y += __shfl_xor_sync(0xffffffffu, y, 2);
    y += __shfl_xor_sync(0xffffffffu, y, 4);
    y += __shfl_xor_sync(0xffffffffu, y, 8);
    y += __shfl_xor_sync(0xffffffffu, y, 16);
    if (lane == 0) atomicAdd(&g_acc[batch[d]], y);
}

__global__ void final_kernel(float* __restrict__ out, int G, const float* __restrict__ bo)
{
    int g = threadIdx.x;
    if (g < G) out[g] = g_acc[g] / fmaxf(g_cnt[g], 1.f) + bo[0];
}

// ---------------- launch ----------------
extern "C" void kernel_launch(void* const* d_in, const int* in_sizes, int n_in,
                              void* d_out, int out_size)
{
    const float* x    = (const float*)d_in[0];
    const int* ei     = (const int*)d_in[1];
    const int* bat    = (const int*)d_in[2];
    const float* Wl1 = (const float*)d_in[3];
    const float* Wr1 = (const float*)d_in[4];
    const float* att1 = (const float*)d_in[5];
    const float* b1  = (const float*)d_in[6];
    const float* Wl2 = (const float*)d_in[7];
    const float* Wr2 = (const float*)d_in[8];
    const float* att2 = (const float*)d_in[9];
    const float* b2  = (const float*)d_in[10];
    const float* Wo  = (const float*)d_in[11];
    const float* bo  = (const float*)d_in[12];

    int N = in_sizes[0] / 128;
    int E = in_sizes[1] / 2;
    int G = out_size;
    const int* src = ei;
    const int* dst = ei + E;
    int tiles = (N + 127) / 128;
    int nb = (N + 255) / 256;

    // smem: L1 = 4 bufs of 128x136 bf16 = 139264 ; L2 = A 2x34816 + B 2x17408 = 104448
    const int SM1 = 4 * 128 * 136 * 2;
    const int SM2 = 2 * 128 * 136 * 2 + 2 * 64 * 136 * 2;
    cudaFuncSetAttribute(mma_gemm<1>, cudaFuncAttributeMaxDynamicSharedMemorySize, SM1);
    cudaFuncSetAttribute(mma_gemm<2>, cudaFuncAttributeMaxDynamicSharedMemorySize, SM2);

    init0<<<(N + 255) / 256, 256>>>(N);
    prep_kernel<<<(N * 128 + 255) / 256, 256>>>(x, dst, bat, N, E);
    split_wt_all<<<(98304 + 255) / 256, 256>>>(Wl1, Wr1, Wl2, Wr2);

    blocksum_kernel<<<nb, 256>>>(N);
    scanb_kernel<<<1, 256>>>(nb);
    rowptr_kernel<<<nb, 256>>>(N, E);
    scatter_kernel<<<(E + 255) / 256, 256>>>(src, dst, E);

    mma_gemm<1><<<dim3(2, tiles, 2), 256, SM1>>>(N);
    gat1_kernel<<<(N * 32 + 255) / 256, 256>>>(att1, b1, N);

    mma_gemm<2><<<dim3(1, tiles, 2), 256, SM2>>>(N);
    gat2_kernel<<<(N * 32 + 255) / 256, 256>>>(att2, bat, b2, Wo, N);

    final_kernel<<<1, 64>>>((float*)d_out, G, bo);
}

// round 9
// speedup vs baseline: 3.4198x; 1.0125x over previous
#include <cuda_runtime.h>
#include <cuda_bf16.h>
#include <cstdint>

#define MAXN 50000
#define MAXE 800000
typedef __nv_bfloat16 bf16;

// ---------------- scratch (device globals; no allocation allowed) ----------------
__device__ __align__(16) bf16 g_xl1b[(size_t)MAXN * 256];
__device__ __align__(16) bf16 g_xr1b[(size_t)MAXN * 256];
__device__ __align__(16) bf16 g_xl2b[(size_t)MAXN * 64];
__device__ __align__(16) bf16 g_xr2b[(size_t)MAXN * 64];
__device__ __align__(16) bf16 g_xhi[(size_t)MAXN * 128];
__device__ __align__(16) bf16 g_xlo[(size_t)MAXN * 128];
__device__ __align__(16) bf16 g_hhi[(size_t)MAXN * 256];
__device__ __align__(16) bf16 g_hlo[(size_t)MAXN * 256];
// weight transposes [n][k], bf16 split: w1l@0 (256x128), w1r@32768, w2l@65536 (64x256), w2r@81920
__device__ __align__(16) bf16 g_wthi[98304];
__device__ __align__(16) bf16 g_wtlo[98304];
__device__ int g_deg[MAXN];
__device__ int g_rowptr[MAXN + 1];
__device__ int g_woff[MAXN];
__device__ int g_csr_src[MAXE];
__device__ int g_bsum[256];
__device__ float g_acc[64];
__device__ float g_cnt[64];

__device__ __forceinline__ float lrelu(float v) { return v > 0.f ? v : 0.2f * v; }

__device__ __forceinline__ uint32_t smem_u32(const void* p) {
    uint32_t a;
    asm("{ .reg .u64 t; cvta.to.shared.u64 t, %1; cvt.u32.u64 %0, t; }" : "=r"(a) : "l"(p));
    return a;
}
__device__ __forceinline__ void cp16(uint32_t s, const void* g) {
    asm volatile("cp.async.cg.shared.global [%0], [%1], 16;" :: "r"(s), "l"(g));
}
#define CP_COMMIT() asm volatile("cp.async.commit_group;" ::: "memory")
#define LDSM4(r0, r1, r2, r3, addr) \
    asm volatile("ldmatrix.sync.aligned.m8n8.x4.shared.b16 {%0,%1,%2,%3}, [%4];" \
                 : "=r"(r0), "=r"(r1), "=r"(r2), "=r"(r3) : "r"(addr))

__device__ __forceinline__ void mma_bf16(float* d, const uint32_t* a, const uint32_t* b) {
    asm volatile("mma.sync.aligned.m16n8k16.row.col.f32.bf16.bf16.f32 "
                 "{%0,%1,%2,%3}, {%4,%5,%6,%7}, {%8,%9}, {%0,%1,%2,%3};"
                 : "+f"(d[0]), "+f"(d[1]), "+f"(d[2]), "+f"(d[3])
                 : "r"(a[0]), "r"(a[1]), "r"(a[2]), "r"(a[3]), "r"(b[0]), "r"(b[1]));
}

// ---------------- init ----------------
__global__ void init0(int N) {
    int i = blockIdx.x * blockDim.x + threadIdx.x;
    if (i < N) g_deg[i] = 0;
    if (i < 64) { g_acc[i] = 0.f; g_cnt[i] = 0.f; }
}

// ---------------- prep: split x + degree histogram + graph counts ----------------
__global__ void prep_kernel(const float* __restrict__ x, const int* __restrict__ dst,
                            const int* __restrict__ batch, int N, int E) {
    int i = blockIdx.x * blockDim.x + threadIdx.x;
    if (i < N * 128) {
        float v = x[i];
        bf16 h = __float2bfloat16(v);
        g_xhi[i] = h;
        g_xlo[i] = __float2bfloat16(v - __bfloat162float(h));
    }
    if (i < E) atomicAdd(&g_deg[dst[i]], 1);
    if (i < N) atomicAdd(&g_cnt[batch[i]], 1.f);
}

__global__ void split_wt_all(const float* __restrict__ Wl1, const float* __restrict__ Wr1,
                             const float* __restrict__ Wl2, const float* __restrict__ Wr2) {
    int i = blockIdx.x * blockDim.x + threadIdx.x;
    if (i >= 98304) return;
    const float* W;
    int K, Nout, off, j;
    if (i < 32768)      { W = Wl1; K = 128; Nout = 256; off = 0;     j = i; }
    else if (i < 65536) { W = Wr1; K = 128; Nout = 256; off = 32768; j = i - 32768; }
    else if (i < 81920) { W = Wl2; K = 256; Nout = 64;  off = 65536; j = i - 65536; }
    else                { W = Wr2; K = 256; Nout = 64;  off = 81920; j = i - 81920; }
    int k = j / Nout, n = j % Nout;
    float v = W[j];
    bf16 h = __float2bfloat16(v);
    g_wthi[off + n * K + k] = h;
    g_wtlo[off + n * K + k] = __float2bfloat16(v - __bfloat162float(h));
}

// ---------------- CSR build: coalesced 3-stage scan ----------------
__global__ void blocksum_kernel(int N) {
    __shared__ int sh[256];
    int tid = threadIdx.x;
    int i = blockIdx.x * 256 + tid;
    sh[tid] = (i < N) ? g_deg[i] : 0;
    __syncthreads();
    for (int s = 128; s > 0; s >>= 1) {
        if (tid < s) sh[tid] += sh[tid + s];
        __syncthreads();
    }
    if (tid == 0) g_bsum[blockIdx.x] = sh[0];
}
__global__ void scanb_kernel(int nb) {
    __shared__ int sh[256];
    int tid = threadIdx.x;
    int v = (tid < nb) ? g_bsum[tid] : 0;
    sh[tid] = v;
    __syncthreads();
    for (int s = 1; s < 256; s <<= 1) {
        int t = (tid >= s) ? sh[tid - s] : 0;
        __syncthreads();
        sh[tid] += t;
        __syncthreads();
    }
    if (tid < nb) g_bsum[tid] = sh[tid] - v;
}
__global__ void rowptr_kernel(int N, int E) {
    __shared__ int sh[256];
    int tid = threadIdx.x;
    int i = blockIdx.x * 256 + tid;
    int v = (i < N) ? g_deg[i] : 0;
    sh[tid] = v;
    __syncthreads();
    for (int s = 1; s < 256; s <<= 1) {
        int t = (tid >= s) ? sh[tid - s] : 0;
        __syncthreads();
        sh[tid] += t;
        __syncthreads();
    }
    if (i < N) {
        int ex = g_bsum[blockIdx.x] + sh[tid] - v;
        g_rowptr[i] = ex;
        g_woff[i] = ex;
        if (i == N - 1) g_rowptr[N] = E;
    }
}
__global__ void scatter_kernel(const int* __restrict__ src, const int* __restrict__ dst, int E) {
    int e = blockIdx.x * blockDim.x + threadIdx.x;
    if (e >= E) return;
    int pos = atomicAdd(&g_woff[dst[e]], 1);
    g_csr_src[pos] = src[e];
}

// ---------------- layer-1 GEMM: A resident, 4 B-chunks double-buffered ----------
// C[m][z*256 + n] for z in {0,1}: x (Mx128) @ W (128x256); outputs bf16 xl1b / xr1b
__global__ void __launch_bounds__(256) mma_gemm1(int M)
{
    constexpr int SA = 136;
    constexpr int A_H = 0, A_L = 34816;       // 128*136*2
    constexpr int BUF0 = 69632, BUFSZ = 69632; // per buf: B_H +0, B_L +34816
    extern __shared__ char smem[];
    uint32_t sb = smem_u32(smem);
    int tid = threadIdx.x;
    int wid = tid >> 5, lane = tid & 31;
    int m0 = blockIdx.x * 128;

    // A load (once): 128 rows x 128 k, hi+lo
    for (int c = tid; c < 128 * 16; c += 256) {
        int row = c >> 4, kcl = (c & 15) * 8;
        int rg = min(m0 + row, M - 1);
        uint32_t ta = (uint32_t)(row * SA + kcl) * 2;
        cp16(sb + A_H + ta, g_xhi + (size_t)rg * 128 + kcl);
        cp16(sb + A_L + ta, g_xlo + (size_t)rg * 128 + kcl);
    }
    // B chunk 0
    {
        const bf16* WH = g_wthi;   // z=0, nb=0
        const bf16* WL = g_wtlo;
        for (int c = tid; c < 128 * 16; c += 256) {
            int n = c >> 4, kcl = (c & 15) * 8;
            uint32_t ta = (uint32_t)(n * SA + kcl) * 2;
            cp16(sb + BUF0 + ta, WH + (size_t)n * 128 + kcl);
            cp16(sb + BUF0 + 34816 + ta, WL + (size_t)n * 128 + kcl);
        }
    }
    CP_COMMIT();

    int mwarp = (wid & 3) * 32;
    int nwarp = (wid >> 2) * 64;
    int sel = lane >> 3, r8 = lane & 7;
    uint32_t aoff[2], boff[4];
    #pragma unroll
    for (int mt = 0; mt < 2; mt++)
        aoff[mt] = (uint32_t)(((mwarp + mt * 16 + (sel & 1) * 8 + r8) * SA + (sel >> 1) * 8) * 2);
    #pragma unroll
    for (int bt = 0; bt < 4; bt++)
        boff[bt] = (uint32_t)(((nwarp + bt * 16 + (sel >> 1) * 8 + r8) * SA + (sel & 1) * 8) * 2);

    int g4 = lane >> 2, tig = lane & 3;

    for (int c = 0; c < 4; c++) {
        if (c < 3) {   // prefetch next B chunk
            int z = (c + 1) >> 1, nb = (c + 1) & 1;
            const bf16* WH = g_wthi + (z ? 32768 : 0) + (size_t)nb * 128 * 128;
            const bf16* WL = g_wtlo + (z ? 32768 : 0) + (size_t)nb * 128 * 128;
            uint32_t bbase = sb + BUF0 + ((c + 1) & 1) * BUFSZ;
            for (int t = tid; t < 128 * 16; t += 256) {
                int n = t >> 4, kcl = (t & 15) * 8;
                uint32_t ta = (uint32_t)(n * SA + kcl) * 2;
                cp16(bbase + ta, WH + (size_t)n * 128 + kcl);
                cp16(bbase + 34816 + ta, WL + (size_t)n * 128 + kcl);
            }
            CP_COMMIT();
            asm volatile("cp.async.wait_group 1;" ::: "memory");
        } else {
            asm volatile("cp.async.wait_group 0;" ::: "memory");
        }
        __syncthreads();

        uint32_t bb = sb + BUF0 + (c & 1) * BUFSZ;
        float d[2][8][4];
        #pragma unroll
        for (int mt = 0; mt < 2; mt++)
            #pragma unroll
            for (int nt = 0; nt < 8; nt++)
                #pragma unroll
                for (int j = 0; j < 4; j++) d[mt][nt][j] = 0.f;

        #pragma unroll
        for (int ks = 0; ks < 8; ks++) {
            uint32_t kb = ks * 32;
            uint32_t ah[2][4], al[2][4], bh[16], bl[16];
            #pragma unroll
            for (int mt = 0; mt < 2; mt++) {
                LDSM4(ah[mt][0], ah[mt][1], ah[mt][2], ah[mt][3], sb + A_H + aoff[mt] + kb);
                LDSM4(al[mt][0], al[mt][1], al[mt][2], al[mt][3], sb + A_L + aoff[mt] + kb);
            }
            #pragma unroll
            for (int bt = 0; bt < 4; bt++) {
                LDSM4(bh[bt*4], bh[bt*4+1], bh[bt*4+2], bh[bt*4+3], bb + boff[bt] + kb);
                LDSM4(bl[bt*4], bl[bt*4+1], bl[bt*4+2], bl[bt*4+3], bb + 34816 + boff[bt] + kb);
            }
            #pragma unroll
            for (int mt = 0; mt < 2; mt++)
                #pragma unroll
                for (int nt = 0; nt < 8; nt++) {
                    mma_bf16(d[mt][nt], ah[mt], &bh[nt * 2]);
                    mma_bf16(d[mt][nt], ah[mt], &bl[nt * 2]);
                    mma_bf16(d[mt][nt], al[mt], &bh[nt * 2]);
                }
        }

        // epilogue (overlaps next B load): bf16 output
        int z = c >> 1, nb = c & 1;
        bf16* Cb = z ? g_xr1b : g_xl1b;
        int colb = nb * 128;
        #pragma unroll
        for (int mt = 0; mt < 2; mt++) {
            int mrow = m0 + mwarp + mt * 16 + g4;
            #pragma unroll
            for (int nt = 0; nt < 8; nt++) {
                int col = colb + nwarp + nt * 8 + tig * 2;
                if (mrow < M) {
                    __nv_bfloat162 p = __float22bfloat162_rn(make_float2(d[mt][nt][0], d[mt][nt][1]));
                    *(uint32_t*)(Cb + (size_t)mrow * 256 + col) = *(uint32_t*)&p;
                }
                if (mrow + 8 < M) {
                    __nv_bfloat162 p = __float22bfloat162_rn(make_float2(d[mt][nt][2], d[mt][nt][3]));
                    *(uint32_t*)(Cb + (size_t)(mrow + 8) * 256 + col) = *(uint32_t*)&p;
                }
            }
        }
        __syncthreads();
    }
}

// ---------------- layer-2 GEMM: both z accumulated, K pipelined in 4x64 chunks ---
// C[m][n] = h (Mx256) @ W2 (256x64); outputs bf16 xl2b / xr2b
__global__ void __launch_bounds__(256) mma_gemm2(int M)
{
    constexpr int SA = 72;                 // 64 + 8 pad
    constexpr int ABYT = 18432;            // 128*72*2
    constexpr int BBYT = 9216;             // 64*72*2
    constexpr int BUFSZ = 73728;           // A(2*18432) + B(4*9216)
    constexpr int B_OFF = 36864;
    extern __shared__ char smem[];
    uint32_t sb = smem_u32(smem);
    int tid = threadIdx.x;
    int wid = tid >> 5, lane = tid & 31;
    int m0 = blockIdx.x * 128;

    // chunk loader: kc in 0..3 (k window kc*64), into buffer b
    auto load_chunk = [&](int kc, int b) {
        uint32_t base = sb + b * BUFSZ;
        for (int c = tid; c < 128 * 8; c += 256) {   // A: 128 rows x 8 16B-chunks
            int row = c >> 3, kcl = (c & 7) * 8;
            int rg = min(m0 + row, M - 1);
            uint32_t ta = (uint32_t)(row * SA + kcl) * 2;
            cp16(base + ta, g_hhi + (size_t)rg * 256 + kc * 64 + kcl);
            cp16(base + ABYT + ta, g_hlo + (size_t)rg * 256 + kc * 64 + kcl);
        }
        for (int c = tid; c < 2 * 64 * 8; c += 256) { // B: 2z x 64 rows x 8 chunks
            int z = c >> 9, r = c & 511;
            int n = r >> 3, kcl = (r & 7) * 8;
            int woff = z ? 81920 : 65536;
            uint32_t ta = (uint32_t)(n * SA + kcl) * 2;
            cp16(base + B_OFF + z * 2 * BBYT + ta, g_wthi + woff + (size_t)n * 256 + kc * 64 + kcl);
            cp16(base + B_OFF + z * 2 * BBYT + BBYT + ta, g_wtlo + woff + (size_t)n * 256 + kc * 64 + kcl);
        }
        CP_COMMIT();
    };

    load_chunk(0, 0);

    int mwarp = (wid & 3) * 32;
    int nwarp = (wid >> 2) * 32;   // 2 n-warps x WN=32
    int sel = lane >> 3, r8 = lane & 7;
    uint32_t aoff[2], boff[2];
    #pragma unroll
    for (int mt = 0; mt < 2; mt++)
        aoff[mt] = (uint32_t)(((mwarp + mt * 16 + (sel & 1) * 8 + r8) * SA + (sel >> 1) * 8) * 2);
    #pragma unroll
    for (int bt = 0; bt < 2; bt++)
        boff[bt] = (uint32_t)(((nwarp + bt * 16 + (sel >> 1) * 8 + r8) * SA + (sel & 1) * 8) * 2);

    float d[2][2][4][4];   // [z][mt][nt][4]
    #pragma unroll
    for (int z = 0; z < 2; z++)
        #pragma unroll
        for (int mt = 0; mt < 2; mt++)
            #pragma unroll
            for (int nt = 0; nt < 4; nt++)
                #pragma unroll
                for (int j = 0; j < 4; j++) d[z][mt][nt][j] = 0.f;

    for (int kc = 0; kc < 4; kc++) {
        if (kc < 3) {
            load_chunk(kc + 1, (kc + 1) & 1);
            asm volatile("cp.async.wait_group 1;" ::: "memory");
        } else {
            asm volatile("cp.async.wait_group 0;" ::: "memory");
        }
        __syncthreads();
        uint32_t base = sb + (kc & 1) * BUFSZ;

        #pragma unroll
        for (int ks = 0; ks < 4; ks++) {
            uint32_t kb = ks * 32;
            uint32_t ah[2][4], al[2][4], bh[2][8], bl[2][8];
            #pragma unroll
            for (int mt = 0; mt < 2; mt++) {
                LDSM4(ah[mt][0], ah[mt][1], ah[mt][2], ah[mt][3], base + aoff[mt] + kb);
                LDSM4(al[mt][0], al[mt][1], al[mt][2], al[mt][3], base + ABYT + aoff[mt] + kb);
            }
            #pragma unroll
            for (int z = 0; z < 2; z++) {
                uint32_t zb = base + B_OFF + z * 2 * BBYT;
                #pragma unroll
                for (int bt = 0; bt < 2; bt++) {
                    LDSM4(bh[z][bt*4], bh[z][bt*4+1], bh[z][bt*4+2], bh[z][bt*4+3], zb + boff[bt] + kb);
                    LDSM4(bl[z][bt*4], bl[z][bt*4+1], bl[z][bt*4+2], bl[z][bt*4+3], zb + BBYT + boff[bt] + kb);
                }
            }
            #pragma unroll
            for (int z = 0; z < 2; z++)
                #pragma unroll
                for (int mt = 0; mt < 2; mt++)
                    #pragma unroll
                    for (int nt = 0; nt < 4; nt++) {
                        mma_bf16(d[z][mt][nt], ah[mt], &bh[z][nt * 2]);
                        mma_bf16(d[z][mt][nt], ah[mt], &bl[z][nt * 2]);
                        mma_bf16(d[z][mt][nt], al[mt], &bh[z][nt * 2]);
                    }
        }
        __syncthreads();
    }

    int g4 = lane >> 2, tig = lane & 3;
    #pragma unroll
    for (int z = 0; z < 2; z++) {
        bf16* Cb = z ? g_xr2b : g_xl2b;
        #pragma unroll
        for (int mt = 0; mt < 2; mt++) {
            int mrow = m0 + mwarp + mt * 16 + g4;
            #pragma unroll
            for (int nt = 0; nt < 4; nt++) {
                int col = nwarp + nt * 8 + tig * 2;
                if (mrow < M) {
                    __nv_bfloat162 p = __float22bfloat162_rn(make_float2(d[z][mt][nt][0], d[z][mt][nt][1]));
                    *(uint32_t*)(Cb + (size_t)mrow * 64 + col) = *(uint32_t*)&p;
                }
                if (mrow + 8 < M) {
                    __nv_bfloat162 p = __float22bfloat162_rn(make_float2(d[z][mt][nt][2], d[z][mt][nt][3]));
                    *(uint32_t*)(Cb + (size_t)(mrow + 8) * 64 + col) = *(uint32_t*)&p;
                }
            }
        }
    }
}

// ---------------- layer 1 fused attention (H=4, C=64): one warp per dst node -----
__global__ void gat1_kernel(const float* __restrict__ att, const float* __restrict__ b1, int N)
{
    int d = (blockIdx.x * blockDim.x + threadIdx.x) >> 5;
    if (d >= N) return;
    int lane = threadIdx.x & 31;
    int off = lane * 8;

    uint4 xrr = *(const uint4*)(g_xr1b + (size_t)d * 256 + off);
    float2 xr0 = __bfloat1622float2(*(__nv_bfloat162*)&xrr.x);
    float2 xr1 = __bfloat1622float2(*(__nv_bfloat162*)&xrr.y);
    float2 xr2 = __bfloat1622float2(*(__nv_bfloat162*)&xrr.z);
    float2 xr3 = __bfloat1622float2(*(__nv_bfloat162*)&xrr.w);
    float4 aw0 = *(const float4*)(att + off);
    float4 aw1 = *(const float4*)(att + off + 4);

    float num[8];
    #pragma unroll
    for (int j = 0; j < 8; j++) num[j] = 0.f;
    float den = 0.f;

    int lo = g_rowptr[d], hi = g_rowptr[d + 1];
    int cnt = hi - lo + 1;   // + self loop
    uint4 b0, b1v;
    {
        int s0 = (lo < hi) ? g_csr_src[lo] : d;
        b0 = *(const uint4*)(g_xl1b + (size_t)s0 * 256 + off);
    }
    if (cnt > 1) {
        int s1 = (lo + 1 < hi) ? g_csr_src[lo + 1] : d;
        b1v = *(const uint4*)(g_xl1b + (size_t)s1 * 256 + off);
    }
    for (int i = 0; i < cnt; i++) {
        uint4 cur = (i & 1) ? b1v : b0;
        if (i + 2 < cnt) {
            int s2 = (lo + i + 2 < hi) ? g_csr_src[lo + i + 2] : d;
            uint4 nv = *(const uint4*)(g_xl1b + (size_t)s2 * 256 + off);
            if (i & 1) b1v = nv; else b0 = nv;
        }
        float2 f0 = __bfloat1622float2(*(__nv_bfloat162*)&cur.x);
        float2 f1 = __bfloat1622float2(*(__nv_bfloat162*)&cur.y);
        float2 f2 = __bfloat1622float2(*(__nv_bfloat162*)&cur.z);
        float2 f3 = __bfloat1622float2(*(__nv_bfloat162*)&cur.w);
        float p = lrelu(f0.x + xr0.x) * aw0.x + lrelu(f0.y + xr0.y) * aw0.y
                + lrelu(f1.x + xr1.x) * aw0.z + lrelu(f1.y + xr1.y) * aw0.w
                + lrelu(f2.x + xr2.x) * aw1.x + lrelu(f2.y + xr2.y) * aw1.y
                + lrelu(f3.x + xr3.x) * aw1.z + lrelu(f3.y + xr3.y) * aw1.w;
        p += __shfl_xor_sync(0xffffffffu, p, 1);
        p += __shfl_xor_sync(0xffffffffu, p, 2);
        p += __shfl_xor_sync(0xffffffffu, p, 4);
        float ex = __expf(p);
        den += ex;
        num[0] += ex * f0.x; num[1] += ex * f0.y; num[2] += ex * f1.x; num[3] += ex * f1.y;
        num[4] += ex * f2.x; num[5] += ex * f2.y; num[6] += ex * f3.x; num[7] += ex * f3.y;
    }
    float inv = 1.f / (den + 1e-16f);
    float4 bb0 = *(const float4*)(b1 + off);
    float4 bb1 = *(const float4*)(b1 + off + 4);
    float bias[8] = {bb0.x, bb0.y, bb0.z, bb0.w, bb1.x, bb1.y, bb1.z, bb1.w};
    bf16 hi8[8], lo8[8];
    #pragma unroll
    for (int j = 0; j < 8; j++) {
        float v = fmaxf(num[j] * inv + bias[j], 0.f);
        bf16 h = __float2bfloat16(v);
        hi8[j] = h;
        lo8[j] = __float2bfloat16(v - __bfloat162float(h));
    }
    *(uint4*)(g_hhi + (size_t)d * 256 + off) = *(uint4*)hi8;
    *(uint4*)(g_hlo + (size_t)d * 256 + off) = *(uint4*)lo8;
}

// ---------------- layer 2 fused attention + pooling: one warp per dst node -------
__global__ void gat2_kernel(const float* __restrict__ att, const int* __restrict__ batch,
                            const float* __restrict__ b2, const float* __restrict__ Wo, int N)
{
    int d = (blockIdx.x * blockDim.x + threadIdx.x) >> 5;
    if (d >= N) return;
    int lane = threadIdx.x & 31;
    int off = lane * 2;

    uint32_t xrr = *(const uint32_t*)(g_xr2b + (size_t)d * 64 + off);
    float2 xr = __bfloat1622float2(*(__nv_bfloat162*)&xrr);
    float2 aw = *(const float2*)(att + off);

    float num0 = 0.f, num1 = 0.f, den = 0.f;
    int lo = g_rowptr[d], hi = g_rowptr[d + 1];
    int cnt = hi - lo + 1;
    uint32_t b0, b1v = 0;
    {
        int s0 = (lo < hi) ? g_csr_src[lo] : d;
        b0 = *(const uint32_t*)(g_xl2b + (size_t)s0 * 64 + off);
    }
    if (cnt > 1) {
        int s1 = (lo + 1 < hi) ? g_csr_src[lo + 1] : d;
        b1v = *(const uint32_t*)(g_xl2b + (size_t)s1 * 64 + off);
    }
    for (int i = 0; i < cnt; i++) {
        uint32_t cur = (i & 1) ? b1v : b0;
        if (i + 2 < cnt) {
            int s2 = (lo + i + 2 < hi) ? g_csr_src[lo + i + 2] : d;
            uint32_t nv = *(const uint32_t*)(g_xl2b + (size_t)s2 * 64 + off);
            if (i & 1) b1v = nv; else b0 = nv;
        }
        float2 xv = __bfloat1622float2(*(__nv_bfloat162*)&cur);
        float p = lrelu(xv.x + xr.x) * aw.x + lrelu(xv.y + xr.y) * aw.y;
        p += __shfl_xor_sync(0xffffffffu, p, 1);
        p += __shfl_xor_sync(0xffffffffu, p, 2);
        p += __shfl_xor_sync(0xffffffffu, p, 4);
        p += __shfl_xor_sync(0xffffffffu, p, 8);
        p += __shfl_xor_sync(0xffffffffu, p, 16);
        float ex = __expf(p);
        den += ex;
        num0 += ex * xv.x;
        num1 += ex * xv.y;
    }
    float inv = 1.f / (den + 1e-16f);
    float2 bb = *(const float2*)(b2 + off);
    float2 wo = *(const float2*)(Wo + off);
    float y = (num0 * inv + bb.x) * wo.x + (num1 * inv + bb.y) * wo.y;
    y += __shfl_xor_sync(0xffffffffu, y, 1);
    y += __shfl_xor_sync(0xffffffffu, y, 2);
    y += __shfl_xor_sync(0xffffffffu, y, 4);
    y += __shfl_xor_sync(0xffffffffu, y, 8);
    y += __shfl_xor_sync(0xffffffffu, y, 16);
    if (lane == 0) atomicAdd(&g_acc[batch[d]], y);
}

__global__ void final_kernel(float* __restrict__ out, int G, const float* __restrict__ bo)
{
    int g = threadIdx.x;
    if (g < G) out[g] = g_acc[g] / fmaxf(g_cnt[g], 1.f) + bo[0];
}

// ---------------- launch ----------------
extern "C" void kernel_launch(void* const* d_in, const int* in_sizes, int n_in,
                              void* d_out, int out_size)
{
    const float* x    = (const float*)d_in[0];
    const int* ei     = (const int*)d_in[1];
    const int* bat    = (const int*)d_in[2];
    const float* Wl1 = (const float*)d_in[3];
    const float* Wr1 = (const float*)d_in[4];
    const float* att1 = (const float*)d_in[5];
    const float* b1  = (const float*)d_in[6];
    const float* Wl2 = (const float*)d_in[7];
    const float* Wr2 = (const float*)d_in[8];
    const float* att2 = (const float*)d_in[9];
    const float* b2  = (const float*)d_in[10];
    const float* Wo  = (const float*)d_in[11];
    const float* bo  = (const float*)d_in[12];

    int N = in_sizes[0] / 128;
    int E = in_sizes[1] / 2;
    int G = out_size;
    const int* src = ei;
    const int* dst = ei + E;
    int tiles = (N + 127) / 128;
    int nb = (N + 255) / 256;

    const int SM1 = 69632 + 2 * 69632;   // A + 2 B bufs = 208896
    const int SM2 = 2 * 73728;           // 2 pipelined chunks = 147456
    cudaFuncSetAttribute(mma_gemm1, cudaFuncAttributeMaxDynamicSharedMemorySize, SM1);
    cudaFuncSetAttribute(mma_gemm2, cudaFuncAttributeMaxDynamicSharedMemorySize, SM2);

    init0<<<(N + 255) / 256, 256>>>(N);
    prep_kernel<<<(N * 128 + 255) / 256, 256>>>(x, dst, bat, N, E);
    split_wt_all<<<(98304 + 255) / 256, 256>>>(Wl1, Wr1, Wl2, Wr2);

    blocksum_kernel<<<nb, 256>>>(N);
    scanb_kernel<<<1, 256>>>(nb);
    rowptr_kernel<<<nb, 256>>>(N, E);
    scatter_kernel<<<(E + 255) / 256, 256>>>(src, dst, E);

    mma_gemm1<<<tiles, 256, SM1>>>(N);
    gat1_kernel<<<(N * 32 + 255) / 256, 256>>>(att1, b1, N);

    mma_gemm2<<<tiles, 256, SM2>>>(N);
    gat2_kernel<<<(N * 32 + 255) / 256, 256>>>(att2, bat, b2, Wo, N);

    final_kernel<<<1, 64>>>((float*)d_out, G, bo);
}

// round 11
// speedup vs baseline: 3.6375x; 1.0636x over previous
#include <cuda_runtime.h>
#include <cuda_bf16.h>
#include <cstdint>

#define MAXN 50000
#define MAXE 800000
typedef __nv_bfloat16 bf16;

// ---------------- scratch (device globals; no allocation allowed) ----------------
__device__ __align__(16) bf16 g_xl1b[(size_t)MAXN * 256];
__device__ __align__(16) bf16 g_xr1b[(size_t)MAXN * 256];
__device__ __align__(16) bf16 g_xl2b[(size_t)MAXN * 64];
__device__ __align__(16) bf16 g_xr2b[(size_t)MAXN * 64];
__device__ __align__(16) bf16 g_xb[(size_t)MAXN * 128];   // x as plain bf16
__device__ __align__(16) bf16 g_hb[(size_t)MAXN * 256];   // h as plain bf16
// weight transposes [n][k], SPLIT bf16 (systematic error must stay small):
// w1l@0 (256x128), w1r@32768, w2l@65536 (64x256), w2r@81920
__device__ __align__(16) bf16 g_wthi[98304];
__device__ __align__(16) bf16 g_wtlo[98304];
__device__ int g_deg[MAXN];
__device__ int g_rowptr[MAXN + 1];
__device__ int g_woff[MAXN];
__device__ int g_csr_src[MAXE];
__device__ int g_bsum[256];
__device__ float g_acc[64];
__device__ float g_cnt[64];

__device__ __forceinline__ float lrelu(float v) { return v > 0.f ? v : 0.2f * v; }

__device__ __forceinline__ uint32_t smem_u32(const void* p) {
    uint32_t a;
    asm("{ .reg .u64 t; cvta.to.shared.u64 t, %1; cvt.u32.u64 %0, t; }" : "=r"(a) : "l"(p));
    return a;
}
__device__ __forceinline__ void cp16(uint32_t s, const void* g) {
    asm volatile("cp.async.cg.shared.global [%0], [%1], 16;" :: "r"(s), "l"(g));
}
#define CP_COMMIT() asm volatile("cp.async.commit_group;" ::: "memory")
#define LDSM4(r0, r1, r2, r3, addr) \
    asm volatile("ldmatrix.sync.aligned.m8n8.x4.shared.b16 {%0,%1,%2,%3}, [%4];" \
                 : "=r"(r0), "=r"(r1), "=r"(r2), "=r"(r3) : "r"(addr))

__device__ __forceinline__ void mma_bf16(float* d, const uint32_t* a, const uint32_t* b) {
    asm volatile("mma.sync.aligned.m16n8k16.row.col.f32.bf16.bf16.f32 "
                 "{%0,%1,%2,%3}, {%4,%5,%6,%7}, {%8,%9}, {%0,%1,%2,%3};"
                 : "+f"(d[0]), "+f"(d[1]), "+f"(d[2]), "+f"(d[3])
                 : "r"(a[0]), "r"(a[1]), "r"(a[2]), "r"(a[3]), "r"(b[0]), "r"(b[1]));
}

// ---------------- init ----------------
__global__ void init0(int N) {
    int i = blockIdx.x * blockDim.x + threadIdx.x;
    if (i < N) g_deg[i] = 0;
    if (i < 64) { g_acc[i] = 0.f; g_cnt[i] = 0.f; }
}

// ---------------- prep: x -> bf16 + degree histogram + graph counts --------------
__global__ void prep_kernel(const float* __restrict__ x, const int* __restrict__ dst,
                            const int* __restrict__ batch, int N, int E) {
    int i = blockIdx.x * blockDim.x + threadIdx.x;
    if (i < N * 128) g_xb[i] = __float2bfloat16(x[i]);
    if (i < E) atomicAdd(&g_deg[dst[i]], 1);
    if (i < N) atomicAdd(&g_cnt[batch[i]], 1.f);
}

// weight transposes, SPLIT bf16 hi/lo
__global__ void split_wt_all(const float* __restrict__ Wl1, const float* __restrict__ Wr1,
                             const float* __restrict__ Wl2, const float* __restrict__ Wr2) {
    int i = blockIdx.x * blockDim.x + threadIdx.x;
    if (i >= 98304) return;
    const float* W;
    int K, Nout, off, j;
    if (i < 32768)      { W = Wl1; K = 128; Nout = 256; off = 0;     j = i; }
    else if (i < 65536) { W = Wr1; K = 128; Nout = 256; off = 32768; j = i - 32768; }
    else if (i < 81920) { W = Wl2; K = 256; Nout = 64;  off = 65536; j = i - 65536; }
    else                { W = Wr2; K = 256; Nout = 64;  off = 81920; j = i - 81920; }
    int k = j / Nout, n = j % Nout;
    float v = W[j];
    bf16 h = __float2bfloat16(v);
    g_wthi[off + n * K + k] = h;
    g_wtlo[off + n * K + k] = __float2bfloat16(v - __bfloat162float(h));
}

// ---------------- layer-1 GEMM: A bf16 resident, W split, 4 B-chunks dbl-buffered
// C[m][z*256 + n]: x (Mx128) @ W (128x256); outputs bf16 xl1b / xr1b
__global__ void __launch_bounds__(256) mma_gemm1(int M)
{
    constexpr int SA = 136;
    constexpr int A_OFF = 0;                   // 128*136*2 = 34816
    constexpr int BUF0 = 34816, BUFSZ = 69632; // per buf: B_H +0, B_L +34816
    extern __shared__ char smem[];
    uint32_t sb = smem_u32(smem);
    int tid = threadIdx.x;
    int wid = tid >> 5, lane = tid & 31;
    int m0 = blockIdx.x * 128;

    // A load (once): 128 rows x 128 k, plain bf16
    for (int c = tid; c < 128 * 16; c += 256) {
        int row = c >> 4, kcl = (c & 15) * 8;
        int rg = min(m0 + row, M - 1);
        cp16(sb + A_OFF + (uint32_t)(row * SA + kcl) * 2, g_xb + (size_t)rg * 128 + kcl);
    }
    // B chunk 0 (z=0, nb=0): hi + lo
    for (int c = tid; c < 128 * 16; c += 256) {
        int n = c >> 4, kcl = (c & 15) * 8;
        uint32_t ta = (uint32_t)(n * SA + kcl) * 2;
        cp16(sb + BUF0 + ta, g_wthi + (size_t)n * 128 + kcl);
        cp16(sb + BUF0 + 34816 + ta, g_wtlo + (size_t)n * 128 + kcl);
    }
    CP_COMMIT();

    int mwarp = (wid & 3) * 32;
    int nwarp = (wid >> 2) * 64;
    int sel = lane >> 3, r8 = lane & 7;
    uint32_t aoff[2], boff[4];
    #pragma unroll
    for (int mt = 0; mt < 2; mt++)
        aoff[mt] = (uint32_t)(((mwarp + mt * 16 + (sel & 1) * 8 + r8) * SA + (sel >> 1) * 8) * 2);
    #pragma unroll
    for (int bt = 0; bt < 4; bt++)
        boff[bt] = (uint32_t)(((nwarp + bt * 16 + (sel >> 1) * 8 + r8) * SA + (sel & 1) * 8) * 2);

    int g4 = lane >> 2, tig = lane & 3;

    for (int c = 0; c < 4; c++) {
        if (c < 3) {   // prefetch next B chunk (hi+lo)
            int z = (c + 1) >> 1, nb = (c + 1) & 1;
            const bf16* WH = g_wthi + (z ? 32768 : 0) + (size_t)nb * 128 * 128;
            const bf16* WL = g_wtlo + (z ? 32768 : 0) + (size_t)nb * 128 * 128;
            uint32_t bbase = sb + BUF0 + ((c + 1) & 1) * BUFSZ;
            for (int t = tid; t < 128 * 16; t += 256) {
                int n = t >> 4, kcl = (t & 15) * 8;
                uint32_t ta = (uint32_t)(n * SA + kcl) * 2;
                cp16(bbase + ta, WH + (size_t)n * 128 + kcl);
                cp16(bbase + 34816 + ta, WL + (size_t)n * 128 + kcl);
            }
            CP_COMMIT();
            asm volatile("cp.async.wait_group 1;" ::: "memory");
        } else {
            asm volatile("cp.async.wait_group 0;" ::: "memory");
        }
        __syncthreads();

        uint32_t bb = sb + BUF0 + (c & 1) * BUFSZ;
        float d[2][8][4];
        #pragma unroll
        for (int mt = 0; mt < 2; mt++)
            #pragma unroll
            for (int nt = 0; nt < 8; nt++)
                #pragma unroll
                for (int j = 0; j < 4; j++) d[mt][nt][j] = 0.f;

        #pragma unroll
        for (int ks = 0; ks < 8; ks++) {
            uint32_t kb = ks * 32;
            uint32_t ah[2][4], bh[16], bl[16];
            #pragma unroll
            for (int mt = 0; mt < 2; mt++)
                LDSM4(ah[mt][0], ah[mt][1], ah[mt][2], ah[mt][3], sb + A_OFF + aoff[mt] + kb);
            #pragma unroll
            for (int bt = 0; bt < 4; bt++) {
                LDSM4(bh[bt*4], bh[bt*4+1], bh[bt*4+2], bh[bt*4+3], bb + boff[bt] + kb);
                LDSM4(bl[bt*4], bl[bt*4+1], bl[bt*4+2], bl[bt*4+3], bb + 34816 + boff[bt] + kb);
            }
            #pragma unroll
            for (int mt = 0; mt < 2; mt++)
                #pragma unroll
                for (int nt = 0; nt < 8; nt++) {
                    mma_bf16(d[mt][nt], ah[mt], &bh[nt * 2]);   // a * W_hi
                    mma_bf16(d[mt][nt], ah[mt], &bl[nt * 2]);   // a * W_lo
                }
        }

        // epilogue (overlaps next B load): bf16 output
        int z = c >> 1, nb = c & 1;
        bf16* Cb = z ? g_xr1b : g_xl1b;
        int colb = nb * 128;
        #pragma unroll
        for (int mt = 0; mt < 2; mt++) {
            int mrow = m0 + mwarp + mt * 16 + g4;
            #pragma unroll
            for (int nt = 0; nt < 8; nt++) {
                int col = colb + nwarp + nt * 8 + tig * 2;
                if (mrow < M) {
                    __nv_bfloat162 p = __float22bfloat162_rn(make_float2(d[mt][nt][0], d[mt][nt][1]));
                    *(uint32_t*)(Cb + (size_t)mrow * 256 + col) = *(uint32_t*)&p;
                }
                if (mrow + 8 < M) {
                    __nv_bfloat162 p = __float22bfloat162_rn(make_float2(d[mt][nt][2], d[mt][nt][3]));
                    *(uint32_t*)(Cb + (size_t)(mrow + 8) * 256 + col) = *(uint32_t*)&p;
                }
            }
        }
        __syncthreads();
    }
}

// ---------------- CSR build: coalesced 3-stage scan ----------------
__global__ void blocksum_kernel(int N) {
    __shared__ int sh[256];
    int tid = threadIdx.x;
    int i = blockIdx.x * 256 + tid;
    sh[tid] = (i < N) ? g_deg[i] : 0;
    __syncthreads();
    for (int s = 128; s > 0; s >>= 1) {
        if (tid < s) sh[tid] += sh[tid + s];
        __syncthreads();
    }
    if (tid == 0) g_bsum[blockIdx.x] = sh[0];
}
__global__ void scanb_kernel(int nb) {
    __shared__ int sh[256];
    int tid = threadIdx.x;
    int v = (tid < nb) ? g_bsum[tid] : 0;
    sh[tid] = v;
    __syncthreads();
    for (int s = 1; s < 256; s <<= 1) {
        int t = (tid >= s) ? sh[tid - s] : 0;
        __syncthreads();
        sh[tid] += t;
        __syncthreads();
    }
    if (tid < nb) g_bsum[tid] = sh[tid] - v;
}
__global__ void rowptr_kernel(int N, int E) {
    __shared__ int sh[256];
    int tid = threadIdx.x;
    int i = blockIdx.x * 256 + tid;
    int v = (i < N) ? g_deg[i] : 0;
    sh[tid] = v;
    __syncthreads();
    for (int s = 1; s < 256; s <<= 1) {
        int t = (tid >= s) ? sh[tid - s] : 0;
        __syncthreads();
        sh[tid] += t;
        __syncthreads();
    }
    if (i < N) {
        int ex = g_bsum[blockIdx.x] + sh[tid] - v;
        g_rowptr[i] = ex;
        g_woff[i] = ex;
        if (i == N - 1) g_rowptr[N] = E;
    }
}
__global__ void scatter_kernel(const int* __restrict__ src, const int* __restrict__ dst, int E) {
    int e = blockIdx.x * blockDim.x + threadIdx.x;
    if (e >= E) return;
    int pos = atomicAdd(&g_woff[dst[e]], 1);
    g_csr_src[pos] = src[e];
}

// ---------------- layer-2 GEMM: both z accumulated, K pipelined in 4x64 chunks ---
// C[m][n] = h (Mx256) @ W2 (256x64); W split; outputs bf16 xl2b / xr2b
__global__ void __launch_bounds__(256) mma_gemm2(int M)
{
    constexpr int SA = 72;                 // 64 + 8 pad
    constexpr int ABYT = 18432;            // 128*72*2 (A plain bf16)
    constexpr int BBYT = 9216;             // 64*72*2
    constexpr int B_OFF = 18432;           // B: z0_hi, z0_lo, z1_hi, z1_lo
    constexpr int BUFSZ = 55296;           // 18432 + 4*9216
    extern __shared__ char smem[];
    uint32_t sb = smem_u32(smem);
    int tid = threadIdx.x;
    int wid = tid >> 5, lane = tid & 31;
    int m0 = blockIdx.x * 128;

    auto load_chunk = [&](int kc, int b) {
        uint32_t base = sb + b * BUFSZ;
        for (int c = tid; c < 128 * 8; c += 256) {   // A: 128 rows x 8 16B-chunks
            int row = c >> 3, kcl = (c & 7) * 8;
            int rg = min(m0 + row, M - 1);
            cp16(base + (uint32_t)(row * SA + kcl) * 2, g_hb + (size_t)rg * 256 + kc * 64 + kcl);
        }
        for (int c = tid; c < 2 * 64 * 8; c += 256) { // B hi+lo: 2z x 64 rows x 8 chunks
            int z = c >> 9, r = c & 511;
            int n = r >> 3, kcl = (r & 7) * 8;
            int woff = z ? 81920 : 65536;
            uint32_t ta = (uint32_t)(n * SA + kcl) * 2;
            cp16(base + B_OFF + z * 2 * BBYT + ta, g_wthi + woff + (size_t)n * 256 + kc * 64 + kcl);
            cp16(base + B_OFF + z * 2 * BBYT + BBYT + ta, g_wtlo + woff + (size_t)n * 256 + kc * 64 + kcl);
        }
        CP_COMMIT();
    };

    load_chunk(0, 0);

    int mwarp = (wid & 3) * 32;
    int nwarp = (wid >> 2) * 32;
    int sel = lane >> 3, r8 = lane & 7;
    uint32_t aoff[2], boff[2];
    #pragma unroll
    for (int mt = 0; mt < 2; mt++)
        aoff[mt] = (uint32_t)(((mwarp + mt * 16 + (sel & 1) * 8 + r8) * SA + (sel >> 1) * 8) * 2);
    #pragma unroll
    for (int bt = 0; bt < 2; bt++)
        boff[bt] = (uint32_t)(((nwarp + bt * 16 + (sel >> 1) * 8 + r8) * SA + (sel & 1) * 8) * 2);

    float d[2][2][4][4];
    #pragma unroll
    for (int z = 0; z < 2; z++)
        #pragma unroll
        for (int mt = 0; mt < 2; mt++)
            #pragma unroll
            for (int nt = 0; nt < 4; nt++)
                #pragma unroll
                for (int j = 0; j < 4; j++) d[z][mt][nt][j] = 0.f;

    for (int kc = 0; kc < 4; kc++) {
        if (kc < 3) {
            load_chunk(kc + 1, (kc + 1) & 1);
            asm volatile("cp.async.wait_group 1;" ::: "memory");
        } else {
            asm volatile("cp.async.wait_group 0;" ::: "memory");
        }
        __syncthreads();
        uint32_t base = sb + (kc & 1) * BUFSZ;

        #pragma unroll
        for (int ks = 0; ks < 4; ks++) {
            uint32_t kb = ks * 32;
            uint32_t ah[2][4], bh[2][8], bl[2][8];
            #pragma unroll
            for (int mt = 0; mt < 2; mt++)
                LDSM4(ah[mt][0], ah[mt][1], ah[mt][2], ah[mt][3], base + aoff[mt] + kb);
            #pragma unroll
            for (int z = 0; z < 2; z++) {
                uint32_t zb = base + B_OFF + z * 2 * BBYT;
                #pragma unroll
                for (int bt = 0; bt < 2; bt++) {
                    LDSM4(bh[z][bt*4], bh[z][bt*4+1], bh[z][bt*4+2], bh[z][bt*4+3], zb + boff[bt] + kb);
                    LDSM4(bl[z][bt*4], bl[z][bt*4+1], bl[z][bt*4+2], bl[z][bt*4+3], zb + BBYT + boff[bt] + kb);
                }
            }
            #pragma unroll
            for (int z = 0; z < 2; z++)
                #pragma unroll
                for (int mt = 0; mt < 2; mt++)
                    #pragma unroll
                    for (int nt = 0; nt < 4; nt++) {
                        mma_bf16(d[z][mt][nt], ah[mt], &bh[z][nt * 2]);
                        mma_bf16(d[z][mt][nt], ah[mt], &bl[z][nt * 2]);
                    }
        }
        __syncthreads();
    }

    int g4 = lane >> 2, tig = lane & 3;
    #pragma unroll
    for (int z = 0; z < 2; z++) {
        bf16* Cb = z ? g_xr2b : g_xl2b;
        #pragma unroll
        for (int mt = 0; mt < 2; mt++) {
            int mrow = m0 + mwarp + mt * 16 + g4;
            #pragma unroll
            for (int nt = 0; nt < 4; nt++) {
                int col = nwarp + nt * 8 + tig * 2;
                if (mrow < M) {
                    __nv_bfloat162 p = __float22bfloat162_rn(make_float2(d[z][mt][nt][0], d[z][mt][nt][1]));
                    *(uint32_t*)(Cb + (size_t)mrow * 64 + col) = *(uint32_t*)&p;
                }
                if (mrow + 8 < M) {
                    __nv_bfloat162 p = __float22bfloat162_rn(make_float2(d[z][mt][nt][2], d[z][mt][nt][3]));
                    *(uint32_t*)(Cb + (size_t)(mrow + 8) * 64 + col) = *(uint32_t*)&p;
                }
            }
        }
    }
}

// ---------------- layer 1 fused attention (H=4, C=64): one warp per dst node -----
__global__ void gat1_kernel(const float* __restrict__ att, const float* __restrict__ b1, int N)
{
    int d = (blockIdx.x * blockDim.x + threadIdx.x) >> 5;
    if (d >= N) return;
    int lane = threadIdx.x & 31;
    int off = lane * 8;

    uint4 xrr = *(const uint4*)(g_xr1b + (size_t)d * 256 + off);
    float2 xr0 = __bfloat1622float2(*(__nv_bfloat162*)&xrr.x);
    float2 xr1 = __bfloat1622float2(*(__nv_bfloat162*)&xrr.y);
    float2 xr2 = __bfloat1622float2(*(__nv_bfloat162*)&xrr.z);
    float2 xr3 = __bfloat1622float2(*(__nv_bfloat162*)&xrr.w);
    float4 aw0 = *(const float4*)(att + off);
    float4 aw1 = *(const float4*)(att + off + 4);

    float num[8];
    #pragma unroll
    for (int j = 0; j < 8; j++) num[j] = 0.f;
    float den = 0.f;

    int lo = g_rowptr[d], hi = g_rowptr[d + 1];
    int cnt = hi - lo + 1;   // + self loop
    uint4 b0, b1v;
    {
        int s0 = (lo < hi) ? g_csr_src[lo] : d;
        b0 = *(const uint4*)(g_xl1b + (size_t)s0 * 256 + off);
    }
    if (cnt > 1) {
        int s1 = (lo + 1 < hi) ? g_csr_src[lo + 1] : d;
        b1v = *(const uint4*)(g_xl1b + (size_t)s1 * 256 + off);
    }
    for (int i = 0; i < cnt; i++) {
        uint4 cur = (i & 1) ? b1v : b0;
        if (i + 2 < cnt) {
            int s2 = (lo + i + 2 < hi) ? g_csr_src[lo + i + 2] : d;
            uint4 nv = *(const uint4*)(g_xl1b + (size_t)s2 * 256 + off);
            if (i & 1) b1v = nv; else b0 = nv;
        }
        float2 f0 = __bfloat1622float2(*(__nv_bfloat162*)&cur.x);
        float2 f1 = __bfloat1622float2(*(__nv_bfloat162*)&cur.y);
        float2 f2 = __bfloat1622float2(*(__nv_bfloat162*)&cur.z);
        float2 f3 = __bfloat1622float2(*(__nv_bfloat162*)&cur.w);
        float p = lrelu(f0.x + xr0.x) * aw0.x + lrelu(f0.y + xr0.y) * aw0.y
                + lrelu(f1.x + xr1.x) * aw0.z + lrelu(f1.y + xr1.y) * aw0.w
                + lrelu(f2.x + xr2.x) * aw1.x + lrelu(f2.y + xr2.y) * aw1.y
                + lrelu(f3.x + xr3.x) * aw1.z + lrelu(f3.y + xr3.y) * aw1.w;
        p += __shfl_xor_sync(0xffffffffu, p, 1);
        p += __shfl_xor_sync(0xffffffffu, p, 2);
        p += __shfl_xor_sync(0xffffffffu, p, 4);
        float ex = __expf(p);
        den += ex;
        num[0] += ex * f0.x; num[1] += ex * f0.y; num[2] += ex * f1.x; num[3] += ex * f1.y;
        num[4] += ex * f2.x; num[5] += ex * f2.y; num[6] += ex * f3.x; num[7] += ex * f3.y;
    }
    float inv = 1.f / (den + 1e-16f);
    float4 bb0 = *(const float4*)(b1 + off);
    float4 bb1 = *(const float4*)(b1 + off + 4);
    float bias[8] = {bb0.x, bb0.y, bb0.z, bb0.w, bb1.x, bb1.y, bb1.z, bb1.w};
    bf16 h8[8];
    #pragma unroll
    for (int j = 0; j < 8; j++)
        h8[j] = __float2bfloat16(fmaxf(num[j] * inv + bias[j], 0.f));
    *(uint4*)(g_hb + (size_t)d * 256 + off) = *(uint4*)h8;
}

// ---------------- layer 2 fused attention + pooling: one warp per dst node -------
__global__ void gat2_kernel(const float* __restrict__ att, const int* __restrict__ batch,
                            const float* __restrict__ b2, const float* __restrict__ Wo, int N)
{
    int d = (blockIdx.x * blockDim.x + threadIdx.x) >> 5;
    if (d >= N) return;
    int lane = threadIdx.x & 31;
    int off = lane * 2;

    uint32_t xrr = *(const uint32_t*)(g_xr2b + (size_t)d * 64 + off);
    float2 xr = __bfloat1622float2(*(__nv_bfloat162*)&xrr);
    float2 aw = *(const float2*)(att + off);

    float num0 = 0.f, num1 = 0.f, den = 0.f;
    int lo = g_rowptr[d], hi = g_rowptr[d + 1];
    int cnt = hi - lo + 1;
    uint32_t b0, b1v = 0;
    {
        int s0 = (lo < hi) ? g_csr_src[lo] : d;
        b0 = *(const uint32_t*)(g_xl2b + (size_t)s0 * 64 + off);
    }
    if (cnt > 1) {
        int s1 = (lo + 1 < hi) ? g_csr_src[lo + 1] : d;
        b1v = *(const uint32_t*)(g_xl2b + (size_t)s1 * 64 + off);
    }
    for (int i = 0; i < cnt; i++) {
        uint32_t cur = (i & 1) ? b1v : b0;
        if (i + 2 < cnt) {
            int s2 = (lo + i + 2 < hi) ? g_csr_src[lo + i + 2] : d;
            uint32_t nv = *(const uint32_t*)(g_xl2b + (size_t)s2 * 64 + off);
            if (i & 1) b1v = nv; else b0 = nv;
        }
        float2 xv = __bfloat1622float2(*(__nv_bfloat162*)&cur);
        float p = lrelu(xv.x + xr.x) * aw.x + lrelu(xv.y + xr.y) * aw.y;
        p += __shfl_xor_sync(0xffffffffu, p, 1);
        p += __shfl_xor_sync(0xffffffffu, p, 2);
        p += __shfl_xor_sync(0xffffffffu, p, 4);
        p += __shfl_xor_sync(0xffffffffu, p, 8);
        p += __shfl_xor_sync(0xffffffffu, p, 16);
        float ex = __expf(p);
        den += ex;
        num0 += ex * xv.x;
        num1 += ex * xv.y;
    }
    float inv = 1.f / (den + 1e-16f);
    float2 bb = *(const float2*)(b2 + off);
    float2 wo = *(const float2*)(Wo + off);
    float y = (num0 * inv + bb.x) * wo.x + (num1 * inv + bb.y) * wo.y;
    y += __shfl_xor_sync(0xffffffffu, y, 1);
    y += __shfl_xor_sync(0xffffffffu, y, 2);
    y += __shfl_xor_sync(0xffffffffu, y, 4);
    y += __shfl_xor_sync(0xffffffffu, y, 8);
    y += __shfl_xor_sync(0xffffffffu, y, 16);
    if (lane == 0) atomicAdd(&g_acc[batch[d]], y);
}

__global__ void final_kernel(float* __restrict__ out, int G, const float* __restrict__ bo)
{
    int g = threadIdx.x;
    if (g < G) out[g] = g_acc[g] / fmaxf(g_cnt[g], 1.f) + bo[0];
}

// ---------------- launch ----------------
extern "C" void kernel_launch(void* const* d_in, const int* in_sizes, int n_in,
                              void* d_out, int out_size)
{
    const float* x    = (const float*)d_in[0];
    const int* ei     = (const int*)d_in[1];
    const int* bat    = (const int*)d_in[2];
    const float* Wl1 = (const float*)d_in[3];
    const float* Wr1 = (const float*)d_in[4];
    const float* att1 = (const float*)d_in[5];
    const float* b1  = (const float*)d_in[6];
    const float* Wl2 = (const float*)d_in[7];
    const float* Wr2 = (const float*)d_in[8];
    const float* att2 = (const float*)d_in[9];
    const float* b2  = (const float*)d_in[10];
    const float* Wo  = (const float*)d_in[11];
    const float* bo  = (const float*)d_in[12];

    int N = in_sizes[0] / 128;
    int E = in_sizes[1] / 2;
    int G = out_size;
    const int* src = ei;
    const int* dst = ei + E;
    int tiles = (N + 127) / 128;
    int nb = (N + 255) / 256;

    const int SM1 = 34816 + 2 * 69632;   // A + 2 B(hi+lo) bufs = 174080
    const int SM2 = 2 * 55296;           // 110592 -> 2 CTAs/SM
    cudaFuncSetAttribute(mma_gemm1, cudaFuncAttributeMaxDynamicSharedMemorySize, SM1);
    cudaFuncSetAttribute(mma_gemm2, cudaFuncAttributeMaxDynamicSharedMemorySize, SM2);

    init0<<<(N + 255) / 256, 256>>>(N);                             // 1
    prep_kernel<<<(N * 128 + 255) / 256, 256>>>(x, dst, bat, N, E); // 2
    split_wt_all<<<(98304 + 255) / 256, 256>>>(Wl1, Wr1, Wl2, Wr2); // 3
    mma_gemm1<<<tiles, 256, SM1>>>(N);                              // 4 <- profiled slot

    blocksum_kernel<<<nb, 256>>>(N);                                // 5
    scanb_kernel<<<1, 256>>>(nb);                                   // 6
    rowptr_kernel<<<nb, 256>>>(N, E);                               // 7
    scatter_kernel<<<(E + 255) / 256, 256>>>(src, dst, E);          // 8

    gat1_kernel<<<(N * 32 + 255) / 256, 256>>>(att1, b1, N);        // 9
    mma_gemm2<<<tiles, 256, SM2>>>(N);                              // 10
    gat2_kernel<<<(N * 32 + 255) / 256, 256>>>(att2, bat, b2, Wo, N); // 11
    final_kernel<<<1, 64>>>((float*)d_out, G, bo);                  // 12
}

// round 12
// speedup vs baseline: 3.6794x; 1.0115x over previous
#include <cuda_runtime.h>
#include <cuda_bf16.h>
#include <cstdint>

#define MAXN 50000
#define MAXE 800000
typedef __nv_bfloat16 bf16;

// ---------------- scratch (device globals; no allocation allowed) ----------------
__device__ __align__(16) bf16 g_xl1b[(size_t)MAXN * 256];
__device__ __align__(16) bf16 g_xr1b[(size_t)MAXN * 256];
__device__ __align__(16) bf16 g_xl2b[(size_t)MAXN * 64];
__device__ __align__(16) bf16 g_xr2b[(size_t)MAXN * 64];
__device__ __align__(16) bf16 g_xb[(size_t)MAXN * 128];   // x as plain bf16
__device__ __align__(16) bf16 g_hb[(size_t)MAXN * 256];   // h as plain bf16
// weight transposes [n][k], SPLIT bf16: w1l@0 (256x128), w1r@32768, w2l@65536 (64x256), w2r@81920
__device__ __align__(16) bf16 g_wthi[98304];
__device__ __align__(16) bf16 g_wtlo[98304];
__device__ int g_deg[MAXN];
__device__ int g_rowptr[MAXN + 1];
__device__ int g_woff[MAXN];
__device__ int g_csr_src[MAXE];
__device__ int g_bsum[256];
__device__ float g_acc[64];
__device__ float g_cnt[64];

__device__ __forceinline__ float lrelu(float v) { return v > 0.f ? v : 0.2f * v; }

__device__ __forceinline__ uint32_t smem_u32(const void* p) {
    uint32_t a;
    asm("{ .reg .u64 t; cvta.to.shared.u64 t, %1; cvt.u32.u64 %0, t; }" : "=r"(a) : "l"(p));
    return a;
}
__device__ __forceinline__ void cp16(uint32_t s, const void* g) {
    asm volatile("cp.async.cg.shared.global [%0], [%1], 16;" :: "r"(s), "l"(g));
}
#define CP_COMMIT() asm volatile("cp.async.commit_group;" ::: "memory")
#define LDSM4(r0, r1, r2, r3, addr) \
    asm volatile("ldmatrix.sync.aligned.m8n8.x4.shared.b16 {%0,%1,%2,%3}, [%4];" \
                 : "=r"(r0), "=r"(r1), "=r"(r2), "=r"(r3) : "r"(addr))

__device__ __forceinline__ void mma_bf16(float* d, const uint32_t* a, const uint32_t* b) {
    asm volatile("mma.sync.aligned.m16n8k16.row.col.f32.bf16.bf16.f32 "
                 "{%0,%1,%2,%3}, {%4,%5,%6,%7}, {%8,%9}, {%0,%1,%2,%3};"
                 : "+f"(d[0]), "+f"(d[1]), "+f"(d[2]), "+f"(d[3])
                 : "r"(a[0]), "r"(a[1]), "r"(a[2]), "r"(a[3]), "r"(b[0]), "r"(b[1]));
}

// ---------------- init ----------------
__global__ void init0(int N) {
    int i = blockIdx.x * blockDim.x + threadIdx.x;
    if (i < N) g_deg[i] = 0;
    if (i < 64) { g_acc[i] = 0.f; g_cnt[i] = 0.f; }
}

// ---------------- prep: x -> bf16 + degree histogram + graph counts --------------
__global__ void prep_kernel(const float* __restrict__ x, const int* __restrict__ dst,
                            const int* __restrict__ batch, int N, int E) {
    int i = blockIdx.x * blockDim.x + threadIdx.x;
    if (i < N * 128) g_xb[i] = __float2bfloat16(x[i]);
    if (i < E) atomicAdd(&g_deg[dst[i]], 1);
    if (i < N) atomicAdd(&g_cnt[batch[i]], 1.f);
}

// weight transposes, SPLIT bf16 hi/lo
__global__ void split_wt_all(const float* __restrict__ Wl1, const float* __restrict__ Wr1,
                             const float* __restrict__ Wl2, const float* __restrict__ Wr2) {
    int i = blockIdx.x * blockDim.x + threadIdx.x;
    if (i >= 98304) return;
    const float* W;
    int K, Nout, off, j;
    if (i < 32768)      { W = Wl1; K = 128; Nout = 256; off = 0;     j = i; }
    else if (i < 65536) { W = Wr1; K = 128; Nout = 256; off = 32768; j = i - 32768; }
    else if (i < 81920) { W = Wl2; K = 256; Nout = 64;  off = 65536; j = i - 65536; }
    else                { W = Wr2; K = 256; Nout = 64;  off = 81920; j = i - 81920; }
    int k = j / Nout, n = j % Nout;
    float v = W[j];
    bf16 h = __float2bfloat16(v);
    g_wthi[off + n * K + k] = h;
    g_wtlo[off + n * K + k] = __float2bfloat16(v - __bfloat162float(h));
}

// ---------------- layer-1 GEMM: A resident, single B buffer, 2 CTAs/SM ----------
// C[m][z*256 + n]: x (Mx128) @ W (128x256); outputs bf16 xl1b / xr1b
__global__ void __launch_bounds__(256) mma_gemm1(int M)
{
    constexpr int SA = 136;
    constexpr int A_OFF = 0;        // 128*136*2 = 34816
    constexpr int B_OFF = 34816;    // B hi @ +0, B lo @ +34816 (one buffer)
    extern __shared__ char smem[];
    uint32_t sb = smem_u32(smem);
    int tid = threadIdx.x;
    int wid = tid >> 5, lane = tid & 31;
    int m0 = blockIdx.x * 128;

    // A load (once) + B chunk 0
    for (int c = tid; c < 128 * 16; c += 256) {
        int row = c >> 4, kcl = (c & 15) * 8;
        int rg = min(m0 + row, M - 1);
        cp16(sb + A_OFF + (uint32_t)(row * SA + kcl) * 2, g_xb + (size_t)rg * 128 + kcl);
    }
    for (int c = tid; c < 128 * 16; c += 256) {
        int n = c >> 4, kcl = (c & 15) * 8;
        uint32_t ta = (uint32_t)(n * SA + kcl) * 2;
        cp16(sb + B_OFF + ta, g_wthi + (size_t)n * 128 + kcl);
        cp16(sb + B_OFF + 34816 + ta, g_wtlo + (size_t)n * 128 + kcl);
    }
    CP_COMMIT();
    asm volatile("cp.async.wait_group 0;" ::: "memory");
    __syncthreads();

    int mwarp = (wid & 3) * 32;
    int nwarp = (wid >> 2) * 64;
    int sel = lane >> 3, r8 = lane & 7;
    uint32_t aoff[2], boff[4];
    #pragma unroll
    for (int mt = 0; mt < 2; mt++)
        aoff[mt] = (uint32_t)(((mwarp + mt * 16 + (sel & 1) * 8 + r8) * SA + (sel >> 1) * 8) * 2);
    #pragma unroll
    for (int bt = 0; bt < 4; bt++)
        boff[bt] = (uint32_t)(((nwarp + bt * 16 + (sel >> 1) * 8 + r8) * SA + (sel & 1) * 8) * 2);

    int g4 = lane >> 2, tig = lane & 3;

    for (int c = 0; c < 4; c++) {
        float d[2][8][4];
        #pragma unroll
        for (int mt = 0; mt < 2; mt++)
            #pragma unroll
            for (int nt = 0; nt < 8; nt++)
                #pragma unroll
                for (int j = 0; j < 4; j++) d[mt][nt][j] = 0.f;

        #pragma unroll
        for (int ks = 0; ks < 8; ks++) {
            uint32_t kb = ks * 32;
            uint32_t ah[2][4], bh[16], bl[16];
            #pragma unroll
            for (int mt = 0; mt < 2; mt++)
                LDSM4(ah[mt][0], ah[mt][1], ah[mt][2], ah[mt][3], sb + A_OFF + aoff[mt] + kb);
            #pragma unroll
            for (int bt = 0; bt < 4; bt++) {
                LDSM4(bh[bt*4], bh[bt*4+1], bh[bt*4+2], bh[bt*4+3], sb + B_OFF + boff[bt] + kb);
                LDSM4(bl[bt*4], bl[bt*4+1], bl[bt*4+2], bl[bt*4+3], sb + B_OFF + 34816 + boff[bt] + kb);
            }
            #pragma unroll
            for (int mt = 0; mt < 2; mt++)
                #pragma unroll
                for (int nt = 0; nt < 8; nt++) {
                    mma_bf16(d[mt][nt], ah[mt], &bh[nt * 2]);   // a * W_hi
                    mma_bf16(d[mt][nt], ah[mt], &bl[nt * 2]);   // a * W_lo
                }
        }
        __syncthreads();   // all warps done reading B buffer

        // issue next B chunk load (overlaps epilogue)
        if (c < 3) {
            int z = (c + 1) >> 1, nb = (c + 1) & 1;
            const bf16* WH = g_wthi + (z ? 32768 : 0) + (size_t)nb * 128 * 128;
            const bf16* WL = g_wtlo + (z ? 32768 : 0) + (size_t)nb * 128 * 128;
            for (int t = tid; t < 128 * 16; t += 256) {
                int n = t >> 4, kcl = (t & 15) * 8;
                uint32_t ta = (uint32_t)(n * SA + kcl) * 2;
                cp16(sb + B_OFF + ta, WH + (size_t)n * 128 + kcl);
                cp16(sb + B_OFF + 34816 + ta, WL + (size_t)n * 128 + kcl);
            }
            CP_COMMIT();
        }

        // epilogue: bf16 output
        int z = c >> 1, nb = c & 1;
        bf16* Cb = z ? g_xr1b : g_xl1b;
        int colb = nb * 128;
        #pragma unroll
        for (int mt = 0; mt < 2; mt++) {
            int mrow = m0 + mwarp + mt * 16 + g4;
            #pragma unroll
            for (int nt = 0; nt < 8; nt++) {
                int col = colb + nwarp + nt * 8 + tig * 2;
                if (mrow < M) {
                    __nv_bfloat162 p = __float22bfloat162_rn(make_float2(d[mt][nt][0], d[mt][nt][1]));
                    *(uint32_t*)(Cb + (size_t)mrow * 256 + col) = *(uint32_t*)&p;
                }
                if (mrow + 8 < M) {
                    __nv_bfloat162 p = __float22bfloat162_rn(make_float2(d[mt][nt][2], d[mt][nt][3]));
                    *(uint32_t*)(Cb + (size_t)(mrow + 8) * 256 + col) = *(uint32_t*)&p;
                }
            }
        }
        if (c < 3) {
            asm volatile("cp.async.wait_group 0;" ::: "memory");
            __syncthreads();
        }
    }
}

// ---------------- CSR build: coalesced 3-stage scan ----------------
__global__ void blocksum_kernel(int N) {
    __shared__ int sh[256];
    int tid = threadIdx.x;
    int i = blockIdx.x * 256 + tid;
    sh[tid] = (i < N) ? g_deg[i] : 0;
    __syncthreads();
    for (int s = 128; s > 0; s >>= 1) {
        if (tid < s) sh[tid] += sh[tid + s];
        __syncthreads();
    }
    if (tid == 0) g_bsum[blockIdx.x] = sh[0];
}
__global__ void scanb_kernel(int nb) {
    __shared__ int sh[256];
    int tid = threadIdx.x;
    int v = (tid < nb) ? g_bsum[tid] : 0;
    sh[tid] = v;
    __syncthreads();
    for (int s = 1; s < 256; s <<= 1) {
        int t = (tid >= s) ? sh[tid - s] : 0;
        __syncthreads();
        sh[tid] += t;
        __syncthreads();
    }
    if (tid < nb) g_bsum[tid] = sh[tid] - v;
}
__global__ void rowptr_kernel(int N, int E) {
    __shared__ int sh[256];
    int tid = threadIdx.x;
    int i = blockIdx.x * 256 + tid;
    int v = (i < N) ? g_deg[i] : 0;
    sh[tid] = v;
    __syncthreads();
    for (int s = 1; s < 256; s <<= 1) {
        int t = (tid >= s) ? sh[tid - s] : 0;
        __syncthreads();
        sh[tid] += t;
        __syncthreads();
    }
    if (i < N) {
        int ex = g_bsum[blockIdx.x] + sh[tid] - v;
        g_rowptr[i] = ex;
        g_woff[i] = ex;
        if (i == N - 1) g_rowptr[N] = E;
    }
}
__global__ void scatter_kernel(const int* __restrict__ src, const int* __restrict__ dst, int E) {
    int e = blockIdx.x * blockDim.x + threadIdx.x;
    if (e >= E) return;
    int pos = atomicAdd(&g_woff[dst[e]], 1);
    g_csr_src[pos] = src[e];
}

// ---------------- layer-2 GEMM: both z accumulated, K pipelined in 4x64 chunks ---
__global__ void __launch_bounds__(256) mma_gemm2(int M)
{
    constexpr int SA = 72;
    constexpr int BBYT = 9216;
    constexpr int B_OFF = 18432;
    constexpr int BUFSZ = 55296;
    extern __shared__ char smem[];
    uint32_t sb = smem_u32(smem);
    int tid = threadIdx.x;
    int wid = tid >> 5, lane = tid & 31;
    int m0 = blockIdx.x * 128;

    auto load_chunk = [&](int kc, int b) {
        uint32_t base = sb + b * BUFSZ;
        for (int c = tid; c < 128 * 8; c += 256) {
            int row = c >> 3, kcl = (c & 7) * 8;
            int rg = min(m0 + row, M - 1);
            cp16(base + (uint32_t)(row * SA + kcl) * 2, g_hb + (size_t)rg * 256 + kc * 64 + kcl);
        }
        for (int c = tid; c < 2 * 64 * 8; c += 256) {
            int z = c >> 9, r = c & 511;
            int n = r >> 3, kcl = (r & 7) * 8;
            int woff = z ? 81920 : 65536;
            uint32_t ta = (uint32_t)(n * SA + kcl) * 2;
            cp16(base + B_OFF + z * 2 * BBYT + ta, g_wthi + woff + (size_t)n * 256 + kc * 64 + kcl);
            cp16(base + B_OFF + z * 2 * BBYT + BBYT + ta, g_wtlo + woff + (size_t)n * 256 + kc * 64 + kcl);
        }
        CP_COMMIT();
    };

    load_chunk(0, 0);

    int mwarp = (wid & 3) * 32;
    int nwarp = (wid >> 2) * 32;
    int sel = lane >> 3, r8 = lane & 7;
    uint32_t aoff[2], boff[2];
    #pragma unroll
    for (int mt = 0; mt < 2; mt++)
        aoff[mt] = (uint32_t)(((mwarp + mt * 16 + (sel & 1) * 8 + r8) * SA + (sel >> 1) * 8) * 2);
    #pragma unroll
    for (int bt = 0; bt < 2; bt++)
        boff[bt] = (uint32_t)(((nwarp + bt * 16 + (sel >> 1) * 8 + r8) * SA + (sel & 1) * 8) * 2);

    float d[2][2][4][4];
    #pragma unroll
    for (int z = 0; z < 2; z++)
        #pragma unroll
        for (int mt = 0; mt < 2; mt++)
            #pragma unroll
            for (int nt = 0; nt < 4; nt++)
                #pragma unroll
                for (int j = 0; j < 4; j++) d[z][mt][nt][j] = 0.f;

    for (int kc = 0; kc < 4; kc++) {
        if (kc < 3) {
            load_chunk(kc + 1, (kc + 1) & 1);
            asm volatile("cp.async.wait_group 1;" ::: "memory");
        } else {
            asm volatile("cp.async.wait_group 0;" ::: "memory");
        }
        __syncthreads();
        uint32_t base = sb + (kc & 1) * BUFSZ;

        #pragma unroll
        for (int ks = 0; ks < 4; ks++) {
            uint32_t kb = ks * 32;
            uint32_t ah[2][4], bh[2][8], bl[2][8];
            #pragma unroll
            for (int mt = 0; mt < 2; mt++)
                LDSM4(ah[mt][0], ah[mt][1], ah[mt][2], ah[mt][3], base + aoff[mt] + kb);
            #pragma unroll
            for (int z = 0; z < 2; z++) {
                uint32_t zb = base + B_OFF + z * 2 * BBYT;
                #pragma unroll
                for (int bt = 0; bt < 2; bt++) {
                    LDSM4(bh[z][bt*4], bh[z][bt*4+1], bh[z][bt*4+2], bh[z][bt*4+3], zb + boff[bt] + kb);
                    LDSM4(bl[z][bt*4], bl[z][bt*4+1], bl[z][bt*4+2], bl[z][bt*4+3], zb + BBYT + boff[bt] + kb);
                }
            }
            #pragma unroll
            for (int z = 0; z < 2; z++)
                #pragma unroll
                for (int mt = 0; mt < 2; mt++)
                    #pragma unroll
                    for (int nt = 0; nt < 4; nt++) {
                        mma_bf16(d[z][mt][nt], ah[mt], &bh[z][nt * 2]);
                        mma_bf16(d[z][mt][nt], ah[mt], &bl[z][nt * 2]);
                    }
        }
        __syncthreads();
    }

    int g4 = lane >> 2, tig = lane & 3;
    #pragma unroll
    for (int z = 0; z < 2; z++) {
        bf16* Cb = z ? g_xr2b : g_xl2b;
        #pragma unroll
        for (int mt = 0; mt < 2; mt++) {
            int mrow = m0 + mwarp + mt * 16 + g4;
            #pragma unroll
            for (int nt = 0; nt < 4; nt++) {
                int col = nwarp + nt * 8 + tig * 2;
                if (mrow < M) {
                    __nv_bfloat162 p = __float22bfloat162_rn(make_float2(d[z][mt][nt][0], d[z][mt][nt][1]));
                    *(uint32_t*)(Cb + (size_t)mrow * 64 + col) = *(uint32_t*)&p;
                }
                if (mrow + 8 < M) {
                    __nv_bfloat162 p = __float22bfloat162_rn(make_float2(d[z][mt][nt][2], d[z][mt][nt][3]));
                    *(uint32_t*)(Cb + (size_t)(mrow + 8) * 64 + col) = *(uint32_t*)&p;
                }
            }
        }
    }
}

// ---------------- layer 1 fused attention: one warp per dst, 2-edge ILP ----------
__global__ void gat1_kernel(const float* __restrict__ att, const float* __restrict__ b1, int N)
{
    int d = (blockIdx.x * blockDim.x + threadIdx.x) >> 5;
    if (d >= N) return;
    int lane = threadIdx.x & 31;
    int off = lane * 8;

    uint4 xrr = *(const uint4*)(g_xr1b + (size_t)d * 256 + off);
    float2 xr0 = __bfloat1622float2(*(__nv_bfloat162*)&xrr.x);
    float2 xr1 = __bfloat1622float2(*(__nv_bfloat162*)&xrr.y);
    float2 xr2 = __bfloat1622float2(*(__nv_bfloat162*)&xrr.z);
    float2 xr3 = __bfloat1622float2(*(__nv_bfloat162*)&xrr.w);
    float4 aw0 = *(const float4*)(att + off);
    float4 aw1 = *(const float4*)(att + off + 4);

    float num[8];
    #pragma unroll
    for (int j = 0; j < 8; j++) num[j] = 0.f;
    float den = 0.f;

    int lo = g_rowptr[d], hi = g_rowptr[d + 1];
    int cnt = hi - lo + 1;   // + self loop (last slot)

    auto srcAt = [&](int i) { return (lo + i < hi) ? g_csr_src[lo + i] : d; };
    auto ld = [&](int i) { return *(const uint4*)(g_xl1b + (size_t)srcAt(i) * 256 + off); };

    uint4 v0 = ld(0);
    uint4 v1 = (cnt > 1) ? ld(1) : v0;

    int i = 0;
    for (; i + 1 < cnt; i += 2) {
        uint4 c0 = v0, c1 = v1;
        if (i + 2 < cnt) v0 = ld(i + 2);
        if (i + 3 < cnt) v1 = ld(i + 3);
        float2 a0 = __bfloat1622float2(*(__nv_bfloat162*)&c0.x);
        float2 a1 = __bfloat1622float2(*(__nv_bfloat162*)&c0.y);
        float2 a2 = __bfloat1622float2(*(__nv_bfloat162*)&c0.z);
        float2 a3 = __bfloat1622float2(*(__nv_bfloat162*)&c0.w);
        float2 q0 = __bfloat1622float2(*(__nv_bfloat162*)&c1.x);
        float2 q1 = __bfloat1622float2(*(__nv_bfloat162*)&c1.y);
        float2 q2 = __bfloat1622float2(*(__nv_bfloat162*)&c1.z);
        float2 q3 = __bfloat1622float2(*(__nv_bfloat162*)&c1.w);
        float p0 = lrelu(a0.x + xr0.x) * aw0.x + lrelu(a0.y + xr0.y) * aw0.y
                 + lrelu(a1.x + xr1.x) * aw0.z + lrelu(a1.y + xr1.y) * aw0.w
                 + lrelu(a2.x + xr2.x) * aw1.x + lrelu(a2.y + xr2.y) * aw1.y
                 + lrelu(a3.x + xr3.x) * aw1.z + lrelu(a3.y + xr3.y) * aw1.w;
        float p1 = lrelu(q0.x + xr0.x) * aw0.x + lrelu(q0.y + xr0.y) * aw0.y
                 + lrelu(q1.x + xr1.x) * aw0.z + lrelu(q1.y + xr1.y) * aw0.w
                 + lrelu(q2.x + xr2.x) * aw1.x + lrelu(q2.y + xr2.y) * aw1.y
                 + lrelu(q3.x + xr3.x) * aw1.z + lrelu(q3.y + xr3.y) * aw1.w;
        p0 += __shfl_xor_sync(0xffffffffu, p0, 1);
        p1 += __shfl_xor_sync(0xffffffffu, p1, 1);
        p0 += __shfl_xor_sync(0xffffffffu, p0, 2);
        p1 += __shfl_xor_sync(0xffffffffu, p1, 2);
        p0 += __shfl_xor_sync(0xffffffffu, p0, 4);
        p1 += __shfl_xor_sync(0xffffffffu, p1, 4);
        float e0 = __expf(p0), e1 = __expf(p1);
        den += e0 + e1;
        num[0] += e0 * a0.x + e1 * q0.x; num[1] += e0 * a0.y + e1 * q0.y;
        num[2] += e0 * a1.x + e1 * q1.x; num[3] += e0 * a1.y + e1 * q1.y;
        num[4] += e0 * a2.x + e1 * q2.x; num[5] += e0 * a2.y + e1 * q2.y;
        num[6] += e0 * a3.x + e1 * q3.x; num[7] += e0 * a3.y + e1 * q3.y;
    }
    if (i < cnt) {   // odd tail
        uint4 c0 = v0;
        float2 a0 = __bfloat1622float2(*(__nv_bfloat162*)&c0.x);
        float2 a1 = __bfloat1622float2(*(__nv_bfloat162*)&c0.y);
        float2 a2 = __bfloat1622float2(*(__nv_bfloat162*)&c0.z);
        float2 a3 = __bfloat1622float2(*(__nv_bfloat162*)&c0.w);
        float p0 = lrelu(a0.x + xr0.x) * aw0.x + lrelu(a0.y + xr0.y) * aw0.y
                 + lrelu(a1.x + xr1.x) * aw0.z + lrelu(a1.y + xr1.y) * aw0.w
                 + lrelu(a2.x + xr2.x) * aw1.x + lrelu(a2.y + xr2.y) * aw1.y
                 + lrelu(a3.x + xr3.x) * aw1.z + lrelu(a3.y + xr3.y) * aw1.w;
        p0 += __shfl_xor_sync(0xffffffffu, p0, 1);
        p0 += __shfl_xor_sync(0xffffffffu, p0, 2);
        p0 += __shfl_xor_sync(0xffffffffu, p0, 4);
        float e0 = __expf(p0);
        den += e0;
        num[0] += e0 * a0.x; num[1] += e0 * a0.y; num[2] += e0 * a1.x; num[3] += e0 * a1.y;
        num[4] += e0 * a2.x; num[5] += e0 * a2.y; num[6] += e0 * a3.x; num[7] += e0 * a3.y;
    }

    float inv = 1.f / (den + 1e-16f);
    float4 bb0 = *(const float4*)(b1 + off);
    float4 bb1 = *(const float4*)(b1 + off + 4);
    float bias[8] = {bb0.x, bb0.y, bb0.z, bb0.w, bb1.x, bb1.y, bb1.z, bb1.w};
    bf16 h8[8];
    #pragma unroll
    for (int j = 0; j < 8; j++)
        h8[j] = __float2bfloat16(fmaxf(num[j] * inv + bias[j], 0.f));
    *(uint4*)(g_hb + (size_t)d * 256 + off) = *(uint4*)h8;
}

// ---------------- layer 2 fused attention + pooling: 2-edge ILP ------------------
__global__ void gat2_kernel(const float* __restrict__ att, const int* __restrict__ batch,
                            const float* __restrict__ b2, const float* __restrict__ Wo, int N)
{
    int d = (blockIdx.x * blockDim.x + threadIdx.x) >> 5;
    if (d >= N) return;
    int lane = threadIdx.x & 31;
    int off = lane * 2;

    uint32_t xrr = *(const uint32_t*)(g_xr2b + (size_t)d * 64 + off);
    float2 xr = __bfloat1622float2(*(__nv_bfloat162*)&xrr);
    float2 aw = *(const float2*)(att + off);

    float num0 = 0.f, num1 = 0.f, den = 0.f;
    int lo = g_rowptr[d], hi = g_rowptr[d + 1];
    int cnt = hi - lo + 1;

    auto srcAt = [&](int i) { return (lo + i < hi) ? g_csr_src[lo + i] : d; };
    auto ld = [&](int i) { return *(const uint32_t*)(g_xl2b + (size_t)srcAt(i) * 64 + off); };

    uint32_t v0 = ld(0);
    uint32_t v1 = (cnt > 1) ? ld(1) : v0;

    int i = 0;
    for (; i + 1 < cnt; i += 2) {
        uint32_t c0 = v0, c1 = v1;
        if (i + 2 < cnt) v0 = ld(i + 2);
        if (i + 3 < cnt) v1 = ld(i + 3);
        float2 x0 = __bfloat1622float2(*(__nv_bfloat162*)&c0);
        float2 x1 = __bfloat1622float2(*(__nv_bfloat162*)&c1);
        float p0 = lrelu(x0.x + xr.x) * aw.x + lrelu(x0.y + xr.y) * aw.y;
        float p1 = lrelu(x1.x + xr.x) * aw.x + lrelu(x1.y + xr.y) * aw.y;
        p0 += __shfl_xor_sync(0xffffffffu, p0, 1);
        p1 += __shfl_xor_sync(0xffffffffu, p1, 1);
        p0 += __shfl_xor_sync(0xffffffffu, p0, 2);
        p1 += __shfl_xor_sync(0xffffffffu, p1, 2);
        p0 += __shfl_xor_sync(0xffffffffu, p0, 4);
        p1 += __shfl_xor_sync(0xffffffffu, p1, 4);
        p0 += __shfl_xor_sync(0xffffffffu, p0, 8);
        p1 += __shfl_xor_sync(0xffffffffu, p1, 8);
        p0 += __shfl_xor_sync(0xffffffffu, p0, 16);
        p1 += __shfl_xor_sync(0xffffffffu, p1, 16);
        float e0 = __expf(p0), e1 = __expf(p1);
        den += e0 + e1;
        num0 += e0 * x0.x + e1 * x1.x;
        num1 += e0 * x0.y + e1 * x1.y;
    }
    if (i < cnt) {
        float2 x0 = __bfloat1622float2(*(__nv_bfloat162*)&v0);
        float p0 = lrelu(x0.x + xr.x) * aw.x + lrelu(x0.y + xr.y) * aw.y;
        p0 += __shfl_xor_sync(0xffffffffu, p0, 1);
        p0 += __shfl_xor_sync(0xffffffffu, p0, 2);
        p0 += __shfl_xor_sync(0xffffffffu, p0, 4);
        p0 += __shfl_xor_sync(0xffffffffu, p0, 8);
        p0 += __shfl_xor_sync(0xffffffffu, p0, 16);
        float e0 = __expf(p0);
        den += e0;
        num0 += e0 * x0.x;
        num1 += e0 * x0.y;
    }

    float inv = 1.f / (den + 1e-16f);
    float2 bb = *(const float2*)(b2 + off);
    float2 wo = *(const float2*)(Wo + off);
    float y = (num0 * inv + bb.x) * wo.x + (num1 * inv + bb.y) * wo.y;
    y += __shfl_xor_sync(0xffffffffu, y, 1);
    y += __shfl_xor_sync(0xffffffffu, y, 2);
    y += __shfl_xor_sync(0xffffffffu, y, 4);
    y += __shfl_xor_sync(0xffffffffu, y, 8);
    y += __shfl_xor_sync(0xffffffffu, y, 16);
    if (lane == 0) atomicAdd(&g_acc[batch[d]], y);
}

__global__ void final_kernel(float* __restrict__ out, int G, const float* __restrict__ bo)
{
    int g = threadIdx.x;
    if (g < G) out[g] = g_acc[g] / fmaxf(g_cnt[g], 1.f) + bo[0];
}

// ---------------- launch ----------------
extern "C" void kernel_launch(void* const* d_in, const int* in_sizes, int n_in,
                              void* d_out, int out_size)
{
    const float* x    = (const float*)d_in[0];
    const int* ei     = (const int*)d_in[1];
    const int* bat    = (const int*)d_in[2];
    const float* Wl1 = (const float*)d_in[3];
    const float* Wr1 = (const float*)d_in[4];
    const float* att1 = (const float*)d_in[5];
    const float* b1  = (const float*)d_in[6];
    const float* Wl2 = (const float*)d_in[7];
    const float* Wr2 = (const float*)d_in[8];
    const float* att2 = (const float*)d_in[9];
    const float* b2  = (const float*)d_in[10];
    const float* Wo  = (const float*)d_in[11];
    const float* bo  = (const float*)d_in[12];

    int N = in_sizes[0] / 128;
    int E = in_sizes[1] / 2;
    int G = out_size;
    const int* src = ei;
    const int* dst = ei + E;
    int tiles = (N + 127) / 128;
    int nb = (N + 255) / 256;

    const int SM1 = 34816 + 69632;       // A + one B(hi+lo) buf = 104448 -> 2 CTAs/SM
    const int SM2 = 2 * 55296;           // 110592 -> 2 CTAs/SM
    cudaFuncSetAttribute(mma_gemm1, cudaFuncAttributeMaxDynamicSharedMemorySize, SM1);
    cudaFuncSetAttribute(mma_gemm2, cudaFuncAttributeMaxDynamicSharedMemorySize, SM2);

    init0<<<(N + 255) / 256, 256>>>(N);                             // 1
    prep_kernel<<<(N * 128 + 255) / 256, 256>>>(x, dst, bat, N, E); // 2
    split_wt_all<<<(98304 + 255) / 256, 256>>>(Wl1, Wr1, Wl2, Wr2); // 3
    mma_gemm1<<<tiles, 256, SM1>>>(N);                              // 4 <- profiled slot

    blocksum_kernel<<<nb, 256>>>(N);                                // 5
    scanb_kernel<<<1, 256>>>(nb);                                   // 6
    rowptr_kernel<<<nb, 256>>>(N, E);                               // 7
    scatter_kernel<<<(E + 255) / 256, 256>>>(src, dst, E);          // 8

    gat1_kernel<<<(N * 32 + 255) / 256, 256>>>(att1, b1, N);        // 9
    mma_gemm2<<<tiles, 256, SM2>>>(N);                              // 10
    gat2_kernel<<<(N * 32 + 255) / 256, 256>>>(att2, bat, b2, Wo, N); // 11
    final_kernel<<<1, 64>>>((float*)d_out, G, bo);                  // 12
}

// round 13
// speedup vs baseline: 3.8148x; 1.0368x over previous
#include <cuda_runtime.h>
#include <cuda_bf16.h>
#include <cstdint>

#define MAXN 50000
#define MAXE 800000
typedef __nv_bfloat16 bf16;

// ---------------- scratch (device globals; no allocation allowed) ----------------
__device__ __align__(16) bf16 g_xl1b[(size_t)MAXN * 256];
__device__ __align__(16) bf16 g_xr1b[(size_t)MAXN * 256];
__device__ __align__(16) bf16 g_xl2b[(size_t)MAXN * 64];
__device__ __align__(16) bf16 g_xr2b[(size_t)MAXN * 64];
__device__ __align__(16) bf16 g_xb[(size_t)MAXN * 128];   // x as plain bf16
__device__ __align__(16) bf16 g_hb[(size_t)MAXN * 256];   // h as plain bf16
// weight transposes [n][k], SPLIT bf16: w1l@0 (256x128), w1r@32768, w2l@65536 (64x256), w2r@81920
__device__ __align__(16) bf16 g_wthi[98304];
__device__ __align__(16) bf16 g_wtlo[98304];
__device__ int g_deg[MAXN];
__device__ int g_rowptr[MAXN + 1];
__device__ int g_woff[MAXN];
__device__ int g_csr_src[MAXE];
__device__ int g_bsum[256];
__device__ float g_acc[64];
__device__ float g_cnt[64];

__device__ __forceinline__ float lrelu(float v) { return v > 0.f ? v : 0.2f * v; }

__device__ __forceinline__ uint32_t smem_u32(const void* p) {
    uint32_t a;
    asm("{ .reg .u64 t; cvta.to.shared.u64 t, %1; cvt.u32.u64 %0, t; }" : "=r"(a) : "l"(p));
    return a;
}
__device__ __forceinline__ void cp16(uint32_t s, const void* g) {
    asm volatile("cp.async.cg.shared.global [%0], [%1], 16;" :: "r"(s), "l"(g));
}
#define CP_COMMIT() asm volatile("cp.async.commit_group;" ::: "memory")
#define LDSM4(r0, r1, r2, r3, addr) \
    asm volatile("ldmatrix.sync.aligned.m8n8.x4.shared.b16 {%0,%1,%2,%3}, [%4];" \
                 : "=r"(r0), "=r"(r1), "=r"(r2), "=r"(r3) : "r"(addr))

__device__ __forceinline__ void mma_bf16(float* d, const uint32_t* a, const uint32_t* b) {
    asm volatile("mma.sync.aligned.m16n8k16.row.col.f32.bf16.bf16.f32 "
                 "{%0,%1,%2,%3}, {%4,%5,%6,%7}, {%8,%9}, {%0,%1,%2,%3};"
                 : "+f"(d[0]), "+f"(d[1]), "+f"(d[2]), "+f"(d[3])
                 : "r"(a[0]), "r"(a[1]), "r"(a[2]), "r"(a[3]), "r"(b[0]), "r"(b[1]));
}

// ---------------- init ----------------
__global__ void init0(int N) {
    int i = blockIdx.x * blockDim.x + threadIdx.x;
    if (i < N) g_deg[i] = 0;
    if (i < 64) { g_acc[i] = 0.f; g_cnt[i] = 0.f; }
}

// ---------------- prep: x -> bf16 + degree histogram + graph counts --------------
__global__ void prep_kernel(const float* __restrict__ x, const int* __restrict__ dst,
                            const int* __restrict__ batch, int N, int E) {
    int i = blockIdx.x * blockDim.x + threadIdx.x;
    if (i < N * 128) g_xb[i] = __float2bfloat16(x[i]);
    if (i < E) atomicAdd(&g_deg[dst[i]], 1);
    if (i < N) atomicAdd(&g_cnt[batch[i]], 1.f);
}

// weight transposes, SPLIT bf16 hi/lo
__global__ void split_wt_all(const float* __restrict__ Wl1, const float* __restrict__ Wr1,
                             const float* __restrict__ Wl2, const float* __restrict__ Wr2) {
    int i = blockIdx.x * blockDim.x + threadIdx.x;
    if (i >= 98304) return;
    const float* W;
    int K, Nout, off, j;
    if (i < 32768)      { W = Wl1; K = 128; Nout = 256; off = 0;     j = i; }
    else if (i < 65536) { W = Wr1; K = 128; Nout = 256; off = 32768; j = i - 32768; }
    else if (i < 81920) { W = Wl2; K = 256; Nout = 64;  off = 65536; j = i - 65536; }
    else                { W = Wr2; K = 256; Nout = 64;  off = 81920; j = i - 81920; }
    int k = j / Nout, n = j % Nout;
    float v = W[j];
    bf16 h = __float2bfloat16(v);
    g_wthi[off + n * K + k] = h;
    g_wtlo[off + n * K + k] = __float2bfloat16(v - __bfloat162float(h));
}

// ---------------- layer-1 GEMM: A resident; 8 x (64-row B) chunks double-buffered;
//                  104 KB smem -> 2 CTAs/SM. C: x (Mx128) @ W (128x256), 2 weights.
__global__ void __launch_bounds__(256) mma_gemm1(int M)
{
    constexpr int SA = 136;
    constexpr int A_OFF = 0;          // 128*136*2 = 34816
    constexpr int BUF0 = 34816;       // two B bufs of 64 rows (hi@+0, lo@+17408)
    constexpr int BUFSZ = 34816;
    extern __shared__ char smem[];
    uint32_t sb = smem_u32(smem);
    int tid = threadIdx.x;
    int wid = tid >> 5, lane = tid & 31;
    int m0 = blockIdx.x * 128;

    // chunk c (0..7): weight z = c>>2, n-rows [ (c&3)*64, +64 )
    auto load_b = [&](int c, int b) {
        const bf16* WH = g_wthi + ((c >> 2) ? 32768 : 0) + (size_t)(c & 3) * 64 * 128;
        const bf16* WL = g_wtlo + ((c >> 2) ? 32768 : 0) + (size_t)(c & 3) * 64 * 128;
        uint32_t bbase = sb + BUF0 + b * BUFSZ;
        for (int t = tid; t < 64 * 16; t += 256) {
            int n = t >> 4, kcl = (t & 15) * 8;
            uint32_t ta = (uint32_t)(n * SA + kcl) * 2;
            cp16(bbase + ta, WH + (size_t)n * 128 + kcl);
            cp16(bbase + 17408 + ta, WL + (size_t)n * 128 + kcl);
        }
        CP_COMMIT();
    };

    // A load (once): 128 rows x 128 k, plain bf16
    for (int c = tid; c < 128 * 16; c += 256) {
        int row = c >> 4, kcl = (c & 15) * 8;
        int rg = min(m0 + row, M - 1);
        cp16(sb + A_OFF + (uint32_t)(row * SA + kcl) * 2, g_xb + (size_t)rg * 128 + kcl);
    }
    CP_COMMIT();
    load_b(0, 0);
    load_b(1, 1);

    int mwarp = (wid & 3) * 32;
    int nwarp = (wid >> 2) * 32;      // 2 n-warps x 32 cols over BN=64
    int sel = lane >> 3, r8 = lane & 7;
    uint32_t aoff[2], boff[2];
    #pragma unroll
    for (int mt = 0; mt < 2; mt++)
        aoff[mt] = (uint32_t)(((mwarp + mt * 16 + (sel & 1) * 8 + r8) * SA + (sel >> 1) * 8) * 2);
    #pragma unroll
    for (int bt = 0; bt < 2; bt++)
        boff[bt] = (uint32_t)(((nwarp + bt * 16 + (sel >> 1) * 8 + r8) * SA + (sel & 1) * 8) * 2);

    int g4 = lane >> 2, tig = lane & 3;

    for (int c = 0; c < 8; c++) {
        // ensure chunk c loaded: allow 1 pending (chunk c+1) except at the end
        if (c < 7) asm volatile("cp.async.wait_group 1;" ::: "memory");
        else       asm volatile("cp.async.wait_group 0;" ::: "memory");
        __syncthreads();

        uint32_t bb = sb + BUF0 + (c & 1) * BUFSZ;
        float d[2][4][4];
        #pragma unroll
        for (int mt = 0; mt < 2; mt++)
            #pragma unroll
            for (int nt = 0; nt < 4; nt++)
                #pragma unroll
                for (int j = 0; j < 4; j++) d[mt][nt][j] = 0.f;

        #pragma unroll
        for (int ks = 0; ks < 8; ks++) {
            uint32_t kb = ks * 32;
            uint32_t ah[2][4], bh[8], bl[8];
            #pragma unroll
            for (int mt = 0; mt < 2; mt++)
                LDSM4(ah[mt][0], ah[mt][1], ah[mt][2], ah[mt][3], sb + A_OFF + aoff[mt] + kb);
            #pragma unroll
            for (int bt = 0; bt < 2; bt++) {
                LDSM4(bh[bt*4], bh[bt*4+1], bh[bt*4+2], bh[bt*4+3], bb + boff[bt] + kb);
                LDSM4(bl[bt*4], bl[bt*4+1], bl[bt*4+2], bl[bt*4+3], bb + 17408 + boff[bt] + kb);
            }
            #pragma unroll
            for (int mt = 0; mt < 2; mt++)
                #pragma unroll
                for (int nt = 0; nt < 4; nt++) {
                    mma_bf16(d[mt][nt], ah[mt], &bh[nt * 2]);   // a * W_hi
                    mma_bf16(d[mt][nt], ah[mt], &bl[nt * 2]);   // a * W_lo
                }
        }
        __syncthreads();   // all warps done with buffer (c&1)

        if (c + 2 < 8) load_b(c + 2, c & 1);   // refill; epilogue overlaps it

        // epilogue: bf16 output, 64 columns of weight z at colb
        int z = c >> 2;
        int colb = (c & 3) * 64;
        bf16* Cb = z ? g_xr1b : g_xl1b;
        #pragma unroll
        for (int mt = 0; mt < 2; mt++) {
            int mrow = m0 + mwarp + mt * 16 + g4;
            #pragma unroll
            for (int nt = 0; nt < 4; nt++) {
                int col = colb + nwarp + nt * 8 + tig * 2;
                if (mrow < M) {
                    __nv_bfloat162 p = __float22bfloat162_rn(make_float2(d[mt][nt][0], d[mt][nt][1]));
                    *(uint32_t*)(Cb + (size_t)mrow * 256 + col) = *(uint32_t*)&p;
                }
                if (mrow + 8 < M) {
                    __nv_bfloat162 p = __float22bfloat162_rn(make_float2(d[mt][nt][2], d[mt][nt][3]));
                    *(uint32_t*)(Cb + (size_t)(mrow + 8) * 256 + col) = *(uint32_t*)&p;
                }
            }
        }
    }
}

// ---------------- CSR build: coalesced 3-stage scan ----------------
__global__ void blocksum_kernel(int N) {
    __shared__ int sh[256];
    int tid = threadIdx.x;
    int i = blockIdx.x * 256 + tid;
    sh[tid] = (i < N) ? g_deg[i] : 0;
    __syncthreads();
    for (int s = 128; s > 0; s >>= 1) {
        if (tid < s) sh[tid] += sh[tid + s];
        __syncthreads();
    }
    if (tid == 0) g_bsum[blockIdx.x] = sh[0];
}
__global__ void scanb_kernel(int nb) {
    __shared__ int sh[256];
    int tid = threadIdx.x;
    int v = (tid < nb) ? g_bsum[tid] : 0;
    sh[tid] = v;
    __syncthreads();
    for (int s = 1; s < 256; s <<= 1) {
        int t = (tid >= s) ? sh[tid - s] : 0;
        __syncthreads();
        sh[tid] += t;
        __syncthreads();
    }
    if (tid < nb) g_bsum[tid] = sh[tid] - v;
}
__global__ void rowptr_kernel(int N, int E) {
    __shared__ int sh[256];
    int tid = threadIdx.x;
    int i = blockIdx.x * 256 + tid;
    int v = (i < N) ? g_deg[i] : 0;
    sh[tid] = v;
    __syncthreads();
    for (int s = 1; s < 256; s <<= 1) {
        int t = (tid >= s) ? sh[tid - s] : 0;
        __syncthreads();
        sh[tid] += t;
        __syncthreads();
    }
    if (i < N) {
        int ex = g_bsum[blockIdx.x] + sh[tid] - v;
        g_rowptr[i] = ex;
        g_woff[i] = ex;
        if (i == N - 1) g_rowptr[N] = E;
    }
}
__global__ void scatter_kernel(const int* __restrict__ src, const int* __restrict__ dst, int E) {
    int e = blockIdx.x * blockDim.x + threadIdx.x;
    if (e >= E) return;
    int pos = atomicAdd(&g_woff[dst[e]], 1);
    g_csr_src[pos] = src[e];
}

// ---------------- layer-2 GEMM: both z accumulated, K pipelined in 4x64 chunks ---
__global__ void __launch_bounds__(256) mma_gemm2(int M)
{
    constexpr int SA = 72;
    constexpr int BBYT = 9216;
    constexpr int B_OFF = 18432;
    constexpr int BUFSZ = 55296;
    extern __shared__ char smem[];
    uint32_t sb = smem_u32(smem);
    int tid = threadIdx.x;
    int wid = tid >> 5, lane = tid & 31;
    int m0 = blockIdx.x * 128;

    auto load_chunk = [&](int kc, int b) {
        uint32_t base = sb + b * BUFSZ;
        for (int c = tid; c < 128 * 8; c += 256) {
            int row = c >> 3, kcl = (c & 7) * 8;
            int rg = min(m0 + row, M - 1);
            cp16(base + (uint32_t)(row * SA + kcl) * 2, g_hb + (size_t)rg * 256 + kc * 64 + kcl);
        }
        for (int c = tid; c < 2 * 64 * 8; c += 256) {
            int z = c >> 9, r = c & 511;
            int n = r >> 3, kcl = (r & 7) * 8;
            int woff = z ? 81920 : 65536;
            uint32_t ta = (uint32_t)(n * SA + kcl) * 2;
            cp16(base + B_OFF + z * 2 * BBYT + ta, g_wthi + woff + (size_t)n * 256 + kc * 64 + kcl);
            cp16(base + B_OFF + z * 2 * BBYT + BBYT + ta, g_wtlo + woff + (size_t)n * 256 + kc * 64 + kcl);
        }
        CP_COMMIT();
    };

    load_chunk(0, 0);

    int mwarp = (wid & 3) * 32;
    int nwarp = (wid >> 2) * 32;
    int sel = lane >> 3, r8 = lane & 7;
    uint32_t aoff[2], boff[2];
    #pragma unroll
    for (int mt = 0; mt < 2; mt++)
        aoff[mt] = (uint32_t)(((mwarp + mt * 16 + (sel & 1) * 8 + r8) * SA + (sel >> 1) * 8) * 2);
    #pragma unroll
    for (int bt = 0; bt < 2; bt++)
        boff[bt] = (uint32_t)(((nwarp + bt * 16 + (sel >> 1) * 8 + r8) * SA + (sel & 1) * 8) * 2);

    float d[2][2][4][4];
    #pragma unroll
    for (int z = 0; z < 2; z++)
        #pragma unroll
        for (int mt = 0; mt < 2; mt++)
            #pragma unroll
            for (int nt = 0; nt < 4; nt++)
                #pragma unroll
                for (int j = 0; j < 4; j++) d[z][mt][nt][j] = 0.f;

    for (int kc = 0; kc < 4; kc++) {
        if (kc < 3) {
            load_chunk(kc + 1, (kc + 1) & 1);
            asm volatile("cp.async.wait_group 1;" ::: "memory");
        } else {
            asm volatile("cp.async.wait_group 0;" ::: "memory");
        }
        __syncthreads();
        uint32_t base = sb + (kc & 1) * BUFSZ;

        #pragma unroll
        for (int ks = 0; ks < 4; ks++) {
            uint32_t kb = ks * 32;
            uint32_t ah[2][4], bh[2][8], bl[2][8];
            #pragma unroll
            for (int mt = 0; mt < 2; mt++)
                LDSM4(ah[mt][0], ah[mt][1], ah[mt][2], ah[mt][3], base + aoff[mt] + kb);
            #pragma unroll
            for (int z = 0; z < 2; z++) {
                uint32_t zb = base + B_OFF + z * 2 * BBYT;
                #pragma unroll
                for (int bt = 0; bt < 2; bt++) {
                    LDSM4(bh[z][bt*4], bh[z][bt*4+1], bh[z][bt*4+2], bh[z][bt*4+3], zb + boff[bt] + kb);
                    LDSM4(bl[z][bt*4], bl[z][bt*4+1], bl[z][bt*4+2], bl[z][bt*4+3], zb + BBYT + boff[bt] + kb);
                }
            }
            #pragma unroll
            for (int z = 0; z < 2; z++)
                #pragma unroll
                for (int mt = 0; mt < 2; mt++)
                    #pragma unroll
                    for (int nt = 0; nt < 4; nt++) {
                        mma_bf16(d[z][mt][nt], ah[mt], &bh[z][nt * 2]);
                        mma_bf16(d[z][mt][nt], ah[mt], &bl[z][nt * 2]);
                    }
        }
        __syncthreads();
    }

    int g4 = lane >> 2, tig = lane & 3;
    #pragma unroll
    for (int z = 0; z < 2; z++) {
        bf16* Cb = z ? g_xr2b : g_xl2b;
        #pragma unroll
        for (int mt = 0; mt < 2; mt++) {
            int mrow = m0 + mwarp + mt * 16 + g4;
            #pragma unroll
            for (int nt = 0; nt < 4; nt++) {
                int col = nwarp + nt * 8 + tig * 2;
                if (mrow < M) {
                    __nv_bfloat162 p = __float22bfloat162_rn(make_float2(d[z][mt][nt][0], d[z][mt][nt][1]));
                    *(uint32_t*)(Cb + (size_t)mrow * 64 + col) = *(uint32_t*)&p;
                }
                if (mrow + 8 < M) {
                    __nv_bfloat162 p = __float22bfloat162_rn(make_float2(d[z][mt][nt][2], d[z][mt][nt][3]));
                    *(uint32_t*)(Cb + (size_t)(mrow + 8) * 64 + col) = *(uint32_t*)&p;
                }
            }
        }
    }
}

// ---------------- layer 1 fused attention: one warp per dst, 2-edge ILP ----------
__global__ void gat1_kernel(const float* __restrict__ att, const float* __restrict__ b1, int N)
{
    int d = (blockIdx.x * blockDim.x + threadIdx.x) >> 5;
    if (d >= N) return;
    int lane = threadIdx.x & 31;
    int off = lane * 8;

    uint4 xrr = *(const uint4*)(g_xr1b + (size_t)d * 256 + off);
    float2 xr0 = __bfloat1622float2(*(__nv_bfloat162*)&xrr.x);
    float2 xr1 = __bfloat1622float2(*(__nv_bfloat162*)&xrr.y);
    float2 xr2 = __bfloat1622float2(*(__nv_bfloat162*)&xrr.z);
    float2 xr3 = __bfloat1622float2(*(__nv_bfloat162*)&xrr.w);
    float4 aw0 = *(const float4*)(att + off);
    float4 aw1 = *(const float4*)(att + off + 4);

    float num[8];
    #pragma unroll
    for (int j = 0; j < 8; j++) num[j] = 0.f;
    float den = 0.f;

    int lo = g_rowptr[d], hi = g_rowptr[d + 1];
    int cnt = hi - lo + 1;   // + self loop (last slot)

    auto srcAt = [&](int i) { return (lo + i < hi) ? g_csr_src[lo + i] : d; };
    auto ld = [&](int i) { return *(const uint4*)(g_xl1b + (size_t)srcAt(i) * 256 + off); };

    uint4 v0 = ld(0);
    uint4 v1 = (cnt > 1) ? ld(1) : v0;

    int i = 0;
    for (; i + 1 < cnt; i += 2) {
        uint4 c0 = v0, c1 = v1;
        if (i + 2 < cnt) v0 = ld(i + 2);
        if (i + 3 < cnt) v1 = ld(i + 3);
        float2 a0 = __bfloat1622float2(*(__nv_bfloat162*)&c0.x);
        float2 a1 = __bfloat1622float2(*(__nv_bfloat162*)&c0.y);
        float2 a2 = __bfloat1622float2(*(__nv_bfloat162*)&c0.z);
        float2 a3 = __bfloat1622float2(*(__nv_bfloat162*)&c0.w);
        float2 q0 = __bfloat1622float2(*(__nv_bfloat162*)&c1.x);
        float2 q1 = __bfloat1622float2(*(__nv_bfloat162*)&c1.y);
        float2 q2 = __bfloat1622float2(*(__nv_bfloat162*)&c1.z);
        float2 q3 = __bfloat1622float2(*(__nv_bfloat162*)&c1.w);
        float p0 = lrelu(a0.x + xr0.x) * aw0.x + lrelu(a0.y + xr0.y) * aw0.y
                 + lrelu(a1.x + xr1.x) * aw0.z + lrelu(a1.y + xr1.y) * aw0.w
                 + lrelu(a2.x + xr2.x) * aw1.x + lrelu(a2.y + xr2.y) * aw1.y
                 + lrelu(a3.x + xr3.x) * aw1.z + lrelu(a3.y + xr3.y) * aw1.w;
        float p1 = lrelu(q0.x + xr0.x) * aw0.x + lrelu(q0.y + xr0.y) * aw0.y
                 + lrelu(q1.x + xr1.x) * aw0.z + lrelu(q1.y + xr1.y) * aw0.w
                 + lrelu(q2.x + xr2.x) * aw1.x + lrelu(q2.y + xr2.y) * aw1.y
                 + lrelu(q3.x + xr3.x) * aw1.z + lrelu(q3.y + xr3.y) * aw1.w;
        p0 += __shfl_xor_sync(0xffffffffu, p0, 1);
        p1 += __shfl_xor_sync(0xffffffffu, p1, 1);
        p0 += __shfl_xor_sync(0xffffffffu, p0, 2);
        p1 += __shfl_xor_sync(0xffffffffu, p1, 2);
        p0 += __shfl_xor_sync(0xffffffffu, p0, 4);
        p1 += __shfl_xor_sync(0xffffffffu, p1, 4);
        float e0 = __expf(p0), e1 = __expf(p1);
        den += e0 + e1;
        num[0] += e0 * a0.x + e1 * q0.x; num[1] += e0 * a0.y + e1 * q0.y;
        num[2] += e0 * a1.x + e1 * q1.x; num[3] += e0 * a1.y + e1 * q1.y;
        num[4] += e0 * a2.x + e1 * q2.x; num[5] += e0 * a2.y + e1 * q2.y;
        num[6] += e0 * a3.x + e1 * q3.x; num[7] += e0 * a3.y + e1 * q3.y;
    }
    if (i < cnt) {   // odd tail
        uint4 c0 = v0;
        float2 a0 = __bfloat1622float2(*(__nv_bfloat162*)&c0.x);
        float2 a1 = __bfloat1622float2(*(__nv_bfloat162*)&c0.y);
        float2 a2 = __bfloat1622float2(*(__nv_bfloat162*)&c0.z);
        float2 a3 = __bfloat1622float2(*(__nv_bfloat162*)&c0.w);
        float p0 = lrelu(a0.x + xr0.x) * aw0.x + lrelu(a0.y + xr0.y) * aw0.y
                 + lrelu(a1.x + xr1.x) * aw0.z + lrelu(a1.y + xr1.y) * aw0.w
                 + lrelu(a2.x + xr2.x) * aw1.x + lrelu(a2.y + xr2.y) * aw1.y
                 + lrelu(a3.x + xr3.x) * aw1.z + lrelu(a3.y + xr3.y) * aw1.w;
        p0 += __shfl_xor_sync(0xffffffffu, p0, 1);
        p0 += __shfl_xor_sync(0xffffffffu, p0, 2);
        p0 += __shfl_xor_sync(0xffffffffu, p0, 4);
        float e0 = __expf(p0);
        den += e0;
        num[0] += e0 * a0.x; num[1] += e0 * a0.y; num[2] += e0 * a1.x; num[3] += e0 * a1.y;
        num[4] += e0 * a2.x; num[5] += e0 * a2.y; num[6] += e0 * a3.x; num[7] += e0 * a3.y;
    }

    float inv = 1.f / (den + 1e-16f);
    float4 bb0 = *(const float4*)(b1 + off);
    float4 bb1 = *(const float4*)(b1 + off + 4);
    float bias[8] = {bb0.x, bb0.y, bb0.z, bb0.w, bb1.x, bb1.y, bb1.z, bb1.w};
    bf16 h8[8];
    #pragma unroll
    for (int j = 0; j < 8; j++)
        h8[j] = __float2bfloat16(fmaxf(num[j] * inv + bias[j], 0.f));
    *(uint4*)(g_hb + (size_t)d * 256 + off) = *(uint4*)h8;
}

// ---------------- layer 2 fused attention + pooling: 2-edge ILP ------------------
__global__ void gat2_kernel(const float* __restrict__ att, const int* __restrict__ batch,
                            const float* __restrict__ b2, const float* __restrict__ Wo, int N)
{
    int d = (blockIdx.x * blockDim.x + threadIdx.x) >> 5;
    if (d >= N) return;
    int lane = threadIdx.x & 31;
    int off = lane * 2;

    uint32_t xrr = *(const uint32_t*)(g_xr2b + (size_t)d * 64 + off);
    float2 xr = __bfloat1622float2(*(__nv_bfloat162*)&xrr);
    float2 aw = *(const float2*)(att + off);

    float num0 = 0.f, num1 = 0.f, den = 0.f;
    int lo = g_rowptr[d], hi = g_rowptr[d + 1];
    int cnt = hi - lo + 1;

    auto srcAt = [&](int i) { return (lo + i < hi) ? g_csr_src[lo + i] : d; };
    auto ld = [&](int i) { return *(const uint32_t*)(g_xl2b + (size_t)srcAt(i) * 64 + off); };

    uint32_t v0 = ld(0);
    uint32_t v1 = (cnt > 1) ? ld(1) : v0;

    int i = 0;
    for (; i + 1 < cnt; i += 2) {
        uint32_t c0 = v0, c1 = v1;
        if (i + 2 < cnt) v0 = ld(i + 2);
        if (i + 3 < cnt) v1 = ld(i + 3);
        float2 x0 = __bfloat1622float2(*(__nv_bfloat162*)&c0);
        float2 x1 = __bfloat1622float2(*(__nv_bfloat162*)&c1);
        float p0 = lrelu(x0.x + xr.x) * aw.x + lrelu(x0.y + xr.y) * aw.y;
        float p1 = lrelu(x1.x + xr.x) * aw.x + lrelu(x1.y + xr.y) * aw.y;
        p0 += __shfl_xor_sync(0xffffffffu, p0, 1);
        p1 += __shfl_xor_sync(0xffffffffu, p1, 1);
        p0 += __shfl_xor_sync(0xffffffffu, p0, 2);
        p1 += __shfl_xor_sync(0xffffffffu, p1, 2);
        p0 += __shfl_xor_sync(0xffffffffu, p0, 4);
        p1 += __shfl_xor_sync(0xffffffffu, p1, 4);
        p0 += __shfl_xor_sync(0xffffffffu, p0, 8);
        p1 += __shfl_xor_sync(0xffffffffu, p1, 8);
        p0 += __shfl_xor_sync(0xffffffffu, p0, 16);
        p1 += __shfl_xor_sync(0xffffffffu, p1, 16);
        float e0 = __expf(p0), e1 = __expf(p1);
        den += e0 + e1;
        num0 += e0 * x0.x + e1 * x1.x;
        num1 += e0 * x0.y + e1 * x1.y;
    }
    if (i < cnt) {
        float2 x0 = __bfloat1622float2(*(__nv_bfloat162*)&v0);
        float p0 = lrelu(x0.x + xr.x) * aw.x + lrelu(x0.y + xr.y) * aw.y;
        p0 += __shfl_xor_sync(0xffffffffu, p0, 1);
        p0 += __shfl_xor_sync(0xffffffffu, p0, 2);
        p0 += __shfl_xor_sync(0xffffffffu, p0, 4);
        p0 += __shfl_xor_sync(0xffffffffu, p0, 8);
        p0 += __shfl_xor_sync(0xffffffffu, p0, 16);
        float e0 = __expf(p0);
        den += e0;
        num0 += e0 * x0.x;
        num1 += e0 * x0.y;
    }

    float inv = 1.f / (den + 1e-16f);
    float2 bb = *(const float2*)(b2 + off);
    float2 wo = *(const float2*)(Wo + off);
    float y = (num0 * inv + bb.x) * wo.x + (num1 * inv + bb.y) * wo.y;
    y += __shfl_xor_sync(0xffffffffu, y, 1);
    y += __shfl_xor_sync(0xffffffffu, y, 2);
    y += __shfl_xor_sync(0xffffffffu, y, 4);
    y += __shfl_xor_sync(0xffffffffu, y, 8);
    y += __shfl_xor_sync(0xffffffffu, y, 16);
    if (lane == 0) atomicAdd(&g_acc[batch[d]], y);
}

__global__ void final_kernel(float* __restrict__ out, int G, const float* __restrict__ bo)
{
    int g = threadIdx.x;
    if (g < G) out[g] = g_acc[g] / fmaxf(g_cnt[g], 1.f) + bo[0];
}

// ---------------- launch ----------------
extern "C" void kernel_launch(void* const* d_in, const int* in_sizes, int n_in,
                              void* d_out, int out_size)
{
    const float* x    = (const float*)d_in[0];
    const int* ei     = (const int*)d_in[1];
    const int* bat    = (const int*)d_in[2];
    const float* Wl1 = (const float*)d_in[3];
    const float* Wr1 = (const float*)d_in[4];
    const float* att1 = (const float*)d_in[5];
    const float* b1  = (const float*)d_in[6];
    const float* Wl2 = (const float*)d_in[7];
    const float* Wr2 = (const float*)d_in[8];
    const float* att2 = (const float*)d_in[9];
    const float* b2  = (const float*)d_in[10];
    const float* Wo  = (const float*)d_in[11];
    const float* bo  = (const float*)d_in[12];

    int N = in_sizes[0] / 128;
    int E = in_sizes[1] / 2;
    int G = out_size;
    const int* src = ei;
    const int* dst = ei + E;
    int tiles = (N + 127) / 128;
    int nb = (N + 255) / 256;

    const int SM1 = 34816 + 2 * 34816;   // A + 2 half-B bufs = 104448 -> 2 CTAs/SM
    const int SM2 = 2 * 55296;           // 110592 -> 2 CTAs/SM
    cudaFuncSetAttribute(mma_gemm1, cudaFuncAttributeMaxDynamicSharedMemorySize, SM1);
    cudaFuncSetAttribute(mma_gemm2, cudaFuncAttributeMaxDynamicSharedMemorySize, SM2);

    init0<<<(N + 255) / 256, 256>>>(N);                             // 1
    prep_kernel<<<(N * 128 + 255) / 256, 256>>>(x, dst, bat, N, E); // 2
    split_wt_all<<<(98304 + 255) / 256, 256>>>(Wl1, Wr1, Wl2, Wr2); // 3
    mma_gemm1<<<tiles, 256, SM1>>>(N);                              // 4 <- profiled slot

    blocksum_kernel<<<nb, 256>>>(N);                                // 5
    scanb_kernel<<<1, 256>>>(nb);                                   // 6
    rowptr_kernel<<<nb, 256>>>(N, E);                               // 7
    scatter_kernel<<<(E + 255) / 256, 256>>>(src, dst, E);          // 8

    gat1_kernel<<<(N * 32 + 255) / 256, 256>>>(att1, b1, N);        // 9
    mma_gemm2<<<tiles, 256, SM2>>>(N);                              // 10
    gat2_kernel<<<(N * 32 + 255) / 256, 256>>>(att2, bat, b2, Wo, N); // 11
    final_kernel<<<1, 64>>>((float*)d_out, G, bo);                  // 12
}

// round 14
// speedup vs baseline: 4.0090x; 1.0509x over previous
#include <cuda_runtime.h>
#include <cuda_bf16.h>
#include <cstdint>

#define MAXN 50000
#define MAXE 800000
typedef __nv_bfloat16 bf16;

// ---------------- scratch (device globals; no allocation allowed) ----------------
__device__ __align__(16) bf16 g_xl1b[(size_t)MAXN * 256];
__device__ __align__(16) bf16 g_xr1b[(size_t)MAXN * 256];
__device__ __align__(16) bf16 g_xl2b[(size_t)MAXN * 64];
__device__ __align__(16) bf16 g_xr2b[(size_t)MAXN * 64];
__device__ __align__(16) bf16 g_xb[(size_t)MAXN * 128];
__device__ __align__(16) bf16 g_hb[(size_t)MAXN * 256];
// weight transposes [n][k], SPLIT bf16: w1l@0 (256x128), w1r@32768, w2l@65536 (64x256), w2r@81920
__device__ __align__(16) bf16 g_wthi[98304];
__device__ __align__(16) bf16 g_wtlo[98304];
__device__ int g_deg[MAXN];
__device__ int g_rowptr[MAXN + 1];
__device__ int g_woff[MAXN];
__device__ int g_csr_src[MAXE];
__device__ int g_bsum[256];
__device__ float g_acc[64];
__device__ float g_cnt[64];

__device__ __forceinline__ float lrelu(float v) { return v > 0.f ? v : 0.2f * v; }

__device__ __forceinline__ uint32_t smem_u32(const void* p) {
    uint32_t a;
    asm("{ .reg .u64 t; cvta.to.shared.u64 t, %1; cvt.u32.u64 %0, t; }" : "=r"(a) : "l"(p));
    return a;
}
__device__ __forceinline__ void cp16(uint32_t s, const void* g) {
    asm volatile("cp.async.cg.shared.global [%0], [%1], 16;" :: "r"(s), "l"(g));
}
#define CP_COMMIT() asm volatile("cp.async.commit_group;" ::: "memory")
#define LDSM4(r0, r1, r2, r3, addr) \
    asm volatile("ldmatrix.sync.aligned.m8n8.x4.shared.b16 {%0,%1,%2,%3}, [%4];" \
                 : "=r"(r0), "=r"(r1), "=r"(r2), "=r"(r3) : "r"(addr))

__device__ __forceinline__ void mma_bf16(float* d, const uint32_t* a, const uint32_t* b) {
    asm volatile("mma.sync.aligned.m16n8k16.row.col.f32.bf16.bf16.f32 "
                 "{%0,%1,%2,%3}, {%4,%5,%6,%7}, {%8,%9}, {%0,%1,%2,%3};"
                 : "+f"(d[0]), "+f"(d[1]), "+f"(d[2]), "+f"(d[3])
                 : "r"(a[0]), "r"(a[1]), "r"(a[2]), "r"(a[3]), "r"(b[0]), "r"(b[1]));
}

// ---------------- init ----------------
__global__ void init0(int N) {
    int i = blockIdx.x * blockDim.x + threadIdx.x;
    if (i < N) g_deg[i] = 0;
    if (i < 64) { g_acc[i] = 0.f; g_cnt[i] = 0.f; }
}

// ---------------- prep: x -> bf16 + degree histogram + graph counts --------------
__global__ void prep_kernel(const float* __restrict__ x, const int* __restrict__ dst,
                            const int* __restrict__ batch, int N, int E) {
    int i = blockIdx.x * blockDim.x + threadIdx.x;
    if (i < N * 128) g_xb[i] = __float2bfloat16(x[i]);
    if (i < E) atomicAdd(&g_deg[dst[i]], 1);
    if (i < N) atomicAdd(&g_cnt[batch[i]], 1.f);
}

// weight transposes, SPLIT bf16 hi/lo
__global__ void split_wt_all(const float* __restrict__ Wl1, const float* __restrict__ Wr1,
                             const float* __restrict__ Wl2, const float* __restrict__ Wr2) {
    int i = blockIdx.x * blockDim.x + threadIdx.x;
    if (i >= 98304) return;
    const float* W;
    int K, Nout, off, j;
    if (i < 32768)      { W = Wl1; K = 128; Nout = 256; off = 0;     j = i; }
    else if (i < 65536) { W = Wr1; K = 128; Nout = 256; off = 32768; j = i - 32768; }
    else if (i < 81920) { W = Wl2; K = 256; Nout = 64;  off = 65536; j = i - 65536; }
    else                { W = Wr2; K = 256; Nout = 64;  off = 81920; j = i - 81920; }
    int k = j / Nout, n = j % Nout;
    float v = W[j];
    bf16 h = __float2bfloat16(v);
    g_wthi[off + n * K + k] = h;
    g_wtlo[off + n * K + k] = __float2bfloat16(v - __bfloat162float(h));
}

// ---------------- layer-1 GEMM: A resident; 16 x (32-row B) chunks dbl-buffered;
//                  69.6 KB smem -> 3 CTAs/SM. C: x (Mx128) @ W (128x256), 2 weights.
__global__ void __launch_bounds__(256) mma_gemm1(int M)
{
    constexpr int SA = 136;
    constexpr int A_OFF = 0;          // 128*136*2 = 34816
    constexpr int BUF0 = 34816;       // two B bufs of 32 rows (hi@+0, lo@+8704)
    constexpr int BUFSZ = 17408;
    extern __shared__ char smem[];
    uint32_t sb = smem_u32(smem);
    int tid = threadIdx.x;
    int wid = tid >> 5, lane = tid & 31;
    int m0 = blockIdx.x * 128;

    // chunk c (0..15): weight z = c>>3, n-rows [ (c&7)*32, +32 )
    auto load_b = [&](int c, int b) {
        const bf16* WH = g_wthi + ((c >> 3) ? 32768 : 0) + (size_t)(c & 7) * 32 * 128;
        const bf16* WL = g_wtlo + ((c >> 3) ? 32768 : 0) + (size_t)(c & 7) * 32 * 128;
        uint32_t bbase = sb + BUF0 + b * BUFSZ;
        for (int t = tid; t < 32 * 16; t += 256) {
            int n = t >> 4, kcl = (t & 15) * 8;
            uint32_t ta = (uint32_t)(n * SA + kcl) * 2;
            cp16(bbase + ta, WH + (size_t)n * 128 + kcl);
            cp16(bbase + 8704 + ta, WL + (size_t)n * 128 + kcl);
        }
        CP_COMMIT();
    };

    // A load (once): 128 rows x 128 k, plain bf16
    for (int c = tid; c < 128 * 16; c += 256) {
        int row = c >> 4, kcl = (c & 15) * 8;
        int rg = min(m0 + row, M - 1);
        cp16(sb + A_OFF + (uint32_t)(row * SA + kcl) * 2, g_xb + (size_t)rg * 128 + kcl);
    }
    CP_COMMIT();
    load_b(0, 0);
    load_b(1, 1);

    int mwarp = (wid & 3) * 32;
    int nwarp = (wid >> 2) * 16;      // 2 n-warps x 16 cols over BN=32
    int sel = lane >> 3, r8 = lane & 7;
    uint32_t aoff[2];
    #pragma unroll
    for (int mt = 0; mt < 2; mt++)
        aoff[mt] = (uint32_t)(((mwarp + mt * 16 + (sel & 1) * 8 + r8) * SA + (sel >> 1) * 8) * 2);
    uint32_t boff = (uint32_t)(((nwarp + (sel >> 1) * 8 + r8) * SA + (sel & 1) * 8) * 2);

    int g4 = lane >> 2, tig = lane & 3;

    for (int c = 0; c < 16; c++) {
        if (c < 15) asm volatile("cp.async.wait_group 1;" ::: "memory");
        else        asm volatile("cp.async.wait_group 0;" ::: "memory");
        __syncthreads();

        uint32_t bb = sb + BUF0 + (c & 1) * BUFSZ;
        float d[2][2][4];
        #pragma unroll
        for (int mt = 0; mt < 2; mt++)
            #pragma unroll
            for (int nt = 0; nt < 2; nt++)
                #pragma unroll
                for (int j = 0; j < 4; j++) d[mt][nt][j] = 0.f;

        #pragma unroll
        for (int ks = 0; ks < 8; ks++) {
            uint32_t kb = ks * 32;
            uint32_t ah[2][4], bh[4], bl[4];
            #pragma unroll
            for (int mt = 0; mt < 2; mt++)
                LDSM4(ah[mt][0], ah[mt][1], ah[mt][2], ah[mt][3], sb + A_OFF + aoff[mt] + kb);
            LDSM4(bh[0], bh[1], bh[2], bh[3], bb + boff + kb);
            LDSM4(bl[0], bl[1], bl[2], bl[3], bb + 8704 + boff + kb);
            #pragma unroll
            for (int mt = 0; mt < 2; mt++)
                #pragma unroll
                for (int nt = 0; nt < 2; nt++) {
                    mma_bf16(d[mt][nt], ah[mt], &bh[nt * 2]);   // a * W_hi
                    mma_bf16(d[mt][nt], ah[mt], &bl[nt * 2]);   // a * W_lo
                }
        }
        __syncthreads();   // all warps done with buffer (c&1)

        if (c + 2 < 16) load_b(c + 2, c & 1);

        // epilogue: bf16 output, 32 columns of weight z at colb
        int z = c >> 3;
        int colb = (c & 7) * 32;
        bf16* Cb = z ? g_xr1b : g_xl1b;
        #pragma unroll
        for (int mt = 0; mt < 2; mt++) {
            int mrow = m0 + mwarp + mt * 16 + g4;
            #pragma unroll
            for (int nt = 0; nt < 2; nt++) {
                int col = colb + nwarp + nt * 8 + tig * 2;
                if (mrow < M) {
                    __nv_bfloat162 p = __float22bfloat162_rn(make_float2(d[mt][nt][0], d[mt][nt][1]));
                    *(uint32_t*)(Cb + (size_t)mrow * 256 + col) = *(uint32_t*)&p;
                }
                if (mrow + 8 < M) {
                    __nv_bfloat162 p = __float22bfloat162_rn(make_float2(d[mt][nt][2], d[mt][nt][3]));
                    *(uint32_t*)(Cb + (size_t)(mrow + 8) * 256 + col) = *(uint32_t*)&p;
                }
            }
        }
    }
}

// ---------------- CSR build: coalesced 3-stage scan ----------------
__global__ void blocksum_kernel(int N) {
    __shared__ int sh[256];
    int tid = threadIdx.x;
    int i = blockIdx.x * 256 + tid;
    sh[tid] = (i < N) ? g_deg[i] : 0;
    __syncthreads();
    for (int s = 128; s > 0; s >>= 1) {
        if (tid < s) sh[tid] += sh[tid + s];
        __syncthreads();
    }
    if (tid == 0) g_bsum[blockIdx.x] = sh[0];
}
__global__ void scanb_kernel(int nb) {
    __shared__ int sh[256];
    int tid = threadIdx.x;
    int v = (tid < nb) ? g_bsum[tid] : 0;
    sh[tid] = v;
    __syncthreads();
    for (int s = 1; s < 256; s <<= 1) {
        int t = (tid >= s) ? sh[tid - s] : 0;
        __syncthreads();
        sh[tid] += t;
        __syncthreads();
    }
    if (tid < nb) g_bsum[tid] = sh[tid] - v;
}
__global__ void rowptr_kernel(int N, int E) {
    __shared__ int sh[256];
    int tid = threadIdx.x;
    int i = blockIdx.x * 256 + tid;
    int v = (i < N) ? g_deg[i] : 0;
    sh[tid] = v;
    __syncthreads();
    for (int s = 1; s < 256; s <<= 1) {
        int t = (tid >= s) ? sh[tid - s] : 0;
        __syncthreads();
        sh[tid] += t;
        __syncthreads();
    }
    if (i < N) {
        int ex = g_bsum[blockIdx.x] + sh[tid] - v;
        g_rowptr[i] = ex;
        g_woff[i] = ex;
        if (i == N - 1) g_rowptr[N] = E;
    }
}
__global__ void scatter_kernel(const int* __restrict__ src, const int* __restrict__ dst, int E) {
    int e = blockIdx.x * blockDim.x + threadIdx.x;
    if (e >= E) return;
    int pos = atomicAdd(&g_woff[dst[e]], 1);
    g_csr_src[pos] = src[e];
}

// ---------------- layer-2 GEMM: both z accumulated, K pipelined in 4x64 chunks ---
__global__ void __launch_bounds__(256) mma_gemm2(int M)
{
    constexpr int SA = 72;
    constexpr int BBYT = 9216;
    constexpr int B_OFF = 18432;
    constexpr int BUFSZ = 55296;
    extern __shared__ char smem[];
    uint32_t sb = smem_u32(smem);
    int tid = threadIdx.x;
    int wid = tid >> 5, lane = tid & 31;
    int m0 = blockIdx.x * 128;

    auto load_chunk = [&](int kc, int b) {
        uint32_t base = sb + b * BUFSZ;
        for (int c = tid; c < 128 * 8; c += 256) {
            int row = c >> 3, kcl = (c & 7) * 8;
            int rg = min(m0 + row, M - 1);
            cp16(base + (uint32_t)(row * SA + kcl) * 2, g_hb + (size_t)rg * 256 + kc * 64 + kcl);
        }
        for (int c = tid; c < 2 * 64 * 8; c += 256) {
            int z = c >> 9, r = c & 511;
            int n = r >> 3, kcl = (r & 7) * 8;
            int woff = z ? 81920 : 65536;
            uint32_t ta = (uint32_t)(n * SA + kcl) * 2;
            cp16(base + B_OFF + z * 2 * BBYT + ta, g_wthi + woff + (size_t)n * 256 + kc * 64 + kcl);
            cp16(base + B_OFF + z * 2 * BBYT + BBYT + ta, g_wtlo + woff + (size_t)n * 256 + kc * 64 + kcl);
        }
        CP_COMMIT();
    };

    load_chunk(0, 0);

    int mwarp = (wid & 3) * 32;
    int nwarp = (wid >> 2) * 32;
    int sel = lane >> 3, r8 = lane & 7;
    uint32_t aoff[2], boff[2];
    #pragma unroll
    for (int mt = 0; mt < 2; mt++)
        aoff[mt] = (uint32_t)(((mwarp + mt * 16 + (sel & 1) * 8 + r8) * SA + (sel >> 1) * 8) * 2);
    #pragma unroll
    for (int bt = 0; bt < 2; bt++)
        boff[bt] = (uint32_t)(((nwarp + bt * 16 + (sel >> 1) * 8 + r8) * SA + (sel & 1) * 8) * 2);

    float d[2][2][4][4];
    #pragma unroll
    for (int z = 0; z < 2; z++)
        #pragma unroll
        for (int mt = 0; mt < 2; mt++)
            #pragma unroll
            for (int nt = 0; nt < 4; nt++)
                #pragma unroll
                for (int j = 0; j < 4; j++) d[z][mt][nt][j] = 0.f;

    for (int kc = 0; kc < 4; kc++) {
        if (kc < 3) {
            load_chunk(kc + 1, (kc + 1) & 1);
            asm volatile("cp.async.wait_group 1;" ::: "memory");
        } else {
            asm volatile("cp.async.wait_group 0;" ::: "memory");
        }
        __syncthreads();
        uint32_t base = sb + (kc & 1) * BUFSZ;

        #pragma unroll
        for (int ks = 0; ks < 4; ks++) {
            uint32_t kb = ks * 32;
            uint32_t ah[2][4], bh[2][8], bl[2][8];
            #pragma unroll
            for (int mt = 0; mt < 2; mt++)
                LDSM4(ah[mt][0], ah[mt][1], ah[mt][2], ah[mt][3], base + aoff[mt] + kb);
            #pragma unroll
            for (int z = 0; z < 2; z++) {
                uint32_t zb = base + B_OFF + z * 2 * BBYT;
                #pragma unroll
                for (int bt = 0; bt < 2; bt++) {
                    LDSM4(bh[z][bt*4], bh[z][bt*4+1], bh[z][bt*4+2], bh[z][bt*4+3], zb + boff[bt] + kb);
                    LDSM4(bl[z][bt*4], bl[z][bt*4+1], bl[z][bt*4+2], bl[z][bt*4+3], zb + BBYT + boff[bt] + kb);
                }
            }
            #pragma unroll
            for (int z = 0; z < 2; z++)
                #pragma unroll
                for (int mt = 0; mt < 2; mt++)
                    #pragma unroll
                    for (int nt = 0; nt < 4; nt++) {
                        mma_bf16(d[z][mt][nt], ah[mt], &bh[z][nt * 2]);
                        mma_bf16(d[z][mt][nt], ah[mt], &bl[z][nt * 2]);
                    }
        }
        __syncthreads();
    }

    int g4 = lane >> 2, tig = lane & 3;
    #pragma unroll
    for (int z = 0; z < 2; z++) {
        bf16* Cb = z ? g_xr2b : g_xl2b;
        #pragma unroll
        for (int mt = 0; mt < 2; mt++) {
            int mrow = m0 + mwarp + mt * 16 + g4;
            #pragma unroll
            for (int nt = 0; nt < 4; nt++) {
                int col = nwarp + nt * 8 + tig * 2;
                if (mrow < M) {
                    __nv_bfloat162 p = __float22bfloat162_rn(make_float2(d[z][mt][nt][0], d[z][mt][nt][1]));
                    *(uint32_t*)(Cb + (size_t)mrow * 64 + col) = *(uint32_t*)&p;
                }
                if (mrow + 8 < M) {
                    __nv_bfloat162 p = __float22bfloat162_rn(make_float2(d[z][mt][nt][2], d[z][mt][nt][3]));
                    *(uint32_t*)(Cb + (size_t)(mrow + 8) * 64 + col) = *(uint32_t*)&p;
                }
            }
        }
    }
}

// ---------------- layer 1 fused attention: one warp per dst, 4-edge ILP ----------
__global__ void gat1_kernel(const float* __restrict__ att, const float* __restrict__ b1, int N)
{
    int d = (blockIdx.x * blockDim.x + threadIdx.x) >> 5;
    if (d >= N) return;
    int lane = threadIdx.x & 31;
    int off = lane * 8;

    uint4 xrr = *(const uint4*)(g_xr1b + (size_t)d * 256 + off);
    float2 xr0 = __bfloat1622float2(*(__nv_bfloat162*)&xrr.x);
    float2 xr1 = __bfloat1622float2(*(__nv_bfloat162*)&xrr.y);
    float2 xr2 = __bfloat1622float2(*(__nv_bfloat162*)&xrr.z);
    float2 xr3 = __bfloat1622float2(*(__nv_bfloat162*)&xrr.w);
    float4 aw0 = *(const float4*)(att + off);
    float4 aw1 = *(const float4*)(att + off + 4);

    float num[8];
    #pragma unroll
    for (int j = 0; j < 8; j++) num[j] = 0.f;
    float den = 0.f;

    int lo = g_rowptr[d], hi = g_rowptr[d + 1];
    int cnt = hi - lo + 1;   // + self loop (last slot)

    auto srcAt = [&](int i) { return (lo + i < hi) ? g_csr_src[lo + i] : d; };
    auto ld = [&](int i) { return *(const uint4*)(g_xl1b + (size_t)srcAt(i) * 256 + off); };

    // score of one edge (temporaries die inside)
    auto scoreOf = [&](uint4 cc) {
        float2 f0 = __bfloat1622float2(*(__nv_bfloat162*)&cc.x);
        float2 f1 = __bfloat1622float2(*(__nv_bfloat162*)&cc.y);
        float2 f2 = __bfloat1622float2(*(__nv_bfloat162*)&cc.z);
        float2 f3 = __bfloat1622float2(*(__nv_bfloat162*)&cc.w);
        return lrelu(f0.x + xr0.x) * aw0.x + lrelu(f0.y + xr0.y) * aw0.y
             + lrelu(f1.x + xr1.x) * aw0.z + lrelu(f1.y + xr1.y) * aw0.w
             + lrelu(f2.x + xr2.x) * aw1.x + lrelu(f2.y + xr2.y) * aw1.y
             + lrelu(f3.x + xr3.x) * aw1.z + lrelu(f3.y + xr3.y) * aw1.w;
    };
    // accumulate one edge with weight e (re-convert; keeps live regs low)
    auto accum = [&](uint4 cc, float e) {
        float2 f0 = __bfloat1622float2(*(__nv_bfloat162*)&cc.x);
        float2 f1 = __bfloat1622float2(*(__nv_bfloat162*)&cc.y);
        float2 f2 = __bfloat1622float2(*(__nv_bfloat162*)&cc.z);
        float2 f3 = __bfloat1622float2(*(__nv_bfloat162*)&cc.w);
        num[0] += e * f0.x; num[1] += e * f0.y; num[2] += e * f1.x; num[3] += e * f1.y;
        num[4] += e * f2.x; num[5] += e * f2.y; num[6] += e * f3.x; num[7] += e * f3.y;
    };

    uint4 v0 = ld(0), v1 = ld(1), v2 = ld(2), v3 = ld(3);   // OOB indices clamp to self (safe)

    int i = 0;
    for (; i + 3 < cnt; i += 4) {
        uint4 c0 = v0, c1 = v1, c2 = v2, c3 = v3;
        v0 = ld(i + 4); v1 = ld(i + 5); v2 = ld(i + 6); v3 = ld(i + 7);
        float p0 = scoreOf(c0), p1 = scoreOf(c1), p2 = scoreOf(c2), p3 = scoreOf(c3);
        p0 += __shfl_xor_sync(0xffffffffu, p0, 1);
        p1 += __shfl_xor_sync(0xffffffffu, p1, 1);
        p2 += __shfl_xor_sync(0xffffffffu, p2, 1);
        p3 += __shfl_xor_sync(0xffffffffu, p3, 1);
        p0 += __shfl_xor_sync(0xffffffffu, p0, 2);
        p1 += __shfl_xor_sync(0xffffffffu, p1, 2);
        p2 += __shfl_xor_sync(0xffffffffu, p2, 2);
        p3 += __shfl_xor_sync(0xffffffffu, p3, 2);
        p0 += __shfl_xor_sync(0xffffffffu, p0, 4);
        p1 += __shfl_xor_sync(0xffffffffu, p1, 4);
        p2 += __shfl_xor_sync(0xffffffffu, p2, 4);
        p3 += __shfl_xor_sync(0xffffffffu, p3, 4);
        float e0 = __expf(p0), e1 = __expf(p1), e2 = __expf(p2), e3 = __expf(p3);
        den += (e0 + e1) + (e2 + e3);
        accum(c0, e0); accum(c1, e1); accum(c2, e2); accum(c3, e3);
    }
    // tail: 0..3 edges remain, held in v0..v3
    for (int t = 0; i < cnt; i++, t++) {
        uint4 c0 = (t == 0) ? v0 : (t == 1) ? v1 : (t == 2) ? v2 : v3;
        float p0 = scoreOf(c0);
        p0 += __shfl_xor_sync(0xffffffffu, p0, 1);
        p0 += __shfl_xor_sync(0xffffffffu, p0, 2);
        p0 += __shfl_xor_sync(0xffffffffu, p0, 4);
        float e0 = __expf(p0);
        den += e0;
        accum(c0, e0);
    }

    float inv = 1.f / (den + 1e-16f);
    float4 bb0 = *(const float4*)(b1 + off);
    float4 bb1 = *(const float4*)(b1 + off + 4);
    float bias[8] = {bb0.x, bb0.y, bb0.z, bb0.w, bb1.x, bb1.y, bb1.z, bb1.w};
    bf16 h8[8];
    #pragma unroll
    for (int j = 0; j < 8; j++)
        h8[j] = __float2bfloat16(fmaxf(num[j] * inv + bias[j], 0.f));
    *(uint4*)(g_hb + (size_t)d * 256 + off) = *(uint4*)h8;
}

// ---------------- layer 2 fused attention + pooling: 4-edge ILP ------------------
__global__ void gat2_kernel(const float* __restrict__ att, const int* __restrict__ batch,
                            const float* __restrict__ b2, const float* __restrict__ Wo, int N)
{
    int d = (blockIdx.x * blockDim.x + threadIdx.x) >> 5;
    if (d >= N) return;
    int lane = threadIdx.x & 31;
    int off = lane * 2;

    uint32_t xrr = *(const uint32_t*)(g_xr2b + (size_t)d * 64 + off);
    float2 xr = __bfloat1622float2(*(__nv_bfloat162*)&xrr);
    float2 aw = *(const float2*)(att + off);

    float num0 = 0.f, num1 = 0.f, den = 0.f;
    int lo = g_rowptr[d], hi = g_rowptr[d + 1];
    int cnt = hi - lo + 1;

    auto srcAt = [&](int i) { return (lo + i < hi) ? g_csr_src[lo + i] : d; };
    auto ld = [&](int i) { return *(const uint32_t*)(g_xl2b + (size_t)srcAt(i) * 64 + off); };
    auto scoreOf = [&](uint32_t cc) {
        float2 xv = __bfloat1622float2(*(__nv_bfloat162*)&cc);
        return lrelu(xv.x + xr.x) * aw.x + lrelu(xv.y + xr.y) * aw.y;
    };
    auto accum = [&](uint32_t cc, float e) {
        float2 xv = __bfloat1622float2(*(__nv_bfloat162*)&cc);
        num0 += e * xv.x;
        num1 += e * xv.y;
    };

    uint32_t v0 = ld(0), v1 = ld(1), v2 = ld(2), v3 = ld(3);

    int i = 0;
    for (; i + 3 < cnt; i += 4) {
        uint32_t c0 = v0, c1 = v1, c2 = v2, c3 = v3;
        v0 = ld(i + 4); v1 = ld(i + 5); v2 = ld(i + 6); v3 = ld(i + 7);
        float p0 = scoreOf(c0), p1 = scoreOf(c1), p2 = scoreOf(c2), p3 = scoreOf(c3);
        #pragma unroll
        for (int s = 1; s < 32; s <<= 1) {
            p0 += __shfl_xor_sync(0xffffffffu, p0, s);
            p1 += __shfl_xor_sync(0xffffffffu, p1, s);
            p2 += __shfl_xor_sync(0xffffffffu, p2, s);
            p3 += __shfl_xor_sync(0xffffffffu, p3, s);
        }
        float e0 = __expf(p0), e1 = __expf(p1), e2 = __expf(p2), e3 = __expf(p3);
        den += (e0 + e1) + (e2 + e3);
        accum(c0, e0); accum(c1, e1); accum(c2, e2); accum(c3, e3);
    }
    for (int t = 0; i < cnt; i++, t++) {
        uint32_t c0 = (t == 0) ? v0 : (t == 1) ? v1 : (t == 2) ? v2 : v3;
        float p0 = scoreOf(c0);
        #pragma unroll
        for (int s = 1; s < 32; s <<= 1)
            p0 += __shfl_xor_sync(0xffffffffu, p0, s);
        float e0 = __expf(p0);
        den += e0;
        accum(c0, e0);
    }

    float inv = 1.f / (den + 1e-16f);
    float2 bb = *(const float2*)(b2 + off);
    float2 wo = *(const float2*)(Wo + off);
    float y = (num0 * inv + bb.x) * wo.x + (num1 * inv + bb.y) * wo.y;
    y += __shfl_xor_sync(0xffffffffu, y, 1);
    y += __shfl_xor_sync(0xffffffffu, y, 2);
    y += __shfl_xor_sync(0xffffffffu, y, 4);
    y += __shfl_xor_sync(0xffffffffu, y, 8);
    y += __shfl_xor_sync(0xffffffffu, y, 16);
    if (lane == 0) atomicAdd(&g_acc[batch[d]], y);
}

__global__ void final_kernel(float* __restrict__ out, int G, const float* __restrict__ bo)
{
    int g = threadIdx.x;
    if (g < G) out[g] = g_acc[g] / fmaxf(g_cnt[g], 1.f) + bo[0];
}

// ---------------- launch ----------------
extern "C" void kernel_launch(void* const* d_in, const int* in_sizes, int n_in,
                              void* d_out, int out_size)
{
    const float* x    = (const float*)d_in[0];
    const int* ei     = (const int*)d_in[1];
    const int* bat    = (const int*)d_in[2];
    const float* Wl1 = (const float*)d_in[3];
    const float* Wr1 = (const float*)d_in[4];
    const float* att1 = (const float*)d_in[5];
    const float* b1  = (const float*)d_in[6];
    const float* Wl2 = (const float*)d_in[7];
    const float* Wr2 = (const float*)d_in[8];
    const float* att2 = (const float*)d_in[9];
    const float* b2  = (const float*)d_in[10];
    const float* Wo  = (const float*)d_in[11];
    const float* bo  = (const float*)d_in[12];

    int N = in_sizes[0] / 128;
    int E = in_sizes[1] / 2;
    int G = out_size;
    const int* src = ei;
    const int* dst = ei + E;
    int tiles = (N + 127) / 128;
    int nb = (N + 255) / 256;

    const int SM1 = 34816 + 2 * 17408;   // A + 2 quarter-B bufs = 69632 -> 3 CTAs/SM
    const int SM2 = 2 * 55296;           // 110592 -> 2 CTAs/SM
    cudaFuncSetAttribute(mma_gemm1, cudaFuncAttributeMaxDynamicSharedMemorySize, SM1);
    cudaFuncSetAttribute(mma_gemm2, cudaFuncAttributeMaxDynamicSharedMemorySize, SM2);

    init0<<<(N + 255) / 256, 256>>>(N);                             // 1
    prep_kernel<<<(N * 128 + 255) / 256, 256>>>(x, dst, bat, N, E); // 2
    split_wt_all<<<(98304 + 255) / 256, 256>>>(Wl1, Wr1, Wl2, Wr2); // 3
    mma_gemm1<<<tiles, 256, SM1>>>(N);                              // 4 <- profiled slot

    blocksum_kernel<<<nb, 256>>>(N);                                // 5
    scanb_kernel<<<1, 256>>>(nb);                                   // 6
    rowptr_kernel<<<nb, 256>>>(N, E);                               // 7
    scatter_kernel<<<(E + 255) / 256, 256>>>(src, dst, E);          // 8

    gat1_kernel<<<(N * 32 + 255) / 256, 256>>>(att1, b1, N);        // 9
    mma_gemm2<<<tiles, 256, SM2>>>(N);                              // 10
    gat2_kernel<<<(N * 32 + 255) / 256, 256>>>(att2, bat, b2, Wo, N); // 11
    final_kernel<<<1, 64>>>((float*)d_out, G, bo);                  // 12
}

// round 15
// speedup vs baseline: 4.0270x; 1.0045x over previous
#include <cuda_runtime.h>
#include <cuda_bf16.h>
#include <cstdint>

#define MAXN 50000
#define MAXE 800000
typedef __nv_bfloat16 bf16;

// ---------------- scratch (device globals; no allocation allowed) ----------------
__device__ __align__(16) bf16 g_xl1b[(size_t)MAXN * 256];
__device__ __align__(16) bf16 g_xr1b[(size_t)MAXN * 256];
__device__ __align__(16) bf16 g_xl2b[(size_t)MAXN * 64];
__device__ __align__(16) bf16 g_xr2b[(size_t)MAXN * 64];
__device__ __align__(16) bf16 g_xb[(size_t)MAXN * 128];
__device__ __align__(16) bf16 g_hb[(size_t)MAXN * 256];
// weight transposes [n][k], SPLIT bf16: w1l@0 (256x128), w1r@32768, w2l@65536 (64x256), w2r@81920
__device__ __align__(16) bf16 g_wthi[98304];
__device__ __align__(16) bf16 g_wtlo[98304];
__device__ int g_deg[MAXN];
__device__ int g_rowptr[MAXN + 1];
__device__ int g_woff[MAXN];
__device__ int g_csr_src[MAXE];
__device__ int g_bsum[256];
__device__ float g_acc[64];
__device__ float g_cnt[64];

__device__ __forceinline__ float lrelu(float v) { return v > 0.f ? v : 0.2f * v; }

__device__ __forceinline__ uint32_t smem_u32(const void* p) {
    uint32_t a;
    asm("{ .reg .u64 t; cvta.to.shared.u64 t, %1; cvt.u32.u64 %0, t; }" : "=r"(a) : "l"(p));
    return a;
}
__device__ __forceinline__ void cp16(uint32_t s, const void* g) {
    asm volatile("cp.async.cg.shared.global [%0], [%1], 16;" :: "r"(s), "l"(g));
}
#define CP_COMMIT() asm volatile("cp.async.commit_group;" ::: "memory")
#define LDSM4(r0, r1, r2, r3, addr) \
    asm volatile("ldmatrix.sync.aligned.m8n8.x4.shared.b16 {%0,%1,%2,%3}, [%4];" \
                 : "=r"(r0), "=r"(r1), "=r"(r2), "=r"(r3) : "r"(addr))

__device__ __forceinline__ void mma_bf16(float* d, const uint32_t* a, const uint32_t* b) {
    asm volatile("mma.sync.aligned.m16n8k16.row.col.f32.bf16.bf16.f32 "
                 "{%0,%1,%2,%3}, {%4,%5,%6,%7}, {%8,%9}, {%0,%1,%2,%3};"
                 : "+f"(d[0]), "+f"(d[1]), "+f"(d[2]), "+f"(d[3])
                 : "r"(a[0]), "r"(a[1]), "r"(a[2]), "r"(a[3]), "r"(b[0]), "r"(b[1]));
}

// ---------------- init ----------------
__global__ void init0(int N) {
    int i = blockIdx.x * blockDim.x + threadIdx.x;
    if (i < N) g_deg[i] = 0;
    if (i < 64) { g_acc[i] = 0.f; g_cnt[i] = 0.f; }
}

// ---------------- prep: x -> bf16 + degree histogram + graph counts --------------
__global__ void prep_kernel(const float* __restrict__ x, const int* __restrict__ dst,
                            const int* __restrict__ batch, int N, int E) {
    int i = blockIdx.x * blockDim.x + threadIdx.x;
    if (i < N * 128) g_xb[i] = __float2bfloat16(x[i]);
    if (i < E) atomicAdd(&g_deg[dst[i]], 1);
    if (i < N) atomicAdd(&g_cnt[batch[i]], 1.f);
}

// weight transposes, SPLIT bf16 hi/lo
__global__ void split_wt_all(const float* __restrict__ Wl1, const float* __restrict__ Wr1,
                             const float* __restrict__ Wl2, const float* __restrict__ Wr2) {
    int i = blockIdx.x * blockDim.x + threadIdx.x;
    if (i >= 98304) return;
    const float* W;
    int K, Nout, off, j;
    if (i < 32768)      { W = Wl1; K = 128; Nout = 256; off = 0;     j = i; }
    else if (i < 65536) { W = Wr1; K = 128; Nout = 256; off = 32768; j = i - 32768; }
    else if (i < 81920) { W = Wl2; K = 256; Nout = 64;  off = 65536; j = i - 65536; }
    else                { W = Wr2; K = 256; Nout = 64;  off = 81920; j = i - 81920; }
    int k = j / Nout, n = j % Nout;
    float v = W[j];
    bf16 h = __float2bfloat16(v);
    g_wthi[off + n * K + k] = h;
    g_wtlo[off + n * K + k] = __float2bfloat16(v - __bfloat162float(h));
}

// ---------------- layer-1 GEMM: A resident; 8 x (64-row B) chunks double-buffered;
//                  104 KB smem -> 2 CTAs/SM (best measured config, R13).
__global__ void __launch_bounds__(256) mma_gemm1(int M)
{
    constexpr int SA = 136;
    constexpr int A_OFF = 0;          // 128*136*2 = 34816
    constexpr int BUF0 = 34816;       // two B bufs of 64 rows (hi@+0, lo@+17408)
    constexpr int BUFSZ = 34816;
    extern __shared__ char smem[];
    uint32_t sb = smem_u32(smem);
    int tid = threadIdx.x;
    int wid = tid >> 5, lane = tid & 31;
    int m0 = blockIdx.x * 128;

    auto load_b = [&](int c, int b) {
        const bf16* WH = g_wthi + ((c >> 2) ? 32768 : 0) + (size_t)(c & 3) * 64 * 128;
        const bf16* WL = g_wtlo + ((c >> 2) ? 32768 : 0) + (size_t)(c & 3) * 64 * 128;
        uint32_t bbase = sb + BUF0 + b * BUFSZ;
        for (int t = tid; t < 64 * 16; t += 256) {
            int n = t >> 4, kcl = (t & 15) * 8;
            uint32_t ta = (uint32_t)(n * SA + kcl) * 2;
            cp16(bbase + ta, WH + (size_t)n * 128 + kcl);
            cp16(bbase + 17408 + ta, WL + (size_t)n * 128 + kcl);
        }
        CP_COMMIT();
    };

    for (int c = tid; c < 128 * 16; c += 256) {
        int row = c >> 4, kcl = (c & 15) * 8;
        int rg = min(m0 + row, M - 1);
        cp16(sb + A_OFF + (uint32_t)(row * SA + kcl) * 2, g_xb + (size_t)rg * 128 + kcl);
    }
    CP_COMMIT();
    load_b(0, 0);
    load_b(1, 1);

    int mwarp = (wid & 3) * 32;
    int nwarp = (wid >> 2) * 32;      // 2 n-warps x 32 cols over BN=64
    int sel = lane >> 3, r8 = lane & 7;
    uint32_t aoff[2], boff[2];
    #pragma unroll
    for (int mt = 0; mt < 2; mt++)
        aoff[mt] = (uint32_t)(((mwarp + mt * 16 + (sel & 1) * 8 + r8) * SA + (sel >> 1) * 8) * 2);
    #pragma unroll
    for (int bt = 0; bt < 2; bt++)
        boff[bt] = (uint32_t)(((nwarp + bt * 16 + (sel >> 1) * 8 + r8) * SA + (sel & 1) * 8) * 2);

    int g4 = lane >> 2, tig = lane & 3;

    for (int c = 0; c < 8; c++) {
        if (c < 7) asm volatile("cp.async.wait_group 1;" ::: "memory");
        else       asm volatile("cp.async.wait_group 0;" ::: "memory");
        __syncthreads();

        uint32_t bb = sb + BUF0 + (c & 1) * BUFSZ;
        float d[2][4][4];
        #pragma unroll
        for (int mt = 0; mt < 2; mt++)
            #pragma unroll
            for (int nt = 0; nt < 4; nt++)
                #pragma unroll
                for (int j = 0; j < 4; j++) d[mt][nt][j] = 0.f;

        #pragma unroll
        for (int ks = 0; ks < 8; ks++) {
            uint32_t kb = ks * 32;
            uint32_t ah[2][4], bh[8], bl[8];
            #pragma unroll
            for (int mt = 0; mt < 2; mt++)
                LDSM4(ah[mt][0], ah[mt][1], ah[mt][2], ah[mt][3], sb + A_OFF + aoff[mt] + kb);
            #pragma unroll
            for (int bt = 0; bt < 2; bt++) {
                LDSM4(bh[bt*4], bh[bt*4+1], bh[bt*4+2], bh[bt*4+3], bb + boff[bt] + kb);
                LDSM4(bl[bt*4], bl[bt*4+1], bl[bt*4+2], bl[bt*4+3], bb + 17408 + boff[bt] + kb);
            }
            #pragma unroll
            for (int mt = 0; mt < 2; mt++)
                #pragma unroll
                for (int nt = 0; nt < 4; nt++) {
                    mma_bf16(d[mt][nt], ah[mt], &bh[nt * 2]);
                    mma_bf16(d[mt][nt], ah[mt], &bl[nt * 2]);
                }
        }
        __syncthreads();

        if (c + 2 < 8) load_b(c + 2, c & 1);

        int z = c >> 2;
        int colb = (c & 3) * 64;
        bf16* Cb = z ? g_xr1b : g_xl1b;
        #pragma unroll
        for (int mt = 0; mt < 2; mt++) {
            int mrow = m0 + mwarp + mt * 16 + g4;
            #pragma unroll
            for (int nt = 0; nt < 4; nt++) {
                int col = colb + nwarp + nt * 8 + tig * 2;
                if (mrow < M) {
                    __nv_bfloat162 p = __float22bfloat162_rn(make_float2(d[mt][nt][0], d[mt][nt][1]));
                    *(uint32_t*)(Cb + (size_t)mrow * 256 + col) = *(uint32_t*)&p;
                }
                if (mrow + 8 < M) {
                    __nv_bfloat162 p = __float22bfloat162_rn(make_float2(d[mt][nt][2], d[mt][nt][3]));
                    *(uint32_t*)(Cb + (size_t)(mrow + 8) * 256 + col) = *(uint32_t*)&p;
                }
            }
        }
    }
}

// ---------------- CSR build: coalesced 3-stage scan ----------------
__global__ void blocksum_kernel(int N) {
    __shared__ int sh[256];
    int tid = threadIdx.x;
    int i = blockIdx.x * 256 + tid;
    sh[tid] = (i < N) ? g_deg[i] : 0;
    __syncthreads();
    for (int s = 128; s > 0; s >>= 1) {
        if (tid < s) sh[tid] += sh[tid + s];
        __syncthreads();
    }
    if (tid == 0) g_bsum[blockIdx.x] = sh[0];
}
__global__ void scanb_kernel(int nb) {
    __shared__ int sh[256];
    int tid = threadIdx.x;
    int v = (tid < nb) ? g_bsum[tid] : 0;
    sh[tid] = v;
    __syncthreads();
    for (int s = 1; s < 256; s <<= 1) {
        int t = (tid >= s) ? sh[tid - s] : 0;
        __syncthreads();
        sh[tid] += t;
        __syncthreads();
    }
    if (tid < nb) g_bsum[tid] = sh[tid] - v;
}
__global__ void rowptr_kernel(int N, int E) {
    __shared__ int sh[256];
    int tid = threadIdx.x;
    int i = blockIdx.x * 256 + tid;
    int v = (i < N) ? g_deg[i] : 0;
    sh[tid] = v;
    __syncthreads();
    for (int s = 1; s < 256; s <<= 1) {
        int t = (tid >= s) ? sh[tid - s] : 0;
        __syncthreads();
        sh[tid] += t;
        __syncthreads();
    }
    if (i < N) {
        int ex = g_bsum[blockIdx.x] + sh[tid] - v;
        g_rowptr[i] = ex;
        g_woff[i] = ex;
        if (i == N - 1) g_rowptr[N] = E;
    }
}
__global__ void scatter_kernel(const int* __restrict__ src, const int* __restrict__ dst, int E) {
    int e = blockIdx.x * blockDim.x + threadIdx.x;
    if (e >= E) return;
    int pos = atomicAdd(&g_woff[dst[e]], 1);
    g_csr_src[pos] = src[e];
}

// ---------------- layer-2 GEMM: both z accumulated, K pipelined in 4x64 chunks ---
__global__ void __launch_bounds__(256) mma_gemm2(int M)
{
    constexpr int SA = 72;
    constexpr int BBYT = 9216;
    constexpr int B_OFF = 18432;
    constexpr int BUFSZ = 55296;
    extern __shared__ char smem[];
    uint32_t sb = smem_u32(smem);
    int tid = threadIdx.x;
    int wid = tid >> 5, lane = tid & 31;
    int m0 = blockIdx.x * 128;

    auto load_chunk = [&](int kc, int b) {
        uint32_t base = sb + b * BUFSZ;
        for (int c = tid; c < 128 * 8; c += 256) {
            int row = c >> 3, kcl = (c & 7) * 8;
            int rg = min(m0 + row, M - 1);
            cp16(base + (uint32_t)(row * SA + kcl) * 2, g_hb + (size_t)rg * 256 + kc * 64 + kcl);
        }
        for (int c = tid; c < 2 * 64 * 8; c += 256) {
            int z = c >> 9, r = c & 511;
            int n = r >> 3, kcl = (r & 7) * 8;
            int woff = z ? 81920 : 65536;
            uint32_t ta = (uint32_t)(n * SA + kcl) * 2;
            cp16(base + B_OFF + z * 2 * BBYT + ta, g_wthi + woff + (size_t)n * 256 + kc * 64 + kcl);
            cp16(base + B_OFF + z * 2 * BBYT + BBYT + ta, g_wtlo + woff + (size_t)n * 256 + kc * 64 + kcl);
        }
        CP_COMMIT();
    };

    load_chunk(0, 0);

    int mwarp = (wid & 3) * 32;
    int nwarp = (wid >> 2) * 32;
    int sel = lane >> 3, r8 = lane & 7;
    uint32_t aoff[2], boff[2];
    #pragma unroll
    for (int mt = 0; mt < 2; mt++)
        aoff[mt] = (uint32_t)(((mwarp + mt * 16 + (sel & 1) * 8 + r8) * SA + (sel >> 1) * 8) * 2);
    #pragma unroll
    for (int bt = 0; bt < 2; bt++)
        boff[bt] = (uint32_t)(((nwarp + bt * 16 + (sel >> 1) * 8 + r8) * SA + (sel & 1) * 8) * 2);

    float d[2][2][4][4];
    #pragma unroll
    for (int z = 0; z < 2; z++)
        #pragma unroll
        for (int mt = 0; mt < 2; mt++)
            #pragma unroll
            for (int nt = 0; nt < 4; nt++)
                #pragma unroll
                for (int j = 0; j < 4; j++) d[z][mt][nt][j] = 0.f;

    for (int kc = 0; kc < 4; kc++) {
        if (kc < 3) {
            load_chunk(kc + 1, (kc + 1) & 1);
            asm volatile("cp.async.wait_group 1;" ::: "memory");
        } else {
            asm volatile("cp.async.wait_group 0;" ::: "memory");
        }
        __syncthreads();
        uint32_t base = sb + (kc & 1) * BUFSZ;

        #pragma unroll
        for (int ks = 0; ks < 4; ks++) {
            uint32_t kb = ks * 32;
            uint32_t ah[2][4], bh[2][8], bl[2][8];
            #pragma unroll
            for (int mt = 0; mt < 2; mt++)
                LDSM4(ah[mt][0], ah[mt][1], ah[mt][2], ah[mt][3], base + aoff[mt] + kb);
            #pragma unroll
            for (int z = 0; z < 2; z++) {
                uint32_t zb = base + B_OFF + z * 2 * BBYT;
                #pragma unroll
                for (int bt = 0; bt < 2; bt++) {
                    LDSM4(bh[z][bt*4], bh[z][bt*4+1], bh[z][bt*4+2], bh[z][bt*4+3], zb + boff[bt] + kb);
                    LDSM4(bl[z][bt*4], bl[z][bt*4+1], bl[z][bt*4+2], bl[z][bt*4+3], zb + BBYT + boff[bt] + kb);
                }
            }
            #pragma unroll
            for (int z = 0; z < 2; z++)
                #pragma unroll
                for (int mt = 0; mt < 2; mt++)
                    #pragma unroll
                    for (int nt = 0; nt < 4; nt++) {
                        mma_bf16(d[z][mt][nt], ah[mt], &bh[z][nt * 2]);
                        mma_bf16(d[z][mt][nt], ah[mt], &bl[z][nt * 2]);
                    }
        }
        __syncthreads();
    }

    int g4 = lane >> 2, tig = lane & 3;
    #pragma unroll
    for (int z = 0; z < 2; z++) {
        bf16* Cb = z ? g_xr2b : g_xl2b;
        #pragma unroll
        for (int mt = 0; mt < 2; mt++) {
            int mrow = m0 + mwarp + mt * 16 + g4;
            #pragma unroll
            for (int nt = 0; nt < 4; nt++) {
                int col = nwarp + nt * 8 + tig * 2;
                if (mrow < M) {
                    __nv_bfloat162 p = __float22bfloat162_rn(make_float2(d[z][mt][nt][0], d[z][mt][nt][1]));
                    *(uint32_t*)(Cb + (size_t)mrow * 64 + col) = *(uint32_t*)&p;
                }
                if (mrow + 8 < M) {
                    __nv_bfloat162 p = __float22bfloat162_rn(make_float2(d[z][mt][nt][2], d[z][mt][nt][3]));
                    *(uint32_t*)(Cb + (size_t)(mrow + 8) * 64 + col) = *(uint32_t*)&p;
                }
            }
        }
    }
}

// ---------------- layer 1 fused attention: one warp per dst, 4-edge ILP ----------
__global__ void gat1_kernel(const float* __restrict__ att, const float* __restrict__ b1, int N)
{
    int d = (blockIdx.x * blockDim.x + threadIdx.x) >> 5;
    if (d >= N) return;
    int lane = threadIdx.x & 31;
    int off = lane * 8;

    uint4 xrr = *(const uint4*)(g_xr1b + (size_t)d * 256 + off);
    float2 xr0 = __bfloat1622float2(*(__nv_bfloat162*)&xrr.x);
    float2 xr1 = __bfloat1622float2(*(__nv_bfloat162*)&xrr.y);
    float2 xr2 = __bfloat1622float2(*(__nv_bfloat162*)&xrr.z);
    float2 xr3 = __bfloat1622float2(*(__nv_bfloat162*)&xrr.w);
    float4 aw0 = *(const float4*)(att + off);
    float4 aw1 = *(const float4*)(att + off + 4);

    float num[8];
    #pragma unroll
    for (int j = 0; j < 8; j++) num[j] = 0.f;
    float den = 0.f;

    int lo = g_rowptr[d], hi = g_rowptr[d + 1];
    int cnt = hi - lo + 1;

    auto srcAt = [&](int i) { return (lo + i < hi) ? g_csr_src[lo + i] : d; };
    auto ld = [&](int i) { return *(const uint4*)(g_xl1b + (size_t)srcAt(i) * 256 + off); };
    auto scoreOf = [&](uint4 cc) {
        float2 f0 = __bfloat1622float2(*(__nv_bfloat162*)&cc.x);
        float2 f1 = __bfloat1622float2(*(__nv_bfloat162*)&cc.y);
        float2 f2 = __bfloat1622float2(*(__nv_bfloat162*)&cc.z);
        float2 f3 = __bfloat1622float2(*(__nv_bfloat162*)&cc.w);
        return lrelu(f0.x + xr0.x) * aw0.x + lrelu(f0.y + xr0.y) * aw0.y
             + lrelu(f1.x + xr1.x) * aw0.z + lrelu(f1.y + xr1.y) * aw0.w
             + lrelu(f2.x + xr2.x) * aw1.x + lrelu(f2.y + xr2.y) * aw1.y
             + lrelu(f3.x + xr3.x) * aw1.z + lrelu(f3.y + xr3.y) * aw1.w;
    };
    auto accum = [&](uint4 cc, float e) {
        float2 f0 = __bfloat1622float2(*(__nv_bfloat162*)&cc.x);
        float2 f1 = __bfloat1622float2(*(__nv_bfloat162*)&cc.y);
        float2 f2 = __bfloat1622float2(*(__nv_bfloat162*)&cc.z);
        float2 f3 = __bfloat1622float2(*(__nv_bfloat162*)&cc.w);
        num[0] += e * f0.x; num[1] += e * f0.y; num[2] += e * f1.x; num[3] += e * f1.y;
        num[4] += e * f2.x; num[5] += e * f2.y; num[6] += e * f3.x; num[7] += e * f3.y;
    };

    uint4 v0 = ld(0), v1 = ld(1), v2 = ld(2), v3 = ld(3);

    int i = 0;
    for (; i + 3 < cnt; i += 4) {
        uint4 c0 = v0, c1 = v1, c2 = v2, c3 = v3;
        v0 = ld(i + 4); v1 = ld(i + 5); v2 = ld(i + 6); v3 = ld(i + 7);
        float p0 = scoreOf(c0), p1 = scoreOf(c1), p2 = scoreOf(c2), p3 = scoreOf(c3);
        p0 += __shfl_xor_sync(0xffffffffu, p0, 1);
        p1 += __shfl_xor_sync(0xffffffffu, p1, 1);
        p2 += __shfl_xor_sync(0xffffffffu, p2, 1);
        p3 += __shfl_xor_sync(0xffffffffu, p3, 1);
        p0 += __shfl_xor_sync(0xffffffffu, p0, 2);
        p1 += __shfl_xor_sync(0xffffffffu, p1, 2);
        p2 += __shfl_xor_sync(0xffffffffu, p2, 2);
        p3 += __shfl_xor_sync(0xffffffffu, p3, 2);
        p0 += __shfl_xor_sync(0xffffffffu, p0, 4);
        p1 += __shfl_xor_sync(0xffffffffu, p1, 4);
        p2 += __shfl_xor_sync(0xffffffffu, p2, 4);
        p3 += __shfl_xor_sync(0xffffffffu, p3, 4);
        float e0 = __expf(p0), e1 = __expf(p1), e2 = __expf(p2), e3 = __expf(p3);
        den += (e0 + e1) + (e2 + e3);
        accum(c0, e0); accum(c1, e1); accum(c2, e2); accum(c3, e3);
    }
    for (int t = 0; i < cnt; i++, t++) {
        uint4 c0 = (t == 0) ? v0 : (t == 1) ? v1 : (t == 2) ? v2 : v3;
        float p0 = scoreOf(c0);
        p0 += __shfl_xor_sync(0xffffffffu, p0, 1);
        p0 += __shfl_xor_sync(0xffffffffu, p0, 2);
        p0 += __shfl_xor_sync(0xffffffffu, p0, 4);
        float e0 = __expf(p0);
        den += e0;
        accum(c0, e0);
    }

    float inv = 1.f / (den + 1e-16f);
    float4 bb0 = *(const float4*)(b1 + off);
    float4 bb1 = *(const float4*)(b1 + off + 4);
    float bias[8] = {bb0.x, bb0.y, bb0.z, bb0.w, bb1.x, bb1.y, bb1.z, bb1.w};
    bf16 h8[8];
    #pragma unroll
    for (int j = 0; j < 8; j++)
        h8[j] = __float2bfloat16(fmaxf(num[j] * inv + bias[j], 0.f));
    *(uint4*)(g_hb + (size_t)d * 256 + off) = *(uint4*)h8;
}

// ---------------- layer 2 fused attention + pooling: 4-edge ILP ------------------
__global__ void gat2_kernel(const float* __restrict__ att, const int* __restrict__ batch,
                            const float* __restrict__ b2, const float* __restrict__ Wo, int N)
{
    int d = (blockIdx.x * blockDim.x + threadIdx.x) >> 5;
    if (d >= N) return;
    int lane = threadIdx.x & 31;
    int off = lane * 2;

    uint32_t xrr = *(const uint32_t*)(g_xr2b + (size_t)d * 64 + off);
    float2 xr = __bfloat1622float2(*(__nv_bfloat162*)&xrr);
    float2 aw = *(const float2*)(att + off);

    float num0 = 0.f, num1 = 0.f, den = 0.f;
    int lo = g_rowptr[d], hi = g_rowptr[d + 1];
    int cnt = hi - lo + 1;

    auto srcAt = [&](int i) { return (lo + i < hi) ? g_csr_src[lo + i] : d; };
    auto ld = [&](int i) { return *(const uint32_t*)(g_xl2b + (size_t)srcAt(i) * 64 + off); };
    auto scoreOf = [&](uint32_t cc) {
        float2 xv = __bfloat1622float2(*(__nv_bfloat162*)&cc);
        return lrelu(xv.x + xr.x) * aw.x + lrelu(xv.y + xr.y) * aw.y;
    };
    auto accum = [&](uint32_t cc, float e) {
        float2 xv = __bfloat1622float2(*(__nv_bfloat162*)&cc);
        num0 += e * xv.x;
        num1 += e * xv.y;
    };

    uint32_t v0 = ld(0), v1 = ld(1), v2 = ld(2), v3 = ld(3);

    int i = 0;
    for (; i + 3 < cnt; i += 4) {
        uint32_t c0 = v0, c1 = v1, c2 = v2, c3 = v3;
        v0 = ld(i + 4); v1 = ld(i + 5); v2 = ld(i + 6); v3 = ld(i + 7);
        float p0 = scoreOf(c0), p1 = scoreOf(c1), p2 = scoreOf(c2), p3 = scoreOf(c3);
        #pragma unroll
        for (int s = 1; s < 32; s <<= 1) {
            p0 += __shfl_xor_sync(0xffffffffu, p0, s);
            p1 += __shfl_xor_sync(0xffffffffu, p1, s);
            p2 += __shfl_xor_sync(0xffffffffu, p2, s);
            p3 += __shfl_xor_sync(0xffffffffu, p3, s);
        }
        float e0 = __expf(p0), e1 = __expf(p1), e2 = __expf(p2), e3 = __expf(p3);
        den += (e0 + e1) + (e2 + e3);
        accum(c0, e0); accum(c1, e1); accum(c2, e2); accum(c3, e3);
    }
    for (int t = 0; i < cnt; i++, t++) {
        uint32_t c0 = (t == 0) ? v0 : (t == 1) ? v1 : (t == 2) ? v2 : v3;
        float p0 = scoreOf(c0);
        #pragma unroll
        for (int s = 1; s < 32; s <<= 1)
            p0 += __shfl_xor_sync(0xffffffffu, p0, s);
        float e0 = __expf(p0);
        den += e0;
        accum(c0, e0);
    }

    float inv = 1.f / (den + 1e-16f);
    float2 bb = *(const float2*)(b2 + off);
    float2 wo = *(const float2*)(Wo + off);
    float y = (num0 * inv + bb.x) * wo.x + (num1 * inv + bb.y) * wo.y;
    y += __shfl_xor_sync(0xffffffffu, y, 1);
    y += __shfl_xor_sync(0xffffffffu, y, 2);
    y += __shfl_xor_sync(0xffffffffu, y, 4);
    y += __shfl_xor_sync(0xffffffffu, y, 8);
    y += __shfl_xor_sync(0xffffffffu, y, 16);
    if (lane == 0) atomicAdd(&g_acc[batch[d]], y);
}

__global__ void final_kernel(float* __restrict__ out, int G, const float* __restrict__ bo)
{
    int g = threadIdx.x;
    if (g < G) out[g] = g_acc[g] / fmaxf(g_cnt[g], 1.f) + bo[0];
}

// ---------------- launch: fork/join multi-stream to overlap CSR with GEMM --------
extern "C" void kernel_launch(void* const* d_in, const int* in_sizes, int n_in,
                              void* d_out, int out_size)
{
    const float* x    = (const float*)d_in[0];
    const int* ei     = (const int*)d_in[1];
    const int* bat    = (const int*)d_in[2];
    const float* Wl1 = (const float*)d_in[3];
    const float* Wr1 = (const float*)d_in[4];
    const float* att1 = (const float*)d_in[5];
    const float* b1  = (const float*)d_in[6];
    const float* Wl2 = (const float*)d_in[7];
    const float* Wr2 = (const float*)d_in[8];
    const float* att2 = (const float*)d_in[9];
    const float* b2  = (const float*)d_in[10];
    const float* Wo  = (const float*)d_in[11];
    const float* bo  = (const float*)d_in[12];

    int N = in_sizes[0] / 128;
    int E = in_sizes[1] / 2;
    int G = out_size;
    const int* src = ei;
    const int* dst = ei + E;
    int tiles = (N + 127) / 128;
    int nb = (N + 255) / 256;

    const int SM1 = 34816 + 2 * 34816;   // 104448 -> 2 CTAs/SM
    const int SM2 = 2 * 55296;           // 110592 -> 2 CTAs/SM

    static bool inited = false;
    static cudaStream_t s2;
    static cudaEvent_t ev0, ev_wt, ev_prep, ev_csr;
    if (!inited) {
        cudaStreamCreateWithFlags(&s2, cudaStreamNonBlocking);
        cudaEventCreateWithFlags(&ev0, cudaEventDisableTiming);
        cudaEventCreateWithFlags(&ev_wt, cudaEventDisableTiming);
        cudaEventCreateWithFlags(&ev_prep, cudaEventDisableTiming);
        cudaEventCreateWithFlags(&ev_csr, cudaEventDisableTiming);
        cudaFuncSetAttribute(mma_gemm1, cudaFuncAttributeMaxDynamicSharedMemorySize, SM1);
        cudaFuncSetAttribute(mma_gemm2, cudaFuncAttributeMaxDynamicSharedMemorySize, SM2);
        inited = true;
    }

    // fork side stream from main (capture) stream
    cudaEventRecord(ev0, 0);
    cudaStreamWaitEvent(s2, ev0, 0);

    // side stream: weight split (independent)
    split_wt_all<<<(98304 + 255) / 256, 256, 0, s2>>>(Wl1, Wr1, Wl2, Wr2);
    cudaEventRecord(ev_wt, s2);

    // main: init + prep
    init0<<<(N + 255) / 256, 256>>>(N);
    prep_kernel<<<(N * 128 + 255) / 256, 256>>>(x, dst, bat, N, E);
    cudaEventRecord(ev_prep, 0);

    // side stream: CSR build (depends on prep's degree histogram)
    cudaStreamWaitEvent(s2, ev_prep, 0);
    blocksum_kernel<<<nb, 256, 0, s2>>>(N);
    scanb_kernel<<<1, 256, 0, s2>>>(nb);
    rowptr_kernel<<<nb, 256, 0, s2>>>(N, E);
    scatter_kernel<<<(E + 255) / 256, 256, 0, s2>>>(src, dst, E);
    cudaEventRecord(ev_csr, s2);

    // main: gemm1 (needs prep + split_wt) runs concurrently with CSR build
    cudaStreamWaitEvent(0, ev_wt, 0);
    mma_gemm1<<<tiles, 256, SM1>>>(N);

    // join: gat1 needs gemm1 + CSR
    cudaStreamWaitEvent(0, ev_csr, 0);
    gat1_kernel<<<(N * 32 + 255) / 256, 256>>>(att1, b1, N);
    mma_gemm2<<<tiles, 256, SM2>>>(N);
    gat2_kernel<<<(N * 32 + 255) / 256, 256>>>(att2, bat, b2, Wo, N);
    final_kernel<<<1, 64>>>((float*)d_out, G, bo);
}

// round 16
// speedup vs baseline: 4.2605x; 1.0580x over previous
#include <cuda_runtime.h>
#include <cuda_bf16.h>
#include <cstdint>

#define MAXN 50000
#define MAXE 800000
typedef __nv_bfloat16 bf16;

// ---------------- scratch (device globals; no allocation allowed) ----------------
__device__ __align__(16) bf16 g_xl1b[(size_t)MAXN * 256];
__device__ __align__(16) bf16 g_xr1b[(size_t)MAXN * 256];
__device__ __align__(16) bf16 g_xl2b[(size_t)MAXN * 64];
__device__ __align__(16) bf16 g_xr2b[(size_t)MAXN * 64];
__device__ __align__(16) bf16 g_hb[(size_t)MAXN * 256];
// weight transposes [n][k], SPLIT bf16: w1l@0 (256x128), w1r@32768, w2l@65536 (64x256), w2r@81920
__device__ __align__(16) bf16 g_wthi[98304];
__device__ __align__(16) bf16 g_wtlo[98304];
__device__ int g_deg[MAXN];
__device__ int g_rowptr[MAXN + 1];
__device__ int g_woff[MAXN];
__device__ int g_csr_src[MAXE];
__device__ int g_bsum[256];
__device__ float g_acc[64];
__device__ float g_cnt[64];

__device__ __forceinline__ float lrelu(float v) { return v > 0.f ? v : 0.2f * v; }

__device__ __forceinline__ uint32_t smem_u32(const void* p) {
    uint32_t a;
    asm("{ .reg .u64 t; cvta.to.shared.u64 t, %1; cvt.u32.u64 %0, t; }" : "=r"(a) : "l"(p));
    return a;
}
__device__ __forceinline__ void cp16(uint32_t s, const void* g) {
    asm volatile("cp.async.cg.shared.global [%0], [%1], 16;" :: "r"(s), "l"(g));
}
#define CP_COMMIT() asm volatile("cp.async.commit_group;" ::: "memory")
#define LDSM4(r0, r1, r2, r3, addr) \
    asm volatile("ldmatrix.sync.aligned.m8n8.x4.shared.b16 {%0,%1,%2,%3}, [%4];" \
                 : "=r"(r0), "=r"(r1), "=r"(r2), "=r"(r3) : "r"(addr))

__device__ __forceinline__ void mma_bf16(float* d, const uint32_t* a, const uint32_t* b) {
    asm volatile("mma.sync.aligned.m16n8k16.row.col.f32.bf16.bf16.f32 "
                 "{%0,%1,%2,%3}, {%4,%5,%6,%7}, {%8,%9}, {%0,%1,%2,%3};"
                 : "+f"(d[0]), "+f"(d[1]), "+f"(d[2]), "+f"(d[3])
                 : "r"(a[0]), "r"(a[1]), "r"(a[2]), "r"(a[3]), "r"(b[0]), "r"(b[1]));
}

// ---------------- side-stream prep: init + histogram + graph counts --------------
__global__ void init0(int N) {
    int i = blockIdx.x * blockDim.x + threadIdx.x;
    if (i < N) g_deg[i] = 0;
    if (i < 64) { g_acc[i] = 0.f; g_cnt[i] = 0.f; }
}
__global__ void hist_kernel(const int* __restrict__ dst, const int* __restrict__ batch,
                            int N, int E) {
    int i = blockIdx.x * blockDim.x + threadIdx.x;
    if (i < E) atomicAdd(&g_deg[dst[i]], 1);
    if (i < N) atomicAdd(&g_cnt[batch[i]], 1.f);
}

// weight transposes, SPLIT bf16 hi/lo
__global__ void split_wt_all(const float* __restrict__ Wl1, const float* __restrict__ Wr1,
                             const float* __restrict__ Wl2, const float* __restrict__ Wr2) {
    int i = blockIdx.x * blockDim.x + threadIdx.x;
    if (i >= 98304) return;
    const float* W;
    int K, Nout, off, j;
    if (i < 32768)      { W = Wl1; K = 128; Nout = 256; off = 0;     j = i; }
    else if (i < 65536) { W = Wr1; K = 128; Nout = 256; off = 32768; j = i - 32768; }
    else if (i < 81920) { W = Wl2; K = 256; Nout = 64;  off = 65536; j = i - 65536; }
    else                { W = Wr2; K = 256; Nout = 64;  off = 81920; j = i - 81920; }
    int k = j / Nout, n = j % Nout;
    float v = W[j];
    bf16 h = __float2bfloat16(v);
    g_wthi[off + n * K + k] = h;
    g_wtlo[off + n * K + k] = __float2bfloat16(v - __bfloat162float(h));
}

// ---------------- layer-1 GEMM: A (fp32->bf16 in-kernel) resident; 8 B chunks ----
// chunks 0-3: z=0 (xl, 2-term hi+lo); chunks 4-7: z=1 (xr, 1-term hi; score-only)
__global__ void __launch_bounds__(256) mma_gemm1(const float* __restrict__ x, int M)
{
    constexpr int SA = 136;
    constexpr int A_OFF = 0;          // 128*136*2 = 34816
    constexpr int BUF0 = 34816;
    constexpr int BUFSZ = 34816;      // hi@+0, lo@+17408
    extern __shared__ char smem[];
    uint32_t sb = smem_u32(smem);
    int tid = threadIdx.x;
    int wid = tid >> 5, lane = tid & 31;
    int m0 = blockIdx.x * 128;

    auto load_b = [&](int c, int b) {
        int z = c >> 2;
        const bf16* WH = g_wthi + (z ? 32768 : 0) + (size_t)(c & 3) * 64 * 128;
        const bf16* WL = g_wtlo + (z ? 32768 : 0) + (size_t)(c & 3) * 64 * 128;
        uint32_t bbase = sb + BUF0 + b * BUFSZ;
        for (int t = tid; t < 64 * 16; t += 256) {
            int n = t >> 4, kcl = (t & 15) * 8;
            uint32_t ta = (uint32_t)(n * SA + kcl) * 2;
            cp16(bbase + ta, WH + (size_t)n * 128 + kcl);
            if (z == 0) cp16(bbase + 17408 + ta, WL + (size_t)n * 128 + kcl);
        }
        CP_COMMIT();
    };

    load_b(0, 0);
    load_b(1, 1);

    // A: fp32 -> bf16 staged into smem (overlaps in-flight cp.async B loads)
    for (int c = tid; c < 128 * 16; c += 256) {
        int row = c >> 4, kcl = (c & 15) * 8;
        int rg = min(m0 + row, M - 1);
        const float4* xp = (const float4*)(x + (size_t)rg * 128 + kcl);
        float4 v0 = xp[0], v1 = xp[1];
        bf16 h8[8];
        h8[0] = __float2bfloat16(v0.x); h8[1] = __float2bfloat16(v0.y);
        h8[2] = __float2bfloat16(v0.z); h8[3] = __float2bfloat16(v0.w);
        h8[4] = __float2bfloat16(v1.x); h8[5] = __float2bfloat16(v1.y);
        h8[6] = __float2bfloat16(v1.z); h8[7] = __float2bfloat16(v1.w);
        *(uint4*)(smem + A_OFF + (uint32_t)(row * SA + kcl) * 2) = *(uint4*)h8;
    }

    int mwarp = (wid & 3) * 32;
    int nwarp = (wid >> 2) * 32;
    int sel = lane >> 3, r8 = lane & 7;
    uint32_t aoff[2], boff[2];
    #pragma unroll
    for (int mt = 0; mt < 2; mt++)
        aoff[mt] = (uint32_t)(((mwarp + mt * 16 + (sel & 1) * 8 + r8) * SA + (sel >> 1) * 8) * 2);
    #pragma unroll
    for (int bt = 0; bt < 2; bt++)
        boff[bt] = (uint32_t)(((nwarp + bt * 16 + (sel >> 1) * 8 + r8) * SA + (sel & 1) * 8) * 2);

    int g4 = lane >> 2, tig = lane & 3;

    for (int c = 0; c < 8; c++) {
        if (c < 7) asm volatile("cp.async.wait_group 1;" ::: "memory");
        else       asm volatile("cp.async.wait_group 0;" ::: "memory");
        __syncthreads();

        bool twoterm = (c < 4);
        uint32_t bb = sb + BUF0 + (c & 1) * BUFSZ;
        float d[2][4][4];
        #pragma unroll
        for (int mt = 0; mt < 2; mt++)
            #pragma unroll
            for (int nt = 0; nt < 4; nt++)
                #pragma unroll
                for (int j = 0; j < 4; j++) d[mt][nt][j] = 0.f;

        #pragma unroll
        for (int ks = 0; ks < 8; ks++) {
            uint32_t kb = ks * 32;
            uint32_t ah[2][4], bh[8], bl[8];
            #pragma unroll
            for (int mt = 0; mt < 2; mt++)
                LDSM4(ah[mt][0], ah[mt][1], ah[mt][2], ah[mt][3], sb + A_OFF + aoff[mt] + kb);
            #pragma unroll
            for (int bt = 0; bt < 2; bt++)
                LDSM4(bh[bt*4], bh[bt*4+1], bh[bt*4+2], bh[bt*4+3], bb + boff[bt] + kb);
            if (twoterm) {
                #pragma unroll
                for (int bt = 0; bt < 2; bt++)
                    LDSM4(bl[bt*4], bl[bt*4+1], bl[bt*4+2], bl[bt*4+3], bb + 17408 + boff[bt] + kb);
            }
            #pragma unroll
            for (int mt = 0; mt < 2; mt++)
                #pragma unroll
                for (int nt = 0; nt < 4; nt++) {
                    mma_bf16(d[mt][nt], ah[mt], &bh[nt * 2]);
                    if (twoterm) mma_bf16(d[mt][nt], ah[mt], &bl[nt * 2]);
                }
        }
        __syncthreads();

        if (c + 2 < 8) load_b(c + 2, c & 1);

        int z = c >> 2;
        int colb = (c & 3) * 64;
        bf16* Cb = z ? g_xr1b : g_xl1b;
        #pragma unroll
        for (int mt = 0; mt < 2; mt++) {
            int mrow = m0 + mwarp + mt * 16 + g4;
            #pragma unroll
            for (int nt = 0; nt < 4; nt++) {
                int col = colb + nwarp + nt * 8 + tig * 2;
                if (mrow < M) {
                    __nv_bfloat162 p = __float22bfloat162_rn(make_float2(d[mt][nt][0], d[mt][nt][1]));
                    *(uint32_t*)(Cb + (size_t)mrow * 256 + col) = *(uint32_t*)&p;
                }
                if (mrow + 8 < M) {
                    __nv_bfloat162 p = __float22bfloat162_rn(make_float2(d[mt][nt][2], d[mt][nt][3]));
                    *(uint32_t*)(Cb + (size_t)(mrow + 8) * 256 + col) = *(uint32_t*)&p;
                }
            }
        }
    }
}

// ---------------- CSR build: coalesced 3-stage scan ----------------
__global__ void blocksum_kernel(int N) {
    __shared__ int sh[256];
    int tid = threadIdx.x;
    int i = blockIdx.x * 256 + tid;
    sh[tid] = (i < N) ? g_deg[i] : 0;
    __syncthreads();
    for (int s = 128; s > 0; s >>= 1) {
        if (tid < s) sh[tid] += sh[tid + s];
        __syncthreads();
    }
    if (tid == 0) g_bsum[blockIdx.x] = sh[0];
}
__global__ void scanb_kernel(int nb) {
    __shared__ int sh[256];
    int tid = threadIdx.x;
    int v = (tid < nb) ? g_bsum[tid] : 0;
    sh[tid] = v;
    __syncthreads();
    for (int s = 1; s < 256; s <<= 1) {
        int t = (tid >= s) ? sh[tid - s] : 0;
        __syncthreads();
        sh[tid] += t;
        __syncthreads();
    }
    if (tid < nb) g_bsum[tid] = sh[tid] - v;
}
__global__ void rowptr_kernel(int N, int E) {
    __shared__ int sh[256];
    int tid = threadIdx.x;
    int i = blockIdx.x * 256 + tid;
    int v = (i < N) ? g_deg[i] : 0;
    sh[tid] = v;
    __syncthreads();
    for (int s = 1; s < 256; s <<= 1) {
        int t = (tid >= s) ? sh[tid - s] : 0;
        __syncthreads();
        sh[tid] += t;
        __syncthreads();
    }
    if (i < N) {
        int ex = g_bsum[blockIdx.x] + sh[tid] - v;
        g_rowptr[i] = ex;
        g_woff[i] = ex;
        if (i == N - 1) g_rowptr[N] = E;
    }
}
__global__ void scatter_kernel(const int* __restrict__ src, const int* __restrict__ dst, int E) {
    int e = blockIdx.x * blockDim.x + threadIdx.x;
    if (e >= E) return;
    int pos = atomicAdd(&g_woff[dst[e]], 1);
    g_csr_src[pos] = src[e];
}

// ---------------- layer-2 GEMM: K pipelined in 4x64 chunks; z1 hi-only ------------
__global__ void __launch_bounds__(256) mma_gemm2(int M)
{
    constexpr int SA = 72;
    constexpr int ABYT = 18432;            // 128*72*2
    constexpr int BBYT = 9216;             // 64*72*2
    constexpr int B_OFF = 18432;           // parts: z0_hi, z0_lo, z1_hi
    constexpr int BUFSZ = 46080;           // 18432 + 3*9216
    extern __shared__ char smem[];
    uint32_t sb = smem_u32(smem);
    int tid = threadIdx.x;
    int wid = tid >> 5, lane = tid & 31;
    int m0 = blockIdx.x * 128;

    auto load_chunk = [&](int kc, int b) {
        uint32_t base = sb + b * BUFSZ;
        for (int c = tid; c < 128 * 8; c += 256) {
            int row = c >> 3, kcl = (c & 7) * 8;
            int rg = min(m0 + row, M - 1);
            cp16(base + (uint32_t)(row * SA + kcl) * 2, g_hb + (size_t)rg * 256 + kc * 64 + kcl);
        }
        for (int c = tid; c < 3 * 64 * 8; c += 256) {
            int part = c >> 9, r = c & 511;
            int n = r >> 3, kcl = (r & 7) * 8;
            const bf16* W = (part == 0) ? (g_wthi + 65536)
                          : (part == 1) ? (g_wtlo + 65536)
                                        : (g_wthi + 81920);
            cp16(base + B_OFF + part * BBYT + (uint32_t)(n * SA + kcl) * 2,
                 W + (size_t)n * 256 + kc * 64 + kcl);
        }
        CP_COMMIT();
    };

    load_chunk(0, 0);

    int mwarp = (wid & 3) * 32;
    int nwarp = (wid >> 2) * 32;
    int sel = lane >> 3, r8 = lane & 7;
    uint32_t aoff[2], boff[2];
    #pragma unroll
    for (int mt = 0; mt < 2; mt++)
        aoff[mt] = (uint32_t)(((mwarp + mt * 16 + (sel & 1) * 8 + r8) * SA + (sel >> 1) * 8) * 2);
    #pragma unroll
    for (int bt = 0; bt < 2; bt++)
        boff[bt] = (uint32_t)(((nwarp + bt * 16 + (sel >> 1) * 8 + r8) * SA + (sel & 1) * 8) * 2);

    float d[2][2][4][4];
    #pragma unroll
    for (int z = 0; z < 2; z++)
        #pragma unroll
        for (int mt = 0; mt < 2; mt++)
            #pragma unroll
            for (int nt = 0; nt < 4; nt++)
                #pragma unroll
                for (int j = 0; j < 4; j++) d[z][mt][nt][j] = 0.f;

    for (int kc = 0; kc < 4; kc++) {
        if (kc < 3) {
            load_chunk(kc + 1, (kc + 1) & 1);
            asm volatile("cp.async.wait_group 1;" ::: "memory");
        } else {
            asm volatile("cp.async.wait_group 0;" ::: "memory");
        }
        __syncthreads();
        uint32_t base = sb + (kc & 1) * BUFSZ;

        #pragma unroll
        for (int ks = 0; ks < 4; ks++) {
            uint32_t kb = ks * 32;
            uint32_t ah[2][4], b0h[8], b0l[8], b1h[8];
            #pragma unroll
            for (int mt = 0; mt < 2; mt++)
                LDSM4(ah[mt][0], ah[mt][1], ah[mt][2], ah[mt][3], base + aoff[mt] + kb);
            #pragma unroll
            for (int bt = 0; bt < 2; bt++) {
                LDSM4(b0h[bt*4], b0h[bt*4+1], b0h[bt*4+2], b0h[bt*4+3], base + B_OFF + boff[bt] + kb);
                LDSM4(b0l[bt*4], b0l[bt*4+1], b0l[bt*4+2], b0l[bt*4+3], base + B_OFF + BBYT + boff[bt] + kb);
                LDSM4(b1h[bt*4], b1h[bt*4+1], b1h[bt*4+2], b1h[bt*4+3], base + B_OFF + 2*BBYT + boff[bt] + kb);
            }
            #pragma unroll
            for (int mt = 0; mt < 2; mt++)
                #pragma unroll
                for (int nt = 0; nt < 4; nt++) {
                    mma_bf16(d[0][mt][nt], ah[mt], &b0h[nt * 2]);
                    mma_bf16(d[0][mt][nt], ah[mt], &b0l[nt * 2]);
                    mma_bf16(d[1][mt][nt], ah[mt], &b1h[nt * 2]);
                }
        }
        __syncthreads();
    }

    int g4 = lane >> 2, tig = lane & 3;
    #pragma unroll
    for (int z = 0; z < 2; z++) {
        bf16* Cb = z ? g_xr2b : g_xl2b;
        #pragma unroll
        for (int mt = 0; mt < 2; mt++) {
            int mrow = m0 + mwarp + mt * 16 + g4;
            #pragma unroll
            for (int nt = 0; nt < 4; nt++) {
                int col = nwarp + nt * 8 + tig * 2;
                if (mrow < M) {
                    __nv_bfloat162 p = __float22bfloat162_rn(make_float2(d[z][mt][nt][0], d[z][mt][nt][1]));
                    *(uint32_t*)(Cb + (size_t)mrow * 64 + col) = *(uint32_t*)&p;
                }
                if (mrow + 8 < M) {
                    __nv_bfloat162 p = __float22bfloat162_rn(make_float2(d[z][mt][nt][2], d[z][mt][nt][3]));
                    *(uint32_t*)(Cb + (size_t)(mrow + 8) * 64 + col) = *(uint32_t*)&p;
                }
            }
        }
    }
}

// ---------------- layer 1 fused attention: one warp per dst, 4-edge ILP ----------
__global__ void gat1_kernel(const float* __restrict__ att, const float* __restrict__ b1, int N)
{
    int d = (blockIdx.x * blockDim.x + threadIdx.x) >> 5;
    if (d >= N) return;
    int lane = threadIdx.x & 31;
    int off = lane * 8;

    uint4 xrr = *(const uint4*)(g_xr1b + (size_t)d * 256 + off);
    float2 xr0 = __bfloat1622float2(*(__nv_bfloat162*)&xrr.x);
    float2 xr1 = __bfloat1622float2(*(__nv_bfloat162*)&xrr.y);
    float2 xr2 = __bfloat1622float2(*(__nv_bfloat162*)&xrr.z);
    float2 xr3 = __bfloat1622float2(*(__nv_bfloat162*)&xrr.w);
    float4 aw0 = *(const float4*)(att + off);
    float4 aw1 = *(const float4*)(att + off + 4);

    float num[8];
    #pragma unroll
    for (int j = 0; j < 8; j++) num[j] = 0.f;
    float den = 0.f;

    int lo = g_rowptr[d], hi = g_rowptr[d + 1];
    int cnt = hi - lo + 1;

    auto srcAt = [&](int i) { return (lo + i < hi) ? g_csr_src[lo + i] : d; };
    auto ld = [&](int i) { return *(const uint4*)(g_xl1b + (size_t)srcAt(i) * 256 + off); };
    auto scoreOf = [&](uint4 cc) {
        float2 f0 = __bfloat1622float2(*(__nv_bfloat162*)&cc.x);
        float2 f1 = __bfloat1622float2(*(__nv_bfloat162*)&cc.y);
        float2 f2 = __bfloat1622float2(*(__nv_bfloat162*)&cc.z);
        float2 f3 = __bfloat1622float2(*(__nv_bfloat162*)&cc.w);
        return lrelu(f0.x + xr0.x) * aw0.x + lrelu(f0.y + xr0.y) * aw0.y
             + lrelu(f1.x + xr1.x) * aw0.z + lrelu(f1.y + xr1.y) * aw0.w
             + lrelu(f2.x + xr2.x) * aw1.x + lrelu(f2.y + xr2.y) * aw1.y
             + lrelu(f3.x + xr3.x) * aw1.z + lrelu(f3.y + xr3.y) * aw1.w;
    };
    auto accum = [&](uint4 cc, float e) {
        float2 f0 = __bfloat1622float2(*(__nv_bfloat162*)&cc.x);
        float2 f1 = __bfloat1622float2(*(__nv_bfloat162*)&cc.y);
        float2 f2 = __bfloat1622float2(*(__nv_bfloat162*)&cc.z);
        float2 f3 = __bfloat1622float2(*(__nv_bfloat162*)&cc.w);
        num[0] += e * f0.x; num[1] += e * f0.y; num[2] += e * f1.x; num[3] += e * f1.y;
        num[4] += e * f2.x; num[5] += e * f2.y; num[6] += e * f3.x; num[7] += e * f3.y;
    };

    uint4 v0 = ld(0), v1 = ld(1), v2 = ld(2), v3 = ld(3);

    int i = 0;
    for (; i + 3 < cnt; i += 4) {
        uint4 c0 = v0, c1 = v1, c2 = v2, c3 = v3;
        v0 = ld(i + 4); v1 = ld(i + 5); v2 = ld(i + 6); v3 = ld(i + 7);
        float p0 = scoreOf(c0), p1 = scoreOf(c1), p2 = scoreOf(c2), p3 = scoreOf(c3);
        p0 += __shfl_xor_sync(0xffffffffu, p0, 1);
        p1 += __shfl_xor_sync(0xffffffffu, p1, 1);
        p2 += __shfl_xor_sync(0xffffffffu, p2, 1);
        p3 += __shfl_xor_sync(0xffffffffu, p3, 1);
        p0 += __shfl_xor_sync(0xffffffffu, p0, 2);
        p1 += __shfl_xor_sync(0xffffffffu, p1, 2);
        p2 += __shfl_xor_sync(0xffffffffu, p2, 2);
        p3 += __shfl_xor_sync(0xffffffffu, p3, 2);
        p0 += __shfl_xor_sync(0xffffffffu, p0, 4);
        p1 += __shfl_xor_sync(0xffffffffu, p1, 4);
        p2 += __shfl_xor_sync(0xffffffffu, p2, 4);
        p3 += __shfl_xor_sync(0xffffffffu, p3, 4);
        float e0 = __expf(p0), e1 = __expf(p1), e2 = __expf(p2), e3 = __expf(p3);
        den += (e0 + e1) + (e2 + e3);
        accum(c0, e0); accum(c1, e1); accum(c2, e2); accum(c3, e3);
    }
    for (int t = 0; i < cnt; i++, t++) {
        uint4 c0 = (t == 0) ? v0 : (t == 1) ? v1 : (t == 2) ? v2 : v3;
        float p0 = scoreOf(c0);
        p0 += __shfl_xor_sync(0xffffffffu, p0, 1);
        p0 += __shfl_xor_sync(0xffffffffu, p0, 2);
        p0 += __shfl_xor_sync(0xffffffffu, p0, 4);
        float e0 = __expf(p0);
        den += e0;
        accum(c0, e0);
    }

    float inv = 1.f / (den + 1e-16f);
    float4 bb0 = *(const float4*)(b1 + off);
    float4 bb1 = *(const float4*)(b1 + off + 4);
    float bias[8] = {bb0.x, bb0.y, bb0.z, bb0.w, bb1.x, bb1.y, bb1.z, bb1.w};
    bf16 h8[8];
    #pragma unroll
    for (int j = 0; j < 8; j++)
        h8[j] = __float2bfloat16(fmaxf(num[j] * inv + bias[j], 0.f));
    *(uint4*)(g_hb + (size_t)d * 256 + off) = *(uint4*)h8;
}

// ---------------- layer 2 fused attention + pooling: 4-edge ILP ------------------
__global__ void gat2_kernel(const float* __restrict__ att, const int* __restrict__ batch,
                            const float* __restrict__ b2, const float* __restrict__ Wo, int N)
{
    int d = (blockIdx.x * blockDim.x + threadIdx.x) >> 5;
    if (d >= N) return;
    int lane = threadIdx.x & 31;
    int off = lane * 2;

    uint32_t xrr = *(const uint32_t*)(g_xr2b + (size_t)d * 64 + off);
    float2 xr = __bfloat1622float2(*(__nv_bfloat162*)&xrr);
    float2 aw = *(const float2*)(att + off);

    float num0 = 0.f, num1 = 0.f, den = 0.f;
    int lo = g_rowptr[d], hi = g_rowptr[d + 1];
    int cnt = hi - lo + 1;

    auto srcAt = [&](int i) { return (lo + i < hi) ? g_csr_src[lo + i] : d; };
    auto ld = [&](int i) { return *(const uint32_t*)(g_xl2b + (size_t)srcAt(i) * 64 + off); };
    auto scoreOf = [&](uint32_t cc) {
        float2 xv = __bfloat1622float2(*(__nv_bfloat162*)&cc);
        return lrelu(xv.x + xr.x) * aw.x + lrelu(xv.y + xr.y) * aw.y;
    };
    auto accum = [&](uint32_t cc, float e) {
        float2 xv = __bfloat1622float2(*(__nv_bfloat162*)&cc);
        num0 += e * xv.x;
        num1 += e * xv.y;
    };

    uint32_t v0 = ld(0), v1 = ld(1), v2 = ld(2), v3 = ld(3);

    int i = 0;
    for (; i + 3 < cnt; i += 4) {
        uint32_t c0 = v0, c1 = v1, c2 = v2, c3 = v3;
        v0 = ld(i + 4); v1 = ld(i + 5); v2 = ld(i + 6); v3 = ld(i + 7);
        float p0 = scoreOf(c0), p1 = scoreOf(c1), p2 = scoreOf(c2), p3 = scoreOf(c3);
        #pragma unroll
        for (int s = 1; s < 32; s <<= 1) {
            p0 += __shfl_xor_sync(0xffffffffu, p0, s);
            p1 += __shfl_xor_sync(0xffffffffu, p1, s);
            p2 += __shfl_xor_sync(0xffffffffu, p2, s);
            p3 += __shfl_xor_sync(0xffffffffu, p3, s);
        }
        float e0 = __expf(p0), e1 = __expf(p1), e2 = __expf(p2), e3 = __expf(p3);
        den += (e0 + e1) + (e2 + e3);
        accum(c0, e0); accum(c1, e1); accum(c2, e2); accum(c3, e3);
    }
    for (int t = 0; i < cnt; i++, t++) {
        uint32_t c0 = (t == 0) ? v0 : (t == 1) ? v1 : (t == 2) ? v2 : v3;
        float p0 = scoreOf(c0);
        #pragma unroll
        for (int s = 1; s < 32; s <<= 1)
            p0 += __shfl_xor_sync(0xffffffffu, p0, s);
        float e0 = __expf(p0);
        den += e0;
        accum(c0, e0);
    }

    float inv = 1.f / (den + 1e-16f);
    float2 bb = *(const float2*)(b2 + off);
    float2 wo = *(const float2*)(Wo + off);
    float y = (num0 * inv + bb.x) * wo.x + (num1 * inv + bb.y) * wo.y;
    y += __shfl_xor_sync(0xffffffffu, y, 1);
    y += __shfl_xor_sync(0xffffffffu, y, 2);
    y += __shfl_xor_sync(0xffffffffu, y, 4);
    y += __shfl_xor_sync(0xffffffffu, y, 8);
    y += __shfl_xor_sync(0xffffffffu, y, 16);
    if (lane == 0) atomicAdd(&g_acc[batch[d]], y);
}

__global__ void final_kernel(float* __restrict__ out, int G, const float* __restrict__ bo)
{
    int g = threadIdx.x;
    if (g < G) out[g] = g_acc[g] / fmaxf(g_cnt[g], 1.f) + bo[0];
}

// ---------------- launch: gemm1 starts immediately; all prep on side stream ------
extern "C" void kernel_launch(void* const* d_in, const int* in_sizes, int n_in,
                              void* d_out, int out_size)
{
    const float* x    = (const float*)d_in[0];
    const int* ei     = (const int*)d_in[1];
    const int* bat    = (const int*)d_in[2];
    const float* Wl1 = (const float*)d_in[3];
    const float* Wr1 = (const float*)d_in[4];
    const float* att1 = (const float*)d_in[5];
    const float* b1  = (const float*)d_in[6];
    const float* Wl2 = (const float*)d_in[7];
    const float* Wr2 = (const float*)d_in[8];
    const float* att2 = (const float*)d_in[9];
    const float* b2  = (const float*)d_in[10];
    const float* Wo  = (const float*)d_in[11];
    const float* bo  = (const float*)d_in[12];

    int N = in_sizes[0] / 128;
    int E = in_sizes[1] / 2;
    int G = out_size;
    const int* src = ei;
    const int* dst = ei + E;
    int tiles = (N + 127) / 128;
    int nb = (N + 255) / 256;

    const int SM1 = 34816 + 2 * 34816;   // 104448 -> 2 CTAs/SM
    const int SM2 = 2 * 46080;           // 92160 -> 2 CTAs/SM

    static bool inited = false;
    static cudaStream_t s2;
    static cudaEvent_t ev0, ev_wt, ev_csr;
    if (!inited) {
        cudaStreamCreateWithFlags(&s2, cudaStreamNonBlocking);
        cudaEventCreateWithFlags(&ev0, cudaEventDisableTiming);
        cudaEventCreateWithFlags(&ev_wt, cudaEventDisableTiming);
        cudaEventCreateWithFlags(&ev_csr, cudaEventDisableTiming);
        cudaFuncSetAttribute(mma_gemm1, cudaFuncAttributeMaxDynamicSharedMemorySize, SM1);
        cudaFuncSetAttribute(mma_gemm2, cudaFuncAttributeMaxDynamicSharedMemorySize, SM2);
        inited = true;
    }

    // fork side stream
    cudaEventRecord(ev0, 0);
    cudaStreamWaitEvent(s2, ev0, 0);

    // main: weight split, then gemm1 (critical path)
    split_wt_all<<<(98304 + 255) / 256, 256>>>(Wl1, Wr1, Wl2, Wr2);
    cudaEventRecord(ev_wt, 0);

    // side: init + histogram + CSR (entirely off critical path, under gemm1)
    init0<<<(N + 255) / 256, 256, 0, s2>>>(N);
    hist_kernel<<<(max(N, E) + 255) / 256, 256, 0, s2>>>(dst, bat, N, E);
    blocksum_kernel<<<nb, 256, 0, s2>>>(N);
    scanb_kernel<<<1, 256, 0, s2>>>(nb);
    rowptr_kernel<<<nb, 256, 0, s2>>>(N, E);
    scatter_kernel<<<(E + 255) / 256, 256, 0, s2>>>(src, dst, E);
    cudaEventRecord(ev_csr, s2);

    mma_gemm1<<<tiles, 256, SM1>>>(x, N);

    // join
    cudaStreamWaitEvent(0, ev_csr, 0);
    gat1_kernel<<<(N * 32 + 255) / 256, 256>>>(att1, b1, N);
    mma_gemm2<<<tiles, 256, SM2>>>(N);
    gat2_kernel<<<(N * 32 + 255) / 256, 256>>>(att2, bat, b2, Wo, N);
    final_kernel<<<1, 64>>>((float*)d_out, G, bo);
}